// round 1
// baseline (speedup 1.0000x reference)
#include <cuda_runtime.h>
#include <math.h>

#define NN   16384
#define NE   262144
#define NG   64
#define LMAXC 320
#define EMBD 256
#define FFND 1024
#define NHD  8
#define DHD  32
#define NTOK (LMAXC*NG)

// ---------------- scratch (device globals; no allocation allowed) ----------
__device__ float g_deg[NN];
__device__ float g_agg[NN*EMBD];
__device__ float g_ha [NN*EMBD];
__device__ float g_hb [NN*EMBD];
__device__ float g_hp [NTOK*EMBD];
__device__ float g_q  [NTOK*EMBD];
__device__ float g_k  [NTOK*EMBD];
__device__ float g_v  [NTOK*EMBD];
__device__ float g_o  [NTOK*EMBD];
__device__ float g_tmp[NTOK*EMBD];
__device__ float g_mid[NTOK*FFND];

// ---------------- degree -----------------
__global__ void deg_kernel(const int* __restrict__ ei, float* __restrict__ deg) {
    int e = blockIdx.x * blockDim.x + threadIdx.x;
    if (e < NE) atomicAdd(&deg[ei[NE + e]], 1.0f);
}

// ---------------- scatter-add (float4 chunks) ----------------
__global__ void scatter_kernel(const float* __restrict__ feat, const int* __restrict__ ei,
                               float* __restrict__ out, int D4) {
    int t = blockIdx.x * blockDim.x + threadIdx.x;
    int total = NE * D4;
    if (t >= total) return;
    int e = t / D4;
    int c = t - e * D4;
    int s = ei[e];
    int d = ei[NE + e];
    float4 v = reinterpret_cast<const float4*>(feat)[(long)s * D4 + c];
    float* op = out + ((long)d * D4 + c) * 4;
    atomicAdd(op + 0, v.x);
    atomicAdd(op + 1, v.y);
    atomicAdd(op + 2, v.z);
    atomicAdd(op + 3, v.w);
}

__global__ void divdeg_kernel(float* __restrict__ agg, const float* __restrict__ deg, int D) {
    int t = blockIdx.x * blockDim.x + threadIdx.x;
    if (t >= NN * D) return;
    int i = t / D;
    agg[t] *= 1.0f / fmaxf(deg[i], 1.0f);
}

// ---------------- tiled fp32 GEMM: C[M,N] (+)= A[M,K] @ B[K,N] (+bias)(relu) --
#define BM 64
#define BN 64
#define BK 16
__global__ void gemm_kernel(const float* __restrict__ A, const float* __restrict__ B,
                            const float* __restrict__ bias, float* __restrict__ C,
                            int M, int N, int K, int accum, int relu) {
    __shared__ float As[BK][BM + 1];
    __shared__ float Bs[BK][BN];
    int bm = blockIdx.y * BM;
    int bn = blockIdx.x * BN;
    int tid = threadIdx.x;
    int tx = tid & 15;
    int ty = tid >> 4;
    float r[4][4];
#pragma unroll
    for (int i = 0; i < 4; i++)
#pragma unroll
        for (int j = 0; j < 4; j++) r[i][j] = 0.0f;

    for (int k0 = 0; k0 < K; k0 += BK) {
#pragma unroll
        for (int i = 0; i < 4; i++) {
            int idx = tid + i * 256;      // 1024 elems of A tile
            int rr = idx >> 4;
            int cc = idx & 15;
            As[cc][rr] = A[(long)(bm + rr) * K + k0 + cc];
        }
#pragma unroll
        for (int i = 0; i < 4; i++) {
            int idx = tid + i * 256;      // 1024 elems of B tile
            int rr = idx >> 6;
            int cc = idx & 63;
            Bs[rr][cc] = B[(long)(k0 + rr) * N + bn + cc];
        }
        __syncthreads();
#pragma unroll
        for (int kk = 0; kk < BK; kk++) {
            float a[4], b[4];
#pragma unroll
            for (int i = 0; i < 4; i++) a[i] = As[kk][ty * 4 + i];
#pragma unroll
            for (int j = 0; j < 4; j++) b[j] = Bs[kk][tx * 4 + j];
#pragma unroll
            for (int i = 0; i < 4; i++)
#pragma unroll
                for (int j = 0; j < 4; j++) r[i][j] = fmaf(a[i], b[j], r[i][j]);
        }
        __syncthreads();
    }
#pragma unroll
    for (int i = 0; i < 4; i++) {
        long row = bm + ty * 4 + i;
#pragma unroll
        for (int j = 0; j < 4; j++) {
            int col = bn + tx * 4 + j;
            float val = r[i][j];
            if (accum) val += C[row * N + col];
            if (bias)  val += bias[col];
            if (relu)  val = fmaxf(val, 0.0f);
            C[row * N + col] = val;
        }
    }
}

// ---------------- pack nodes into [LMAX, NG, EMB] (zero padding) ------------
__global__ void pack_kernel(const float* __restrict__ z, const int* __restrict__ batches,
                            float* __restrict__ hp) {
    int l = blockIdx.x;
    int g = blockIdx.y;
    int st = batches[g];
    int len = batches[g + 1] - st;
    float* dst = hp + ((long)l * NG + g) * EMBD;
    if (l < len) {
        const float* src = z + (long)(st + l) * EMBD;
        dst[threadIdx.x] = src[threadIdx.x];
    } else {
        dst[threadIdx.x] = 0.0f;
    }
}

// ---------------- attention: one block per (graph, head) --------------------
__global__ void attn_kernel(const float* __restrict__ q, const float* __restrict__ k,
                            const float* __restrict__ v, const int* __restrict__ batches,
                            float* __restrict__ o) {
    int g = blockIdx.x;
    int hd = blockIdx.y;
    int len = batches[g + 1] - batches[g];
    extern __shared__ float sh[];
    float* Ks = sh;
    float* Vs = sh + LMAXC * DHD;
    for (int idx = threadIdx.x; idx < len * DHD; idx += blockDim.x) {
        int m = idx >> 5;
        int c = idx & 31;
        long off = ((long)m * NG + g) * EMBD + hd * DHD + c;
        Ks[idx] = k[off];
        Vs[idx] = v[off];
    }
    __syncthreads();

    int l = threadIdx.x;  // blockDim.x == LMAX
    const float scale = 0.17677669529663687f;  // 1/sqrt(32)
    float qr[DHD];
    const float* qp = q + ((long)l * NG + g) * EMBD + hd * DHD;
#pragma unroll
    for (int c = 0; c < DHD; c++) qr[c] = qp[c] * scale;

    float mx = -1e30f, sm = 0.0f;
    float acc[DHD];
#pragma unroll
    for (int c = 0; c < DHD; c++) acc[c] = 0.0f;

    for (int m = 0; m < len; m++) {
        const float* kr = Ks + m * DHD;
        float s = 0.0f;
#pragma unroll
        for (int c = 0; c < DHD; c++) s = fmaf(qr[c], kr[c], s);
        float nm = fmaxf(mx, s);
        float corr = __expf(mx - nm);
        float p = __expf(s - nm);
        sm = sm * corr + p;
        const float* vr = Vs + m * DHD;
#pragma unroll
        for (int c = 0; c < DHD; c++) acc[c] = fmaf(acc[c], corr, p * vr[c]);
        mx = nm;
    }
    float inv = 1.0f / sm;
    float* op = o + ((long)l * NG + g) * EMBD + hd * DHD;
#pragma unroll
    for (int c = 0; c < DHD; c++) op[c] = acc[c] * inv;
}

// ---------------- residual add + LayerNorm (row = 256) ----------------------
__global__ void add_ln_kernel(float* __restrict__ h, const float* __restrict__ t,
                              const float* __restrict__ gamma, const float* __restrict__ beta) {
    long row = blockIdx.x;
    int c = threadIdx.x;
    float val = h[row * EMBD + c] + t[row * EMBD + c];

    __shared__ float red[8];
    __shared__ float smean, srstd;
    int lane = c & 31, warp = c >> 5;

    float s = val;
#pragma unroll
    for (int off = 16; off; off >>= 1) s += __shfl_xor_sync(0xffffffffu, s, off);
    if (lane == 0) red[warp] = s;
    __syncthreads();
    if (c == 0) {
        float tot = 0.0f;
        for (int i = 0; i < 8; i++) tot += red[i];
        smean = tot * (1.0f / EMBD);
    }
    __syncthreads();
    float d = val - smean;
    float s2 = d * d;
#pragma unroll
    for (int off = 16; off; off >>= 1) s2 += __shfl_xor_sync(0xffffffffu, s2, off);
    if (lane == 0) red[warp] = s2;
    __syncthreads();
    if (c == 0) {
        float tot = 0.0f;
        for (int i = 0; i < 8; i++) tot += red[i];
        srstd = rsqrtf(tot * (1.0f / EMBD) + 1e-5f);
    }
    __syncthreads();
    h[row * EMBD + c] = d * srstd * gamma[c] + beta[c];
}

// ---------------- host orchestration ----------------------------------------
static void run_gemm(const float* A, const float* B, const float* bias, float* C,
                     int M, int N, int K, int accum, int relu) {
    dim3 grid(N / BN, M / BM);
    gemm_kernel<<<grid, 256>>>(A, B, bias, C, M, N, K, accum, relu);
}

extern "C" void kernel_launch(void* const* d_in, const int* in_sizes, int n_in,
                              void* d_out, int out_size) {
    const float* x       = (const float*)d_in[0];
    const int*   ei      = (const int*)d_in[1];
    const int*   batches = (const int*)d_in[2];

    int wi = 3;
    if (n_in >= 29 && in_sizes[3] == 1) wi = 4;  // skip scalar L_max if present

    const float* sW0  = (const float*)d_in[wi++];
    const float* sWn0 = (const float*)d_in[wi++];
    const float* sb0  = (const float*)d_in[wi++];
    const float* sW1  = (const float*)d_in[wi++];
    const float* sWn1 = (const float*)d_in[wi++];
    const float* sb1  = (const float*)d_in[wi++];
    const float* sW2  = (const float*)d_in[wi++];
    const float* sWn2 = (const float*)d_in[wi++];
    const float* sb2  = (const float*)d_in[wi++];
    const float* Wq   = (const float*)d_in[wi++];
    const float* Wk   = (const float*)d_in[wi++];
    const float* Wv   = (const float*)d_in[wi++];
    const float* bq   = (const float*)d_in[wi++];
    const float* bk   = (const float*)d_in[wi++];
    const float* bv   = (const float*)d_in[wi++];
    const float* Wo   = (const float*)d_in[wi++];
    const float* bo   = (const float*)d_in[wi++];
    const float* ln1g = (const float*)d_in[wi++];
    const float* ln1b = (const float*)d_in[wi++];
    const float* ln2g = (const float*)d_in[wi++];
    const float* ln2b = (const float*)d_in[wi++];
    const float* W1   = (const float*)d_in[wi++];
    const float* b1   = (const float*)d_in[wi++];
    const float* W2   = (const float*)d_in[wi++];
    const float* b2   = (const float*)d_in[wi++];

    float *deg, *agg, *ha, *hb, *hp, *q, *k, *v, *o, *tmp, *mid;
    cudaGetSymbolAddress((void**)&deg, g_deg);
    cudaGetSymbolAddress((void**)&agg, g_agg);
    cudaGetSymbolAddress((void**)&ha,  g_ha);
    cudaGetSymbolAddress((void**)&hb,  g_hb);
    cudaGetSymbolAddress((void**)&hp,  g_hp);
    cudaGetSymbolAddress((void**)&q,   g_q);
    cudaGetSymbolAddress((void**)&k,   g_k);
    cudaGetSymbolAddress((void**)&v,   g_v);
    cudaGetSymbolAddress((void**)&o,   g_o);
    cudaGetSymbolAddress((void**)&tmp, g_tmp);
    cudaGetSymbolAddress((void**)&mid, g_mid);

    // allow 80KB dynamic smem on attention kernel
    cudaFuncSetAttribute(attn_kernel, cudaFuncAttributeMaxDynamicSharedMemorySize,
                         2 * LMAXC * DHD * (int)sizeof(float));

    // ---- degrees ----
    cudaMemsetAsync(deg, 0, NN * sizeof(float), 0);
    deg_kernel<<<(NE + 255) / 256, 256>>>(ei, deg);

    // ---- SAGE layer 0 (input dim 16) ----
    cudaMemsetAsync(agg, 0, NN * 16 * sizeof(float), 0);
    {
        int total = NE * 4;  // D4 = 4
        scatter_kernel<<<(total + 255) / 256, 256>>>(x, ei, agg, 4);
        divdeg_kernel<<<(NN * 16 + 255) / 256, 256>>>(agg, deg, 16);
        run_gemm(x,   sW0,  nullptr, ha, NN, EMBD, 16, 0, 0);
        run_gemm(agg, sWn0, sb0,     ha, NN, EMBD, 16, 1, 1);
    }
    // ---- SAGE layer 1 ----
    cudaMemsetAsync(agg, 0, NN * EMBD * sizeof(float), 0);
    {
        int total = NE * 64;
        scatter_kernel<<<(total + 255) / 256, 256>>>(ha, ei, agg, 64);
        divdeg_kernel<<<(NN * EMBD + 255) / 256, 256>>>(agg, deg, EMBD);
        run_gemm(ha,  sW1,  nullptr, hb, NN, EMBD, EMBD, 0, 0);
        run_gemm(agg, sWn1, sb1,     hb, NN, EMBD, EMBD, 1, 1);
    }
    // ---- SAGE layer 2 (no relu) ----
    cudaMemsetAsync(agg, 0, NN * EMBD * sizeof(float), 0);
    {
        int total = NE * 64;
        scatter_kernel<<<(total + 255) / 256, 256>>>(hb, ei, agg, 64);
        divdeg_kernel<<<(NN * EMBD + 255) / 256, 256>>>(agg, deg, EMBD);
        run_gemm(hb,  sW2,  nullptr, ha, NN, EMBD, EMBD, 0, 0);
        run_gemm(agg, sWn2, sb2,     ha, NN, EMBD, EMBD, 1, 0);
    }

    // ---- pack & pad into [LMAX, NG, EMB] ----
    {
        dim3 grid(LMAXC, NG);
        pack_kernel<<<grid, EMBD>>>(ha, batches, hp);
    }

    // ---- 4 transformer layers ----
    const int E2 = EMBD * EMBD;
    for (int l = 0; l < 4; l++) {
        run_gemm(hp, Wq + (long)l * E2, bq + l * EMBD, q, NTOK, EMBD, EMBD, 0, 0);
        run_gemm(hp, Wk + (long)l * E2, bk + l * EMBD, k, NTOK, EMBD, EMBD, 0, 0);
        run_gemm(hp, Wv + (long)l * E2, bv + l * EMBD, v, NTOK, EMBD, EMBD, 0, 0);

        attn_kernel<<<dim3(NG, NHD), LMAXC, 2 * LMAXC * DHD * sizeof(float)>>>(
            q, k, v, batches, o);

        run_gemm(o, Wo + (long)l * E2, bo + l * EMBD, tmp, NTOK, EMBD, EMBD, 0, 0);
        add_ln_kernel<<<NTOK, EMBD>>>(hp, tmp, ln1g + l * EMBD, ln1b + l * EMBD);

        run_gemm(hp,  W1 + (long)l * EMBD * FFND, b1 + l * FFND, mid, NTOK, FFND, EMBD, 0, 1);
        run_gemm(mid, W2 + (long)l * FFND * EMBD, b2 + l * EMBD, tmp, NTOK, EMBD, FFND, 0, 0);
        add_ln_kernel<<<NTOK, EMBD>>>(hp, tmp, ln2g + l * EMBD, ln2b + l * EMBD);
    }

    cudaMemcpyAsync(d_out, hp, (size_t)NTOK * EMBD * sizeof(float),
                    cudaMemcpyDeviceToDevice, 0);
}

// round 2
// speedup vs baseline: 1.8282x; 1.8282x over previous
#include <cuda_runtime.h>
#include <math.h>
#include <stdint.h>

#define NN   16384
#define NE   262144
#define NG   64
#define LMAXC 320
#define EMBD 256
#define FFND 1024
#define NHD  8
#define DHD  32
#define NTOK (LMAXC*NG)

// ---------------- scratch (device globals; no allocation allowed) ----------
__device__ float g_deg[NN];
__device__ float g_agg[NN*EMBD];
__device__ float g_ha [NN*EMBD];
__device__ float g_hb [NN*EMBD];
__device__ float g_hp [NTOK*EMBD];
__device__ float g_q  [NTOK*EMBD];
__device__ float g_k  [NTOK*EMBD];
__device__ float g_v  [NTOK*EMBD];
__device__ float g_o  [NTOK*EMBD];
__device__ float g_tmp[NTOK*EMBD];
__device__ float g_mid[NTOK*FFND];

// ---------------- degree -----------------
__global__ void deg_kernel(const int* __restrict__ ei, float* __restrict__ deg) {
    int e = blockIdx.x * blockDim.x + threadIdx.x;
    if (e < NE) atomicAdd(&deg[ei[NE + e]], 1.0f);
}

// ---------------- scatter-add (float4 chunks) ----------------
__global__ void scatter_kernel(const float* __restrict__ feat, const int* __restrict__ ei,
                               float* __restrict__ out, int D4) {
    int t = blockIdx.x * blockDim.x + threadIdx.x;
    int total = NE * D4;
    if (t >= total) return;
    int e = t / D4;
    int c = t - e * D4;
    int s = ei[e];
    int d = ei[NE + e];
    float4 v = reinterpret_cast<const float4*>(feat)[(long)s * D4 + c];
    float* op = out + ((long)d * D4 + c) * 4;
    atomicAdd(op + 0, v.x);
    atomicAdd(op + 1, v.y);
    atomicAdd(op + 2, v.z);
    atomicAdd(op + 3, v.w);
}

__global__ void divdeg_kernel(float* __restrict__ agg, const float* __restrict__ deg, int D) {
    int t = blockIdx.x * blockDim.x + threadIdx.x;
    if (t >= NN * D) return;
    int i = t / D;
    agg[t] *= 1.0f / fmaxf(deg[i], 1.0f);
}

// ================= fp32 tiled GEMM (only for K=16 SAGE layer 0) =============
#define BM 64
#define BN 64
#define BK16 16
__global__ void gemm_kernel(const float* __restrict__ A, const float* __restrict__ B,
                            const float* __restrict__ bias, float* __restrict__ C,
                            int M, int N, int K, int accum, int relu) {
    __shared__ float As[BK16][BM + 1];
    __shared__ float Bs[BK16][BN];
    int bm = blockIdx.y * BM;
    int bn = blockIdx.x * BN;
    int tid = threadIdx.x;
    int tx = tid & 15;
    int ty = tid >> 4;
    float r[4][4];
#pragma unroll
    for (int i = 0; i < 4; i++)
#pragma unroll
        for (int j = 0; j < 4; j++) r[i][j] = 0.0f;

    for (int k0 = 0; k0 < K; k0 += BK16) {
#pragma unroll
        for (int i = 0; i < 4; i++) {
            int idx = tid + i * 256;
            int rr = idx >> 4;
            int cc = idx & 15;
            As[cc][rr] = A[(long)(bm + rr) * K + k0 + cc];
        }
#pragma unroll
        for (int i = 0; i < 4; i++) {
            int idx = tid + i * 256;
            int rr = idx >> 6;
            int cc = idx & 63;
            Bs[rr][cc] = B[(long)(k0 + rr) * N + bn + cc];
        }
        __syncthreads();
#pragma unroll
        for (int kk = 0; kk < BK16; kk++) {
            float a[4], b[4];
#pragma unroll
            for (int i = 0; i < 4; i++) a[i] = As[kk][ty * 4 + i];
#pragma unroll
            for (int j = 0; j < 4; j++) b[j] = Bs[kk][tx * 4 + j];
#pragma unroll
            for (int i = 0; i < 4; i++)
#pragma unroll
                for (int j = 0; j < 4; j++) r[i][j] = fmaf(a[i], b[j], r[i][j]);
        }
        __syncthreads();
    }
#pragma unroll
    for (int i = 0; i < 4; i++) {
        long row = bm + ty * 4 + i;
#pragma unroll
        for (int j = 0; j < 4; j++) {
            int col = bn + tx * 4 + j;
            float val = r[i][j];
            if (accum) val += C[row * N + col];
            if (bias)  val += bias[col];
            if (relu)  val = fmaxf(val, 0.0f);
            C[row * N + col] = val;
        }
    }
}

// ================= TF32 tensor-core GEMM ====================================
// C[M,N] (+)= A[M,K] @ B[K,N], optional bias + relu. M%128==0, N%128==0, K%32==0.
// Block 128x128x32, 8 warps (2x4), warp tile 64x32, mma.sync m16n8k8 tf32.
#define TBM 128
#define TBN 128
#define TBK 32
#define ASTR 36     // A smem row stride (floats): 32 + 4
#define BSTR 132    // B smem row stride (floats): 128 + 4
#define ABUF (TBM*ASTR)   // 4608 floats per buffer
#define BBUF (TBK*BSTR)   // 4224 floats per buffer

__device__ __forceinline__ uint32_t f2tf(float f) {
    uint32_t u;
    asm("cvt.rna.tf32.f32 %0, %1;" : "=r"(u) : "f"(f));
    return u;
}

#define CPA16(dst, src) asm volatile("cp.async.cg.shared.global [%0], [%1], 16;" :: "r"(dst), "l"(src))

__global__ void __launch_bounds__(256, 2)
gemm_tf32(const float* __restrict__ A, const float* __restrict__ B,
          const float* __restrict__ bias, float* __restrict__ C,
          int M, int N, int K, int accum, int relu) {
    extern __shared__ float sh[];
    const int tid  = threadIdx.x;
    const int lane = tid & 31;
    const int wid  = tid >> 5;
    const int wr   = wid >> 2;   // 0..1
    const int wc   = wid & 3;    // 0..3
    const int bm   = blockIdx.y * TBM;
    const int bn   = blockIdx.x * TBN;

    uint32_t sbase = (uint32_t)__cvta_generic_to_shared(sh);
    uint32_t aB = sbase;
    uint32_t bB = sbase + 2u * ABUF * 4u;

    float acc[4][4][4];
#pragma unroll
    for (int mt = 0; mt < 4; mt++)
#pragma unroll
        for (int nt = 0; nt < 4; nt++)
#pragma unroll
            for (int r = 0; r < 4; r++) acc[mt][nt][r] = 0.0f;

#define LOAD_TILES(buf, k0)                                                     \
    do {                                                                        \
        _Pragma("unroll")                                                       \
        for (int i = 0; i < 4; i++) {                                           \
            int c = tid + i * 256;                                              \
            int r = c >> 3, c4 = (c & 7) << 2;                                  \
            CPA16(aB + (uint32_t)((buf) * ABUF + r * ASTR + c4) * 4u,           \
                  A + (long)(bm + r) * K + (k0) + c4);                          \
        }                                                                       \
        _Pragma("unroll")                                                       \
        for (int i = 0; i < 4; i++) {                                           \
            int c = tid + i * 256;                                              \
            int r = c >> 5, c4 = (c & 31) << 2;                                 \
            CPA16(bB + (uint32_t)((buf) * BBUF + r * BSTR + c4) * 4u,           \
                  B + (long)((k0) + r) * N + bn + c4);                          \
        }                                                                       \
        asm volatile("cp.async.commit_group;");                                 \
    } while (0)

    const int nk = K / TBK;
    LOAD_TILES(0, 0);

    for (int it = 0; it < nk; it++) {
        int cur = it & 1;
        if (it + 1 < nk) {
            LOAD_TILES(cur ^ 1, (it + 1) * TBK);
            asm volatile("cp.async.wait_group 1;");
        } else {
            asm volatile("cp.async.wait_group 0;");
        }
        __syncthreads();

        const float* Ac = sh + cur * ABUF;
        const float* Bc = sh + 2 * ABUF + cur * BBUF;

#pragma unroll
        for (int ks = 0; ks < 4; ks++) {
            uint32_t af[4][4], bf[4][2];
            const int arow = wr * 64 + (lane >> 2);
            const int acol = ks * 8 + (lane & 3);
#pragma unroll
            for (int mt = 0; mt < 4; mt++) {
                const float* ap = Ac + (arow + mt * 16) * ASTR + acol;
                af[mt][0] = f2tf(ap[0]);
                af[mt][1] = f2tf(ap[8 * ASTR]);
                af[mt][2] = f2tf(ap[4]);
                af[mt][3] = f2tf(ap[8 * ASTR + 4]);
            }
            const int brow = ks * 8 + (lane & 3);
            const int bcol = wc * 32 + (lane >> 2);
#pragma unroll
            for (int nt = 0; nt < 4; nt++) {
                const float* bp = Bc + brow * BSTR + bcol + nt * 8;
                bf[nt][0] = f2tf(bp[0]);
                bf[nt][1] = f2tf(bp[4 * BSTR]);
            }
#pragma unroll
            for (int mt = 0; mt < 4; mt++)
#pragma unroll
                for (int nt = 0; nt < 4; nt++) {
                    asm volatile(
                        "mma.sync.aligned.m16n8k8.row.col.f32.tf32.tf32.f32 "
                        "{%0,%1,%2,%3}, {%4,%5,%6,%7}, {%8,%9}, {%0,%1,%2,%3};"
                        : "+f"(acc[mt][nt][0]), "+f"(acc[mt][nt][1]),
                          "+f"(acc[mt][nt][2]), "+f"(acc[mt][nt][3])
                        : "r"(af[mt][0]), "r"(af[mt][1]), "r"(af[mt][2]), "r"(af[mt][3]),
                          "r"(bf[nt][0]), "r"(bf[nt][1]));
                }
        }
        __syncthreads();
    }

    // epilogue: direct global store with accum/bias/relu
#pragma unroll
    for (int mt = 0; mt < 4; mt++) {
        int row = bm + wr * 64 + mt * 16 + (lane >> 2);
#pragma unroll
        for (int nt = 0; nt < 4; nt++) {
            int col = bn + wc * 32 + nt * 8 + ((lane & 3) << 1);
            long i0 = (long)row * N + col;
            long i1 = i0 + 8L * N;
            float v0 = acc[mt][nt][0], v1 = acc[mt][nt][1];
            float v2 = acc[mt][nt][2], v3 = acc[mt][nt][3];
            if (accum) { v0 += C[i0]; v1 += C[i0 + 1]; v2 += C[i1]; v3 += C[i1 + 1]; }
            if (bias)  { float b0 = bias[col], b1 = bias[col + 1];
                         v0 += b0; v1 += b1; v2 += b0; v3 += b1; }
            if (relu)  { v0 = fmaxf(v0, 0.f); v1 = fmaxf(v1, 0.f);
                         v2 = fmaxf(v2, 0.f); v3 = fmaxf(v3, 0.f); }
            C[i0] = v0; C[i0 + 1] = v1; C[i1] = v2; C[i1 + 1] = v3;
        }
    }
#undef LOAD_TILES
}

// ---------------- pack nodes into [LMAX, NG, EMB] (zero padding) ------------
__global__ void pack_kernel(const float* __restrict__ z, const int* __restrict__ batches,
                            float* __restrict__ hp) {
    int l = blockIdx.x;
    int g = blockIdx.y;
    int st = batches[g];
    int len = batches[g + 1] - st;
    float* dst = hp + ((long)l * NG + g) * EMBD;
    if (l < len) {
        const float* src = z + (long)(st + l) * EMBD;
        dst[threadIdx.x] = src[threadIdx.x];
    } else {
        dst[threadIdx.x] = 0.0f;
    }
}

// ---------------- attention: one block per (graph, head) --------------------
__global__ void attn_kernel(const float* __restrict__ q, const float* __restrict__ k,
                            const float* __restrict__ v, const int* __restrict__ batches,
                            float* __restrict__ o) {
    int g = blockIdx.x;
    int hd = blockIdx.y;
    int len = batches[g + 1] - batches[g];
    extern __shared__ float sh[];
    float* Ks = sh;
    float* Vs = sh + LMAXC * DHD;
    for (int idx = threadIdx.x; idx < len * DHD; idx += blockDim.x) {
        int m = idx >> 5;
        int c = idx & 31;
        long off = ((long)m * NG + g) * EMBD + hd * DHD + c;
        Ks[idx] = k[off];
        Vs[idx] = v[off];
    }
    __syncthreads();

    int l = threadIdx.x;
    const float scale = 0.17677669529663687f;
    float qr[DHD];
    const float* qp = q + ((long)l * NG + g) * EMBD + hd * DHD;
#pragma unroll
    for (int c = 0; c < DHD; c++) qr[c] = qp[c] * scale;

    float mx = -1e30f, sm = 0.0f;
    float acc[DHD];
#pragma unroll
    for (int c = 0; c < DHD; c++) acc[c] = 0.0f;

    for (int m = 0; m < len; m++) {
        const float* kr = Ks + m * DHD;
        float s = 0.0f;
#pragma unroll
        for (int c = 0; c < DHD; c++) s = fmaf(qr[c], kr[c], s);
        float nm = fmaxf(mx, s);
        float corr = __expf(mx - nm);
        float p = __expf(s - nm);
        sm = sm * corr + p;
        const float* vr = Vs + m * DHD;
#pragma unroll
        for (int c = 0; c < DHD; c++) acc[c] = fmaf(acc[c], corr, p * vr[c]);
        mx = nm;
    }
    float inv = 1.0f / sm;
    float* op = o + ((long)l * NG + g) * EMBD + hd * DHD;
#pragma unroll
    for (int c = 0; c < DHD; c++) op[c] = acc[c] * inv;
}

// ---------------- residual add + LayerNorm (row = 256) ----------------------
__global__ void add_ln_kernel(float* __restrict__ h, const float* __restrict__ t,
                              const float* __restrict__ gamma, const float* __restrict__ beta) {
    long row = blockIdx.x;
    int c = threadIdx.x;
    float val = h[row * EMBD + c] + t[row * EMBD + c];

    __shared__ float red[8];
    __shared__ float smean, srstd;
    int lane = c & 31, warp = c >> 5;

    float s = val;
#pragma unroll
    for (int off = 16; off; off >>= 1) s += __shfl_xor_sync(0xffffffffu, s, off);
    if (lane == 0) red[warp] = s;
    __syncthreads();
    if (c == 0) {
        float tot = 0.0f;
        for (int i = 0; i < 8; i++) tot += red[i];
        smean = tot * (1.0f / EMBD);
    }
    __syncthreads();
    float d = val - smean;
    float s2 = d * d;
#pragma unroll
    for (int off = 16; off; off >>= 1) s2 += __shfl_xor_sync(0xffffffffu, s2, off);
    if (lane == 0) red[warp] = s2;
    __syncthreads();
    if (c == 0) {
        float tot = 0.0f;
        for (int i = 0; i < 8; i++) tot += red[i];
        srstd = rsqrtf(tot * (1.0f / EMBD) + 1e-5f);
    }
    __syncthreads();
    h[row * EMBD + c] = d * srstd * gamma[c] + beta[c];
}

// ---------------- host orchestration ----------------------------------------
static void run_gemm_f32(const float* A, const float* B, const float* bias, float* C,
                         int M, int N, int K, int accum, int relu) {
    dim3 grid(N / BN, M / BM);
    gemm_kernel<<<grid, 256>>>(A, B, bias, C, M, N, K, accum, relu);
}

static const int TF32_SMEM = (2 * ABUF + 2 * BBUF) * (int)sizeof(float);  // 70656 B

static void run_gemm_tc(const float* A, const float* B, const float* bias, float* C,
                        int M, int N, int K, int accum, int relu) {
    dim3 grid(N / TBN, M / TBM);
    gemm_tf32<<<grid, 256, TF32_SMEM>>>(A, B, bias, C, M, N, K, accum, relu);
}

extern "C" void kernel_launch(void* const* d_in, const int* in_sizes, int n_in,
                              void* d_out, int out_size) {
    const float* x       = (const float*)d_in[0];
    const int*   ei      = (const int*)d_in[1];
    const int*   batches = (const int*)d_in[2];

    int wi = 3;
    if (n_in >= 29 && in_sizes[3] == 1) wi = 4;  // skip scalar L_max if present

    const float* sW0  = (const float*)d_in[wi++];
    const float* sWn0 = (const float*)d_in[wi++];
    const float* sb0  = (const float*)d_in[wi++];
    const float* sW1  = (const float*)d_in[wi++];
    const float* sWn1 = (const float*)d_in[wi++];
    const float* sb1  = (const float*)d_in[wi++];
    const float* sW2  = (const float*)d_in[wi++];
    const float* sWn2 = (const float*)d_in[wi++];
    const float* sb2  = (const float*)d_in[wi++];
    const float* Wq   = (const float*)d_in[wi++];
    const float* Wk   = (const float*)d_in[wi++];
    const float* Wv   = (const float*)d_in[wi++];
    const float* bq   = (const float*)d_in[wi++];
    const float* bk   = (const float*)d_in[wi++];
    const float* bv   = (const float*)d_in[wi++];
    const float* Wo   = (const float*)d_in[wi++];
    const float* bo   = (const float*)d_in[wi++];
    const float* ln1g = (const float*)d_in[wi++];
    const float* ln1b = (const float*)d_in[wi++];
    const float* ln2g = (const float*)d_in[wi++];
    const float* ln2b = (const float*)d_in[wi++];
    const float* W1   = (const float*)d_in[wi++];
    const float* b1   = (const float*)d_in[wi++];
    const float* W2   = (const float*)d_in[wi++];
    const float* b2   = (const float*)d_in[wi++];

    float *deg, *agg, *ha, *hb, *hp, *q, *k, *v, *o, *tmp, *mid;
    cudaGetSymbolAddress((void**)&deg, g_deg);
    cudaGetSymbolAddress((void**)&agg, g_agg);
    cudaGetSymbolAddress((void**)&ha,  g_ha);
    cudaGetSymbolAddress((void**)&hb,  g_hb);
    cudaGetSymbolAddress((void**)&hp,  g_hp);
    cudaGetSymbolAddress((void**)&q,   g_q);
    cudaGetSymbolAddress((void**)&k,   g_k);
    cudaGetSymbolAddress((void**)&v,   g_v);
    cudaGetSymbolAddress((void**)&o,   g_o);
    cudaGetSymbolAddress((void**)&tmp, g_tmp);
    cudaGetSymbolAddress((void**)&mid, g_mid);

    cudaFuncSetAttribute(attn_kernel, cudaFuncAttributeMaxDynamicSharedMemorySize,
                         2 * LMAXC * DHD * (int)sizeof(float));
    cudaFuncSetAttribute(gemm_tf32, cudaFuncAttributeMaxDynamicSharedMemorySize,
                         TF32_SMEM);

    // ---- degrees ----
    cudaMemsetAsync(deg, 0, NN * sizeof(float), 0);
    deg_kernel<<<(NE + 255) / 256, 256>>>(ei, deg);

    // ---- SAGE layer 0 (input dim 16, fp32 path) ----
    cudaMemsetAsync(agg, 0, NN * 16 * sizeof(float), 0);
    {
        int total = NE * 4;
        scatter_kernel<<<(total + 255) / 256, 256>>>(x, ei, agg, 4);
        divdeg_kernel<<<(NN * 16 + 255) / 256, 256>>>(agg, deg, 16);
        run_gemm_f32(x,   sW0,  nullptr, ha, NN, EMBD, 16, 0, 0);
        run_gemm_f32(agg, sWn0, sb0,     ha, NN, EMBD, 16, 1, 1);
    }
    // ---- SAGE layer 1 ----
    cudaMemsetAsync(agg, 0, NN * EMBD * sizeof(float), 0);
    {
        int total = NE * 64;
        scatter_kernel<<<(total + 255) / 256, 256>>>(ha, ei, agg, 64);
        divdeg_kernel<<<(NN * EMBD + 255) / 256, 256>>>(agg, deg, EMBD);
        run_gemm_tc(ha,  sW1,  nullptr, hb, NN, EMBD, EMBD, 0, 0);
        run_gemm_tc(agg, sWn1, sb1,     hb, NN, EMBD, EMBD, 1, 1);
    }
    // ---- SAGE layer 2 (no relu) ----
    cudaMemsetAsync(agg, 0, NN * EMBD * sizeof(float), 0);
    {
        int total = NE * 64;
        scatter_kernel<<<(total + 255) / 256, 256>>>(hb, ei, agg, 64);
        divdeg_kernel<<<(NN * EMBD + 255) / 256, 256>>>(agg, deg, EMBD);
        run_gemm_tc(hb,  sW2,  nullptr, ha, NN, EMBD, EMBD, 0, 0);
        run_gemm_tc(agg, sWn2, sb2,     ha, NN, EMBD, EMBD, 1, 0);
    }

    // ---- pack & pad into [LMAX, NG, EMB] ----
    {
        dim3 grid(LMAXC, NG);
        pack_kernel<<<grid, EMBD>>>(ha, batches, hp);
    }

    // ---- 4 transformer layers ----
    const int E2 = EMBD * EMBD;
    for (int l = 0; l < 4; l++) {
        run_gemm_tc(hp, Wq + (long)l * E2, bq + l * EMBD, q, NTOK, EMBD, EMBD, 0, 0);
        run_gemm_tc(hp, Wk + (long)l * E2, bk + l * EMBD, k, NTOK, EMBD, EMBD, 0, 0);
        run_gemm_tc(hp, Wv + (long)l * E2, bv + l * EMBD, v, NTOK, EMBD, EMBD, 0, 0);

        attn_kernel<<<dim3(NG, NHD), LMAXC, 2 * LMAXC * DHD * sizeof(float)>>>(
            q, k, v, batches, o);

        run_gemm_tc(o, Wo + (long)l * E2, bo + l * EMBD, tmp, NTOK, EMBD, EMBD, 0, 0);
        add_ln_kernel<<<NTOK, EMBD>>>(hp, tmp, ln1g + l * EMBD, ln1b + l * EMBD);

        run_gemm_tc(hp,  W1 + (long)l * EMBD * FFND, b1 + l * FFND, mid, NTOK, FFND, EMBD, 0, 1);
        run_gemm_tc(mid, W2 + (long)l * FFND * EMBD, b2 + l * EMBD, tmp, NTOK, EMBD, FFND, 0, 0);
        add_ln_kernel<<<NTOK, EMBD>>>(hp, tmp, ln2g + l * EMBD, ln2b + l * EMBD);
    }

    cudaMemcpyAsync(d_out, hp, (size_t)NTOK * EMBD * sizeof(float),
                    cudaMemcpyDeviceToDevice, 0);
}

// round 3
// speedup vs baseline: 2.3009x; 1.2586x over previous
#include <cuda_runtime.h>
#include <math.h>
#include <stdint.h>

#define NN   16384
#define NE   262144
#define NG   64
#define LMAXC 320
#define EMBD 256
#define FFND 1024
#define NHD  8
#define DHD  32
#define NTOK (LMAXC*NG)

// ---------------- scratch (device globals; no allocation allowed) ----------
__device__ int   g_rowptr[NN + 1];
__device__ int   g_cnt[NN];
__device__ int   g_csrc[NE];
__device__ float g_agg16[NN*16];
__device__ float g_comb1[NN*512];
__device__ float g_comb2[NN*512];
__device__ float g_ha [NN*EMBD];
__device__ float g_hp [NTOK*EMBD];
__device__ float g_qkv[NTOK*768];
__device__ float g_o  [NTOK*EMBD];
__device__ float g_tmp[NTOK*EMBD];
__device__ float g_mid[NTOK*FFND];
__device__ float g_wsg1[512*256];
__device__ float g_wsg2[512*256];
__device__ float g_wqkv[4*256*768];
__device__ float g_bqkv[4*768];

// =================== CSR build =============================================
__global__ void degi_kernel(const int* __restrict__ ei, int* __restrict__ cnt) {
    int e = blockIdx.x * blockDim.x + threadIdx.x;
    if (e < NE) atomicAdd(&cnt[ei[NE + e]], 1);
}

__global__ void scan_kernel(int* __restrict__ cnt, int* __restrict__ rowptr) {
    __shared__ int wsum[32];
    int t = threadIdx.x;            // 1024 threads, 16 elems each
    int base = t * 16;
    int loc[16];
    int s = 0;
#pragma unroll
    for (int i = 0; i < 16; i++) { loc[i] = s; s += cnt[base + i]; }
    int lane = t & 31, w = t >> 5;
    int inc = s;
#pragma unroll
    for (int off = 1; off < 32; off <<= 1) {
        int v = __shfl_up_sync(0xffffffffu, inc, off);
        if (lane >= off) inc += v;
    }
    if (lane == 31) wsum[w] = inc;
    __syncthreads();
    if (w == 0) {
        int v = wsum[lane];
#pragma unroll
        for (int off = 1; off < 32; off <<= 1) {
            int u = __shfl_up_sync(0xffffffffu, v, off);
            if (lane >= off) v += u;
        }
        wsum[lane] = v;
    }
    __syncthreads();
    int pre = inc - s + (w > 0 ? wsum[w - 1] : 0);
#pragma unroll
    for (int i = 0; i < 16; i++) { rowptr[base + i] = pre + loc[i]; cnt[base + i] = 0; }
    if (t == 1023) rowptr[NN] = pre + s;
}

__global__ void fill_kernel(const int* __restrict__ ei, int* __restrict__ cnt,
                            int* __restrict__ csrc) {
    int e = blockIdx.x * blockDim.x + threadIdx.x;
    if (e >= NE) return;
    int d = ei[NE + e];
    int pos = atomicAdd(&cnt[d], 1);
    csrc[g_rowptr[d] + pos] = ei[e];
}

// =================== mean aggregation via CSR ==============================
__global__ void agg16_kernel(const float* __restrict__ x, float* __restrict__ out) {
    int w = threadIdx.x >> 5;
    int lane = threadIdx.x & 31;
    int node = blockIdx.x * 8 + w;
    if (lane >= 16) return;
    int s0 = g_rowptr[node], s1 = g_rowptr[node + 1];
    float sum = 0.f;
    for (int j = s0; j < s1; j++) sum += x[g_csrc[j] * 16 + lane];
    out[node * 16 + lane] = sum / fmaxf((float)(s1 - s0), 1.f);
}

__global__ void agg_csr_kernel(const float* __restrict__ feat, long lda,
                               float* __restrict__ out, long ldo) {
    int node = blockIdx.x;
    int col = threadIdx.x;     // 256
    int s0 = g_rowptr[node], s1 = g_rowptr[node + 1];
    float sum = 0.f;
    int j = s0;
    for (; j + 4 <= s1; j += 4) {
        int n0 = g_csrc[j], n1 = g_csrc[j + 1], n2 = g_csrc[j + 2], n3 = g_csrc[j + 3];
        float a = feat[(long)n0 * lda + col];
        float b = feat[(long)n1 * lda + col];
        float c = feat[(long)n2 * lda + col];
        float d = feat[(long)n3 * lda + col];
        sum += (a + b) + (c + d);
    }
    for (; j < s1; j++) sum += feat[(long)g_csrc[j] * lda + col];
    out[(long)node * ldo + col] = sum / fmaxf((float)(s1 - s0), 1.f);
}

// =================== weight packing ========================================
__global__ void pack_pair_kernel(const float* __restrict__ Ws, const float* __restrict__ Wn,
                                 float* __restrict__ out) {
    int row = blockIdx.x;      // 512
    int col = threadIdx.x;     // 256
    out[row * 256 + col] = (row < 256) ? Ws[row * 256 + col] : Wn[(row - 256) * 256 + col];
}

__global__ void pack_qkv_kernel(const float* __restrict__ Wq, const float* __restrict__ Wk,
                                const float* __restrict__ Wv, const float* __restrict__ bq,
                                const float* __restrict__ bk, const float* __restrict__ bv,
                                float* __restrict__ W, float* __restrict__ b) {
    int col = threadIdx.x;     // 256
    int row = blockIdx.x;      // 256
    int s   = blockIdx.y;      // 3
    int l   = blockIdx.z;      // 4
    const float* src = (s == 0) ? Wq : ((s == 1) ? Wk : Wv);
    W[((long)l * 256 + row) * 768 + s * 256 + col] =
        src[((long)l * 256 + row) * 256 + col];
    if (row == 0) {
        const float* bs = (s == 0) ? bq : ((s == 1) ? bk : bv);
        b[l * 768 + s * 256 + col] = bs[l * 256 + col];
    }
}

// ================= fp32 tiled GEMM (only for K=16 SAGE layer 0) =============
#define BM 64
#define BN 64
#define BK16 16
__global__ void gemm_kernel(const float* __restrict__ A, const float* __restrict__ B,
                            const float* __restrict__ bias, float* __restrict__ C,
                            int M, int N, int K, int lda, int ldc, int accum, int relu) {
    __shared__ float As[BK16][BM + 1];
    __shared__ float Bs[BK16][BN];
    int bm = blockIdx.y * BM;
    int bn = blockIdx.x * BN;
    int tid = threadIdx.x;
    int tx = tid & 15;
    int ty = tid >> 4;
    float r[4][4];
#pragma unroll
    for (int i = 0; i < 4; i++)
#pragma unroll
        for (int j = 0; j < 4; j++) r[i][j] = 0.0f;

    for (int k0 = 0; k0 < K; k0 += BK16) {
#pragma unroll
        for (int i = 0; i < 4; i++) {
            int idx = tid + i * 256;
            int rr = idx >> 4;
            int cc = idx & 15;
            As[cc][rr] = A[(long)(bm + rr) * lda + k0 + cc];
        }
#pragma unroll
        for (int i = 0; i < 4; i++) {
            int idx = tid + i * 256;
            int rr = idx >> 6;
            int cc = idx & 63;
            Bs[rr][cc] = B[(long)(k0 + rr) * N + bn + cc];
        }
        __syncthreads();
#pragma unroll
        for (int kk = 0; kk < BK16; kk++) {
            float a[4], b[4];
#pragma unroll
            for (int i = 0; i < 4; i++) a[i] = As[kk][ty * 4 + i];
#pragma unroll
            for (int j = 0; j < 4; j++) b[j] = Bs[kk][tx * 4 + j];
#pragma unroll
            for (int i = 0; i < 4; i++)
#pragma unroll
                for (int j = 0; j < 4; j++) r[i][j] = fmaf(a[i], b[j], r[i][j]);
        }
        __syncthreads();
    }
#pragma unroll
    for (int i = 0; i < 4; i++) {
        long row = bm + ty * 4 + i;
#pragma unroll
        for (int j = 0; j < 4; j++) {
            int col = bn + tx * 4 + j;
            float val = r[i][j];
            if (accum) val += C[row * ldc + col];
            if (bias)  val += bias[col];
            if (relu)  val = fmaxf(val, 0.0f);
            C[row * ldc + col] = val;
        }
    }
}

// ================= TF32 tensor-core GEMM ====================================
#define TBM 128
#define TBN 128
#define TBK 32
#define ASTR 36
#define BSTR 132
#define ABUF (TBM*ASTR)
#define BBUF (TBK*BSTR)

__device__ __forceinline__ uint32_t f2tf(float f) {
    uint32_t u;
    asm("cvt.rna.tf32.f32 %0, %1;" : "=r"(u) : "f"(f));
    return u;
}

#define CPA16(dst, src) asm volatile("cp.async.cg.shared.global [%0], [%1], 16;" :: "r"(dst), "l"(src))

__global__ void __launch_bounds__(256, 2)
gemm_tf32(const float* __restrict__ A, const float* __restrict__ B,
          const float* __restrict__ bias, float* __restrict__ C,
          int M, int N, int K, int lda, int ldc, int relu) {
    extern __shared__ float sh[];
    const int tid  = threadIdx.x;
    const int lane = tid & 31;
    const int wid  = tid >> 5;
    const int wr   = wid >> 2;
    const int wc   = wid & 3;
    const int bm   = blockIdx.y * TBM;
    const int bn   = blockIdx.x * TBN;

    uint32_t sbase = (uint32_t)__cvta_generic_to_shared(sh);
    uint32_t aB = sbase;
    uint32_t bB = sbase + 2u * ABUF * 4u;

    float acc[4][4][4];
#pragma unroll
    for (int mt = 0; mt < 4; mt++)
#pragma unroll
        for (int nt = 0; nt < 4; nt++)
#pragma unroll
            for (int r = 0; r < 4; r++) acc[mt][nt][r] = 0.0f;

#define LOAD_TILES(buf, k0)                                                     \
    do {                                                                        \
        _Pragma("unroll")                                                       \
        for (int i = 0; i < 4; i++) {                                           \
            int c = tid + i * 256;                                              \
            int r = c >> 3, c4 = (c & 7) << 2;                                  \
            CPA16(aB + (uint32_t)((buf) * ABUF + r * ASTR + c4) * 4u,           \
                  A + (long)(bm + r) * lda + (k0) + c4);                        \
        }                                                                       \
        _Pragma("unroll")                                                       \
        for (int i = 0; i < 4; i++) {                                           \
            int c = tid + i * 256;                                              \
            int r = c >> 5, c4 = (c & 31) << 2;                                 \
            CPA16(bB + (uint32_t)((buf) * BBUF + r * BSTR + c4) * 4u,           \
                  B + (long)((k0) + r) * N + bn + c4);                          \
        }                                                                       \
        asm volatile("cp.async.commit_group;");                                 \
    } while (0)

    const int nk = K / TBK;
    LOAD_TILES(0, 0);

    for (int it = 0; it < nk; it++) {
        int cur = it & 1;
        if (it + 1 < nk) {
            LOAD_TILES(cur ^ 1, (it + 1) * TBK);
            asm volatile("cp.async.wait_group 1;");
        } else {
            asm volatile("cp.async.wait_group 0;");
        }
        __syncthreads();

        const float* Ac = sh + cur * ABUF;
        const float* Bc = sh + 2 * ABUF + cur * BBUF;

#pragma unroll
        for (int ks = 0; ks < 4; ks++) {
            uint32_t af[4][4], bf[4][2];
            const int arow = wr * 64 + (lane >> 2);
            const int acol = ks * 8 + (lane & 3);
#pragma unroll
            for (int mt = 0; mt < 4; mt++) {
                const float* ap = Ac + (arow + mt * 16) * ASTR + acol;
                af[mt][0] = f2tf(ap[0]);
                af[mt][1] = f2tf(ap[8 * ASTR]);
                af[mt][2] = f2tf(ap[4]);
                af[mt][3] = f2tf(ap[8 * ASTR + 4]);
            }
            const int brow = ks * 8 + (lane & 3);
            const int bcol = wc * 32 + (lane >> 2);
#pragma unroll
            for (int nt = 0; nt < 4; nt++) {
                const float* bp = Bc + brow * BSTR + bcol + nt * 8;
                bf[nt][0] = f2tf(bp[0]);
                bf[nt][1] = f2tf(bp[4 * BSTR]);
            }
#pragma unroll
            for (int mt = 0; mt < 4; mt++)
#pragma unroll
                for (int nt = 0; nt < 4; nt++) {
                    asm volatile(
                        "mma.sync.aligned.m16n8k8.row.col.f32.tf32.tf32.f32 "
                        "{%0,%1,%2,%3}, {%4,%5,%6,%7}, {%8,%9}, {%0,%1,%2,%3};"
                        : "+f"(acc[mt][nt][0]), "+f"(acc[mt][nt][1]),
                          "+f"(acc[mt][nt][2]), "+f"(acc[mt][nt][3])
                        : "r"(af[mt][0]), "r"(af[mt][1]), "r"(af[mt][2]), "r"(af[mt][3]),
                          "r"(bf[nt][0]), "r"(bf[nt][1]));
                }
        }
        __syncthreads();
    }

#pragma unroll
    for (int mt = 0; mt < 4; mt++) {
        int row = bm + wr * 64 + mt * 16 + (lane >> 2);
#pragma unroll
        for (int nt = 0; nt < 4; nt++) {
            int col = bn + wc * 32 + nt * 8 + ((lane & 3) << 1);
            long i0 = (long)row * ldc + col;
            long i1 = i0 + 8L * ldc;
            float v0 = acc[mt][nt][0], v1 = acc[mt][nt][1];
            float v2 = acc[mt][nt][2], v3 = acc[mt][nt][3];
            if (bias)  { float b0 = bias[col], b1 = bias[col + 1];
                         v0 += b0; v1 += b1; v2 += b0; v3 += b1; }
            if (relu)  { v0 = fmaxf(v0, 0.f); v1 = fmaxf(v1, 0.f);
                         v2 = fmaxf(v2, 0.f); v3 = fmaxf(v3, 0.f); }
            C[i0] = v0; C[i0 + 1] = v1; C[i1] = v2; C[i1 + 1] = v3;
        }
    }
#undef LOAD_TILES
}

// ---------------- pack nodes into [LMAX, NG, EMB] (zero padding) ------------
__global__ void pack_kernel(const float* __restrict__ z, const int* __restrict__ batches,
                            float* __restrict__ hp) {
    int l = blockIdx.x;
    int g = blockIdx.y;
    int st = batches[g];
    int len = batches[g + 1] - st;
    float* dst = hp + ((long)l * NG + g) * EMBD;
    if (l < len) {
        const float* src = z + (long)(st + l) * EMBD;
        dst[threadIdx.x] = src[threadIdx.x];
    } else {
        dst[threadIdx.x] = 0.0f;
    }
}

// ---------------- attention: one block per (graph, head) --------------------
__global__ void __launch_bounds__(LMAXC, 1)
attn_kernel(const float* __restrict__ qkv, const int* __restrict__ batches,
            float* __restrict__ o) {
    int g = blockIdx.x;
    int hd = blockIdx.y;
    int len = batches[g + 1] - batches[g];
    extern __shared__ float sh[];
    float4* K4 = (float4*)sh;                      // LMAXC*8 float4
    float4* V4 = (float4*)(sh + LMAXC * DHD);      // LMAXC*8 float4
    float4* pad_out = (float4*)(sh + 2 * LMAXC * DHD);  // 8 float4

    const float4* qkv4 = (const float4*)qkv;       // row stride 192 float4
    for (int idx = threadIdx.x; idx < len * 8; idx += LMAXC) {
        int m = idx >> 3, c = idx & 7;
        long base = ((long)m * NG + g) * 192 + hd * 8;
        K4[idx] = qkv4[base + 64 + c];
        V4[idx] = qkv4[base + 128 + c];
    }
    __syncthreads();

    int l = threadIdx.x;
    float4 res[8];
    if (l <= len) {
        int lq = (l < len) ? l : len;
        const float scale = 0.17677669529663687f;
        float4 q4[8];
        long qb = ((long)lq * NG + g) * 192 + hd * 8;
#pragma unroll
        for (int c = 0; c < 8; c++) {
            float4 t = qkv4[qb + c];
            q4[c] = make_float4(t.x * scale, t.y * scale, t.z * scale, t.w * scale);
        }
        float mx = -1e30f, sm = 0.f;
        float4 acc[8];
#pragma unroll
        for (int c = 0; c < 8; c++) acc[c] = make_float4(0.f, 0.f, 0.f, 0.f);

        int m = 0;
        for (; m + 4 <= len; m += 4) {
            float sa[4], sb[4];
#pragma unroll
            for (int i = 0; i < 4; i++) { sa[i] = 0.f; sb[i] = 0.f; }
#pragma unroll
            for (int c = 0; c < 8; c++) {
                float4 qq = q4[c];
#pragma unroll
                for (int i = 0; i < 4; i++) {
                    float4 kk = K4[(m + i) * 8 + c];
                    sa[i] = fmaf(qq.x, kk.x, sa[i]);
                    sb[i] = fmaf(qq.y, kk.y, sb[i]);
                    sa[i] = fmaf(qq.z, kk.z, sa[i]);
                    sb[i] = fmaf(qq.w, kk.w, sb[i]);
                }
            }
            float s0 = sa[0] + sb[0], s1 = sa[1] + sb[1];
            float s2 = sa[2] + sb[2], s3 = sa[3] + sb[3];
            float nm = fmaxf(mx, fmaxf(fmaxf(s0, s1), fmaxf(s2, s3)));
            float corr = __expf(mx - nm);
            float p0 = __expf(s0 - nm), p1 = __expf(s1 - nm);
            float p2 = __expf(s2 - nm), p3 = __expf(s3 - nm);
            sm = sm * corr + ((p0 + p1) + (p2 + p3));
#pragma unroll
            for (int c = 0; c < 8; c++) {
                float4 v0 = V4[m * 8 + c], v1 = V4[(m + 1) * 8 + c];
                float4 v2 = V4[(m + 2) * 8 + c], v3 = V4[(m + 3) * 8 + c];
                float4 a = acc[c];
                a.x = fmaf(p0, v0.x, fmaf(p1, v1.x, fmaf(p2, v2.x, fmaf(p3, v3.x, a.x * corr))));
                a.y = fmaf(p0, v0.y, fmaf(p1, v1.y, fmaf(p2, v2.y, fmaf(p3, v3.y, a.y * corr))));
                a.z = fmaf(p0, v0.z, fmaf(p1, v1.z, fmaf(p2, v2.z, fmaf(p3, v3.z, a.z * corr))));
                a.w = fmaf(p0, v0.w, fmaf(p1, v1.w, fmaf(p2, v2.w, fmaf(p3, v3.w, a.w * corr))));
                acc[c] = a;
            }
            mx = nm;
        }
        for (; m < len; m++) {
            float s = 0.f;
#pragma unroll
            for (int c = 0; c < 8; c++) {
                float4 qq = q4[c];
                float4 kk = K4[m * 8 + c];
                s = fmaf(qq.x, kk.x, s); s = fmaf(qq.y, kk.y, s);
                s = fmaf(qq.z, kk.z, s); s = fmaf(qq.w, kk.w, s);
            }
            float nm = fmaxf(mx, s);
            float corr = __expf(mx - nm);
            float p = __expf(s - nm);
            sm = sm * corr + p;
#pragma unroll
            for (int c = 0; c < 8; c++) {
                float4 vv = V4[m * 8 + c];
                float4 a = acc[c];
                a.x = fmaf(p, vv.x, a.x * corr);
                a.y = fmaf(p, vv.y, a.y * corr);
                a.z = fmaf(p, vv.z, a.z * corr);
                a.w = fmaf(p, vv.w, a.w * corr);
                acc[c] = a;
            }
            mx = nm;
        }
        float inv = 1.f / sm;
#pragma unroll
        for (int c = 0; c < 8; c++)
            res[c] = make_float4(acc[c].x * inv, acc[c].y * inv, acc[c].z * inv, acc[c].w * inv);
        if (l == len) {
#pragma unroll
            for (int c = 0; c < 8; c++) pad_out[c] = res[c];
        }
    }
    __syncthreads();
    if (l > len) {
#pragma unroll
        for (int c = 0; c < 8; c++) res[c] = pad_out[c];
    }
    float4* op = (float4*)(o + ((long)l * NG + g) * EMBD + hd * DHD);
#pragma unroll
    for (int c = 0; c < 8; c++) op[c] = res[c];
}

// ---------------- residual add + LayerNorm (row = 256) ----------------------
__global__ void add_ln_kernel(float* __restrict__ h, const float* __restrict__ t,
                              const float* __restrict__ gamma, const float* __restrict__ beta) {
    long row = blockIdx.x;
    int c = threadIdx.x;
    float val = h[row * EMBD + c] + t[row * EMBD + c];

    __shared__ float red[8];
    __shared__ float smean, srstd;
    int lane = c & 31, warp = c >> 5;

    float s = val;
#pragma unroll
    for (int off = 16; off; off >>= 1) s += __shfl_xor_sync(0xffffffffu, s, off);
    if (lane == 0) red[warp] = s;
    __syncthreads();
    if (c == 0) {
        float tot = 0.0f;
        for (int i = 0; i < 8; i++) tot += red[i];
        smean = tot * (1.0f / EMBD);
    }
    __syncthreads();
    float d = val - smean;
    float s2 = d * d;
#pragma unroll
    for (int off = 16; off; off >>= 1) s2 += __shfl_xor_sync(0xffffffffu, s2, off);
    if (lane == 0) red[warp] = s2;
    __syncthreads();
    if (c == 0) {
        float tot = 0.0f;
        for (int i = 0; i < 8; i++) tot += red[i];
        srstd = rsqrtf(tot * (1.0f / EMBD) + 1e-5f);
    }
    __syncthreads();
    h[row * EMBD + c] = d * srstd * gamma[c] + beta[c];
}

// ---------------- host orchestration ----------------------------------------
static const int TF32_SMEM = (2 * ABUF + 2 * BBUF) * (int)sizeof(float);
static const int ATTN_SMEM = (2 * LMAXC * DHD + 32) * (int)sizeof(float);

static void run_gemm_f32(const float* A, const float* B, const float* bias, float* C,
                         int M, int N, int K, int lda, int ldc, int accum, int relu) {
    dim3 grid(N / BN, M / BM);
    gemm_kernel<<<grid, 256>>>(A, B, bias, C, M, N, K, lda, ldc, accum, relu);
}

static void run_gemm_tc(const float* A, const float* B, const float* bias, float* C,
                        int M, int N, int K, int lda, int ldc, int relu) {
    dim3 grid(N / TBN, M / TBM);
    gemm_tf32<<<grid, 256, TF32_SMEM>>>(A, B, bias, C, M, N, K, lda, ldc, relu);
}

extern "C" void kernel_launch(void* const* d_in, const int* in_sizes, int n_in,
                              void* d_out, int out_size) {
    const float* x       = (const float*)d_in[0];
    const int*   ei      = (const int*)d_in[1];
    const int*   batches = (const int*)d_in[2];

    int wi = 3;
    if (n_in >= 29 && in_sizes[3] == 1) wi = 4;  // skip scalar L_max if present

    const float* sW0  = (const float*)d_in[wi++];
    const float* sWn0 = (const float*)d_in[wi++];
    const float* sb0  = (const float*)d_in[wi++];
    const float* sW1  = (const float*)d_in[wi++];
    const float* sWn1 = (const float*)d_in[wi++];
    const float* sb1  = (const float*)d_in[wi++];
    const float* sW2  = (const float*)d_in[wi++];
    const float* sWn2 = (const float*)d_in[wi++];
    const float* sb2  = (const float*)d_in[wi++];
    const float* Wq   = (const float*)d_in[wi++];
    const float* Wk   = (const float*)d_in[wi++];
    const float* Wv   = (const float*)d_in[wi++];
    const float* bq   = (const float*)d_in[wi++];
    const float* bk   = (const float*)d_in[wi++];
    const float* bv   = (const float*)d_in[wi++];
    const float* Wo   = (const float*)d_in[wi++];
    const float* bo   = (const float*)d_in[wi++];
    const float* ln1g = (const float*)d_in[wi++];
    const float* ln1b = (const float*)d_in[wi++];
    const float* ln2g = (const float*)d_in[wi++];
    const float* ln2b = (const float*)d_in[wi++];
    const float* W1   = (const float*)d_in[wi++];
    const float* b1   = (const float*)d_in[wi++];
    const float* W2   = (const float*)d_in[wi++];
    const float* b2   = (const float*)d_in[wi++];

    float *agg16, *comb1, *comb2, *ha, *hp, *qkv, *o, *tmp, *mid;
    float *wsg1, *wsg2, *wqkv, *bqkv;
    int *rowptr, *cnt, *csrc;
    cudaGetSymbolAddress((void**)&rowptr, g_rowptr);
    cudaGetSymbolAddress((void**)&cnt,    g_cnt);
    cudaGetSymbolAddress((void**)&csrc,   g_csrc);
    cudaGetSymbolAddress((void**)&agg16,  g_agg16);
    cudaGetSymbolAddress((void**)&comb1,  g_comb1);
    cudaGetSymbolAddress((void**)&comb2,  g_comb2);
    cudaGetSymbolAddress((void**)&ha,     g_ha);
    cudaGetSymbolAddress((void**)&hp,     g_hp);
    cudaGetSymbolAddress((void**)&qkv,    g_qkv);
    cudaGetSymbolAddress((void**)&o,      g_o);
    cudaGetSymbolAddress((void**)&tmp,    g_tmp);
    cudaGetSymbolAddress((void**)&mid,    g_mid);
    cudaGetSymbolAddress((void**)&wsg1,   g_wsg1);
    cudaGetSymbolAddress((void**)&wsg2,   g_wsg2);
    cudaGetSymbolAddress((void**)&wqkv,   g_wqkv);
    cudaGetSymbolAddress((void**)&bqkv,   g_bqkv);

    cudaFuncSetAttribute(attn_kernel, cudaFuncAttributeMaxDynamicSharedMemorySize, ATTN_SMEM);
    cudaFuncSetAttribute(gemm_tf32, cudaFuncAttributeMaxDynamicSharedMemorySize, TF32_SMEM);

    // ---- weight packing (runs every replay; deterministic, tiny) ----
    pack_pair_kernel<<<512, 256>>>(sW1, sWn1, wsg1);
    pack_pair_kernel<<<512, 256>>>(sW2, sWn2, wsg2);
    pack_qkv_kernel<<<dim3(256, 3, 4), 256>>>(Wq, Wk, Wv, bq, bk, bv, wqkv, bqkv);

    // ---- CSR build ----
    cudaMemsetAsync(cnt, 0, NN * sizeof(int), 0);
    degi_kernel<<<(NE + 255) / 256, 256>>>(ei, cnt);
    scan_kernel<<<1, 1024>>>(cnt, rowptr);
    fill_kernel<<<(NE + 255) / 256, 256>>>(ei, cnt, csrc);

    // ---- SAGE layer 0 (K=16, fp32) -> comb1 cols[0:256) ----
    agg16_kernel<<<NN / 8, 256>>>(x, agg16);
    run_gemm_f32(x,     sW0,  nullptr, comb1, NN, EMBD, 16, 16, 512, 0, 0);
    run_gemm_f32(agg16, sWn0, sb0,     comb1, NN, EMBD, 16, 16, 512, 1, 1);

    // ---- SAGE layer 1: agg -> comb1 cols[256:512), fused K=512 GEMM ----
    agg_csr_kernel<<<NN, 256>>>(comb1, 512, comb1 + 256, 512);
    run_gemm_tc(comb1, wsg1, sb1, comb2, NN, EMBD, 512, 512, 512, 1);

    // ---- SAGE layer 2 ----
    agg_csr_kernel<<<NN, 256>>>(comb2, 512, comb2 + 256, 512);
    run_gemm_tc(comb2, wsg2, sb2, ha, NN, EMBD, 512, 512, 256, 0);

    // ---- pack & pad into [LMAX, NG, EMB] ----
    {
        dim3 grid(LMAXC, NG);
        pack_kernel<<<grid, EMBD>>>(ha, batches, hp);
    }

    // ---- 4 transformer layers ----
    const int E2 = EMBD * EMBD;
    for (int l = 0; l < 4; l++) {
        run_gemm_tc(hp, wqkv + (long)l * 256 * 768, bqkv + l * 768, qkv,
                    NTOK, 768, 256, 256, 768, 0);

        attn_kernel<<<dim3(NG, NHD), LMAXC, ATTN_SMEM>>>(qkv, batches, o);

        run_gemm_tc(o, Wo + (long)l * E2, bo + l * EMBD, tmp,
                    NTOK, EMBD, EMBD, 256, 256, 0);
        add_ln_kernel<<<NTOK, EMBD>>>(hp, tmp, ln1g + l * EMBD, ln1b + l * EMBD);

        run_gemm_tc(hp,  W1 + (long)l * EMBD * FFND, b1 + l * FFND, mid,
                    NTOK, FFND, EMBD, 256, 1024, 1);
        run_gemm_tc(mid, W2 + (long)l * FFND * EMBD, b2 + l * EMBD, tmp,
                    NTOK, EMBD, FFND, 1024, 256, 0);
        add_ln_kernel<<<NTOK, EMBD>>>(hp, tmp, ln2g + l * EMBD, ln2b + l * EMBD);
    }

    cudaMemcpyAsync(d_out, hp, (size_t)NTOK * EMBD * sizeof(float),
                    cudaMemcpyDeviceToDevice, 0);
}

// round 4
// speedup vs baseline: 3.2128x; 1.3963x over previous
#include <cuda_runtime.h>
#include <cuda_fp16.h>
#include <math.h>
#include <stdint.h>

#define NN   16384
#define NE   262144
#define NG   64
#define LMAXC 320
#define EMBD 256
#define FFND 1024
#define NHD  8
#define DHD  32
#define NTOK (LMAXC*EMBD/4)   // placeholder avoided below
#undef NTOK
#define NTOK (LMAXC*NG)

// ---------------- scratch (device globals; no allocation allowed) ----------
__device__ int   g_rowptr[NN + 1];
__device__ int   g_cnt[NN];
__device__ int   g_csrc[NE];
__device__ float g_comb0[NN*32];
__device__ float g_wsg0[32*256];
__device__ __align__(256) __half g_comb1h[NN*512];
__device__ __align__(256) __half g_comb2h[NN*512];
__device__ float g_ha [NN*EMBD];
__device__ float g_hp [NTOK*EMBD];
__device__ __align__(256) __half g_hph[NTOK*EMBD];
__device__ float g_qkv[NTOK*768];
__device__ __align__(256) __half g_oh[NTOK*EMBD];
__device__ float g_tmp[NTOK*EMBD];
__device__ __align__(256) __half g_midh[NTOK*FFND];
__device__ __align__(256) __half g_wsg1t[256*512];
__device__ __align__(256) __half g_wsg2t[256*512];
__device__ __align__(256) __half g_wqkvt[4*768*256];
__device__ __align__(256) __half g_wot[4*256*256];
__device__ __align__(256) __half g_w1t[4*1024*256];
__device__ __align__(256) __half g_w2t[4*256*1024];
__device__ float g_bqkv[4*768];

// =================== CSR build =============================================
__global__ void degi_kernel(const int* __restrict__ ei, int* __restrict__ cnt) {
    int e = blockIdx.x * blockDim.x + threadIdx.x;
    if (e < NE) atomicAdd(&cnt[ei[NE + e]], 1);
}

__global__ void scan_kernel(int* __restrict__ cnt, int* __restrict__ rowptr) {
    __shared__ int wsum[32];
    int t = threadIdx.x;
    int base = t * 16;
    int loc[16];
    int s = 0;
#pragma unroll
    for (int i = 0; i < 16; i++) { loc[i] = s; s += cnt[base + i]; }
    int lane = t & 31, w = t >> 5;
    int inc = s;
#pragma unroll
    for (int off = 1; off < 32; off <<= 1) {
        int v = __shfl_up_sync(0xffffffffu, inc, off);
        if (lane >= off) inc += v;
    }
    if (lane == 31) wsum[w] = inc;
    __syncthreads();
    if (w == 0) {
        int v = wsum[lane];
#pragma unroll
        for (int off = 1; off < 32; off <<= 1) {
            int u = __shfl_up_sync(0xffffffffu, v, off);
            if (lane >= off) v += u;
        }
        wsum[lane] = v;
    }
    __syncthreads();
    int pre = inc - s + (w > 0 ? wsum[w - 1] : 0);
#pragma unroll
    for (int i = 0; i < 16; i++) { rowptr[base + i] = pre + loc[i]; cnt[base + i] = 0; }
    if (t == 1023) rowptr[NN] = pre + s;
}

__global__ void fill_kernel(const int* __restrict__ ei, int* __restrict__ cnt,
                            int* __restrict__ csrc) {
    int e = blockIdx.x * blockDim.x + threadIdx.x;
    if (e >= NE) return;
    int d = ei[NE + e];
    int pos = atomicAdd(&cnt[d], 1);
    csrc[g_rowptr[d] + pos] = ei[e];
}

// =================== SAGE layer-0 input assembly ===========================
// comb0[node] = [ x[node] (16) | mean_agg(x)[node] (16) ]
__global__ void agg0_kernel(const float* __restrict__ x, float* __restrict__ comb0) {
    int w = threadIdx.x >> 5;
    int lane = threadIdx.x & 31;
    int node = blockIdx.x * 8 + w;
    if (lane >= 16) return;
    int s0 = g_rowptr[node], s1 = g_rowptr[node + 1];
    float sum = 0.f;
    for (int j = s0; j < s1; j++) sum += x[g_csrc[j] * 16 + lane];
    comb0[node * 32 + lane] = x[node * 16 + lane];
    comb0[node * 32 + 16 + lane] = sum / fmaxf((float)(s1 - s0), 1.f);
}

// mean agg over half features: feat [NN x 512], cols 0-255 in -> cols 256-511 out
__global__ void agg_csr_h(__half* __restrict__ feat) {
    int node = blockIdx.x;
    int c = threadIdx.x;   // 128 threads, each one half2 column pair
    const __half2* f2 = (const __half2*)feat;
    int s0 = g_rowptr[node], s1 = g_rowptr[node + 1];
    float sx = 0.f, sy = 0.f;
    int j = s0;
    for (; j + 2 <= s1; j += 2) {
        int n0 = g_csrc[j], n1 = g_csrc[j + 1];
        float2 a = __half22float2(f2[(long)n0 * 256 + c]);
        float2 b = __half22float2(f2[(long)n1 * 256 + c]);
        sx += a.x + b.x; sy += a.y + b.y;
    }
    for (; j < s1; j++) {
        float2 a = __half22float2(f2[(long)g_csrc[j] * 256 + c]);
        sx += a.x; sy += a.y;
    }
    float inv = 1.f / fmaxf((float)(s1 - s0), 1.f);
    ((__half2*)feat)[(long)node * 256 + 128 + c] = __floats2half2_rn(sx * inv, sy * inv);
}

// =================== weight packing ========================================
__global__ void pack0_kernel(const float* __restrict__ Ws, const float* __restrict__ Wn,
                             float* __restrict__ out) {
    int k = blockIdx.x;   // 32
    int n = threadIdx.x;  // 256
    out[k * 256 + n] = (k < 16) ? Ws[k * 256 + n] : Wn[(k - 16) * 256 + n];
}

__global__ void pack_bqkv(const float* __restrict__ bq, const float* __restrict__ bk,
                          const float* __restrict__ bv, float* __restrict__ b) {
    int c = threadIdx.x, s = blockIdx.x, l = blockIdx.y;
    const float* src = (s == 0) ? bq : ((s == 1) ? bk : bv);
    b[l * 768 + s * 256 + c] = src[l * 256 + c];
}

// tiled transpose fp32 [K,N] -> half [N,K-ish] with dst row stride ldd
__global__ void transpose_h(const float* __restrict__ src, __half* __restrict__ dst,
                            int N, long src_lstride, long dst_lstride, int ldd) {
    __shared__ float t[32][33];
    const float* s = src + blockIdx.z * src_lstride;
    __half* d = dst + blockIdx.z * dst_lstride;
    int k0 = blockIdx.y * 32, n0 = blockIdx.x * 32;
    int tx = threadIdx.x, ty = threadIdx.y;
#pragma unroll
    for (int i = 0; i < 32; i += 8)
        t[ty + i][tx] = s[(long)(k0 + ty + i) * N + n0 + tx];
    __syncthreads();
#pragma unroll
    for (int i = 0; i < 32; i += 8)
        d[(long)(n0 + ty + i) * ldd + k0 + tx] = __float2half(t[tx][ty + i]);
}

// ================= fp32 GEMM K=32 for SAGE layer 0, half output =============
#define BM 64
#define BN 64
__global__ void gemm32h_kernel(const float* __restrict__ A, const float* __restrict__ B,
                               const float* __restrict__ bias, __half* __restrict__ C,
                               int ldc) {
    __shared__ float As[16][BM + 1];
    __shared__ float Bs[16][BN];
    int bm = blockIdx.y * BM;
    int bn = blockIdx.x * BN;
    int tid = threadIdx.x;
    int tx = tid & 15;
    int ty = tid >> 4;
    float r[4][4];
#pragma unroll
    for (int i = 0; i < 4; i++)
#pragma unroll
        for (int j = 0; j < 4; j++) r[i][j] = 0.0f;

    for (int k0 = 0; k0 < 32; k0 += 16) {
#pragma unroll
        for (int i = 0; i < 4; i++) {
            int idx = tid + i * 256;
            int rr = idx >> 4, cc = idx & 15;
            As[cc][rr] = A[(long)(bm + rr) * 32 + k0 + cc];
        }
#pragma unroll
        for (int i = 0; i < 4; i++) {
            int idx = tid + i * 256;
            int rr = idx >> 6, cc = idx & 63;
            Bs[rr][cc] = B[(long)(k0 + rr) * 256 + bn + cc];
        }
        __syncthreads();
#pragma unroll
        for (int kk = 0; kk < 16; kk++) {
            float a[4], b[4];
#pragma unroll
            for (int i = 0; i < 4; i++) a[i] = As[kk][ty * 4 + i];
#pragma unroll
            for (int j = 0; j < 4; j++) b[j] = Bs[kk][tx * 4 + j];
#pragma unroll
            for (int i = 0; i < 4; i++)
#pragma unroll
                for (int j = 0; j < 4; j++) r[i][j] = fmaf(a[i], b[j], r[i][j]);
        }
        __syncthreads();
    }
#pragma unroll
    for (int i = 0; i < 4; i++) {
        long row = bm + ty * 4 + i;
        __half2* C2 = (__half2*)(C + row * ldc + bn + tx * 4);
#pragma unroll
        for (int j = 0; j < 4; j += 2) {
            int col = bn + tx * 4 + j;
            float v0 = fmaxf(r[i][j] + bias[col], 0.f);
            float v1 = fmaxf(r[i][j + 1] + bias[col + 1], 0.f);
            C2[j >> 1] = __floats2half2_rn(v0, v1);
        }
    }
}

// ================= FP16 tensor-core GEMM (ldmatrix + m16n8k16) ==============
// C[M,N] = A[M,K](half,row-major) @ Bt[N,K](half,"B transposed") + bias
// 128x128x64 CTA tile, 8 warps (2x4), warp tile 64x32.
#define HSTR 72                 // smem row stride in halves (144 B)
#define HBUF (128*HSTR)         // halves per buffer
#define HSMEM (4*HBUF*2)        // bytes: A x2 + B x2

#define CPA16(dst, src) asm volatile("cp.async.cg.shared.global [%0], [%1], 16;" :: "r"(dst), "l"(src))

__device__ __forceinline__ void ldsm4(uint32_t (&r)[4], uint32_t addr) {
    asm volatile("ldmatrix.sync.aligned.m8n8.x4.shared.b16 {%0,%1,%2,%3}, [%4];"
                 : "=r"(r[0]), "=r"(r[1]), "=r"(r[2]), "=r"(r[3]) : "r"(addr));
}
__device__ __forceinline__ void ldsm2(uint32_t (&r)[2], uint32_t addr) {
    asm volatile("ldmatrix.sync.aligned.m8n8.x2.shared.b16 {%0,%1}, [%2];"
                 : "=r"(r[0]), "=r"(r[1]) : "r"(addr));
}

__global__ void __launch_bounds__(256, 2)
hgemm(const __half* __restrict__ A, const __half* __restrict__ Bt,
      const float* __restrict__ bias, void* __restrict__ Cv,
      int M, int N, int K, int lda, int ldc, int relu, int outh) {
    extern __shared__ __half shh[];
    const int tid  = threadIdx.x;
    const int lane = tid & 31;
    const int wid  = tid >> 5;
    const int wr   = wid >> 2;   // 0..1
    const int wc   = wid & 3;    // 0..3
    const int bm   = blockIdx.y * 128;
    const int bn   = blockIdx.x * 128;

    uint32_t sbase = (uint32_t)__cvta_generic_to_shared(shh);

    float acc[4][4][4];
#pragma unroll
    for (int mt = 0; mt < 4; mt++)
#pragma unroll
        for (int nt = 0; nt < 4; nt++)
#pragma unroll
            for (int r = 0; r < 4; r++) acc[mt][nt][r] = 0.0f;

#define HLOAD(buf, k0)                                                          \
    do {                                                                        \
        _Pragma("unroll")                                                       \
        for (int i = 0; i < 4; i++) {                                           \
            int idx = tid + i * 256;                                            \
            int r = idx >> 3, c = (idx & 7) << 3;                               \
            CPA16(sbase + (uint32_t)((buf) * HBUF + r * HSTR + c) * 2u,         \
                  A + (long)(bm + r) * lda + (k0) + c);                         \
        }                                                                       \
        _Pragma("unroll")                                                       \
        for (int i = 0; i < 4; i++) {                                           \
            int idx = tid + i * 256;                                            \
            int r = idx >> 3, c = (idx & 7) << 3;                               \
            CPA16(sbase + (uint32_t)((2 + (buf)) * HBUF + r * HSTR + c) * 2u,   \
                  Bt + (long)(bn + r) * K + (k0) + c);                          \
        }                                                                       \
        asm volatile("cp.async.commit_group;");                                 \
    } while (0)

    const int nk = K >> 6;
    HLOAD(0, 0);

    const int arow = wr * 64 + (lane & 15);
    const int ach  = (lane >> 4) << 3;          // 0 or 8 halves
    const int brow = wc * 32 + (lane & 7);
    const int bch  = ((lane >> 3) & 1) << 3;

    for (int it = 0; it < nk; it++) {
        int cur = it & 1;
        if (it + 1 < nk) {
            HLOAD(cur ^ 1, (it + 1) << 6);
            asm volatile("cp.async.wait_group 1;");
        } else {
            asm volatile("cp.async.wait_group 0;");
        }
        __syncthreads();

        uint32_t aB = sbase + (uint32_t)(cur * HBUF) * 2u;
        uint32_t bB = sbase + (uint32_t)((2 + cur) * HBUF) * 2u;

#pragma unroll
        for (int ks = 0; ks < 4; ks++) {
            uint32_t af[4][4], bf[4][2];
#pragma unroll
            for (int mt = 0; mt < 4; mt++)
                ldsm4(af[mt], aB + (uint32_t)((arow + mt * 16) * HSTR + ks * 16 + ach) * 2u);
#pragma unroll
            for (int nt = 0; nt < 4; nt++)
                ldsm2(bf[nt], bB + (uint32_t)((brow + nt * 8) * HSTR + ks * 16 + bch) * 2u);
#pragma unroll
            for (int mt = 0; mt < 4; mt++)
#pragma unroll
                for (int nt = 0; nt < 4; nt++) {
                    asm volatile(
                        "mma.sync.aligned.m16n8k16.row.col.f32.f16.f16.f32 "
                        "{%0,%1,%2,%3}, {%4,%5,%6,%7}, {%8,%9}, {%0,%1,%2,%3};"
                        : "+f"(acc[mt][nt][0]), "+f"(acc[mt][nt][1]),
                          "+f"(acc[mt][nt][2]), "+f"(acc[mt][nt][3])
                        : "r"(af[mt][0]), "r"(af[mt][1]), "r"(af[mt][2]), "r"(af[mt][3]),
                          "r"(bf[nt][0]), "r"(bf[nt][1]));
                }
        }
        __syncthreads();
    }

#pragma unroll
    for (int mt = 0; mt < 4; mt++) {
        int row = bm + wr * 64 + mt * 16 + (lane >> 2);
#pragma unroll
        for (int nt = 0; nt < 4; nt++) {
            int col = bn + wc * 32 + nt * 8 + ((lane & 3) << 1);
            float b0 = bias[col], b1 = bias[col + 1];
            float v0 = acc[mt][nt][0] + b0, v1 = acc[mt][nt][1] + b1;
            float v2 = acc[mt][nt][2] + b0, v3 = acc[mt][nt][3] + b1;
            if (relu) { v0 = fmaxf(v0, 0.f); v1 = fmaxf(v1, 0.f);
                        v2 = fmaxf(v2, 0.f); v3 = fmaxf(v3, 0.f); }
            if (outh) {
                __half2* C2 = (__half2*)Cv;
                C2[((long)row * ldc + col) >> 1]       = __floats2half2_rn(v0, v1);
                C2[((long)(row + 8) * ldc + col) >> 1] = __floats2half2_rn(v2, v3);
            } else {
                float* C = (float*)Cv;
                long i0 = (long)row * ldc + col;
                long i1 = i0 + 8L * ldc;
                C[i0] = v0; C[i0 + 1] = v1; C[i1] = v2; C[i1 + 1] = v3;
            }
        }
    }
#undef HLOAD
}

// ---------------- pack nodes into [LMAX, NG, EMB] (zero padding) ------------
__global__ void pack_kernel(const float* __restrict__ z, const int* __restrict__ batches,
                            float* __restrict__ hp, __half* __restrict__ hph) {
    int l = blockIdx.x;
    int g = blockIdx.y;
    int st = batches[g];
    int len = batches[g + 1] - st;
    long o = ((long)l * NG + g) * EMBD + threadIdx.x;
    float v = (l < len) ? z[(long)(st + l) * EMBD + threadIdx.x] : 0.0f;
    hp[o] = v;
    hph[o] = __float2half(v);
}

// ---------------- attention: one block per (graph, head) --------------------
__global__ void __launch_bounds__(LMAXC, 1)
attn_kernel(const float* __restrict__ qkv, const int* __restrict__ batches,
            __half* __restrict__ oh) {
    int g = blockIdx.x;
    int hd = blockIdx.y;
    int len = batches[g + 1] - batches[g];
    extern __shared__ float sh[];
    float4* K4 = (float4*)sh;
    float4* V4 = (float4*)(sh + LMAXC * DHD);
    float4* pad_out = (float4*)(sh + 2 * LMAXC * DHD);

    const float4* qkv4 = (const float4*)qkv;
    for (int idx = threadIdx.x; idx < len * 8; idx += LMAXC) {
        int m = idx >> 3, c = idx & 7;
        long base = ((long)m * NG + g) * 192 + hd * 8;
        K4[idx] = qkv4[base + 64 + c];
        V4[idx] = qkv4[base + 128 + c];
    }
    __syncthreads();

    int l = threadIdx.x;
    float4 res[8];
    if (l <= len) {
        int lq = (l < len) ? l : len;
        const float scale = 0.17677669529663687f;
        float4 q4[8];
        long qb = ((long)lq * NG + g) * 192 + hd * 8;
#pragma unroll
        for (int c = 0; c < 8; c++) {
            float4 t = qkv4[qb + c];
            q4[c] = make_float4(t.x * scale, t.y * scale, t.z * scale, t.w * scale);
        }
        float mx = -1e30f, sm = 0.f;
        float4 acc[8];
#pragma unroll
        for (int c = 0; c < 8; c++) acc[c] = make_float4(0.f, 0.f, 0.f, 0.f);

        int m = 0;
        for (; m + 4 <= len; m += 4) {
            float sa[4], sb[4];
#pragma unroll
            for (int i = 0; i < 4; i++) { sa[i] = 0.f; sb[i] = 0.f; }
#pragma unroll
            for (int c = 0; c < 8; c++) {
                float4 qq = q4[c];
#pragma unroll
                for (int i = 0; i < 4; i++) {
                    float4 kk = K4[(m + i) * 8 + c];
                    sa[i] = fmaf(qq.x, kk.x, sa[i]);
                    sb[i] = fmaf(qq.y, kk.y, sb[i]);
                    sa[i] = fmaf(qq.z, kk.z, sa[i]);
                    sb[i] = fmaf(qq.w, kk.w, sb[i]);
                }
            }
            float s0 = sa[0] + sb[0], s1 = sa[1] + sb[1];
            float s2 = sa[2] + sb[2], s3 = sa[3] + sb[3];
            float nm = fmaxf(mx, fmaxf(fmaxf(s0, s1), fmaxf(s2, s3)));
            float corr = __expf(mx - nm);
            float p0 = __expf(s0 - nm), p1 = __expf(s1 - nm);
            float p2 = __expf(s2 - nm), p3 = __expf(s3 - nm);
            sm = sm * corr + ((p0 + p1) + (p2 + p3));
#pragma unroll
            for (int c = 0; c < 8; c++) {
                float4 v0 = V4[m * 8 + c], v1 = V4[(m + 1) * 8 + c];
                float4 v2 = V4[(m + 2) * 8 + c], v3 = V4[(m + 3) * 8 + c];
                float4 a = acc[c];
                a.x = fmaf(p0, v0.x, fmaf(p1, v1.x, fmaf(p2, v2.x, fmaf(p3, v3.x, a.x * corr))));
                a.y = fmaf(p0, v0.y, fmaf(p1, v1.y, fmaf(p2, v2.y, fmaf(p3, v3.y, a.y * corr))));
                a.z = fmaf(p0, v0.z, fmaf(p1, v1.z, fmaf(p2, v2.z, fmaf(p3, v3.z, a.z * corr))));
                a.w = fmaf(p0, v0.w, fmaf(p1, v1.w, fmaf(p2, v2.w, fmaf(p3, v3.w, a.w * corr))));
                acc[c] = a;
            }
            mx = nm;
        }
        for (; m < len; m++) {
            float s = 0.f;
#pragma unroll
            for (int c = 0; c < 8; c++) {
                float4 qq = q4[c];
                float4 kk = K4[m * 8 + c];
                s = fmaf(qq.x, kk.x, s); s = fmaf(qq.y, kk.y, s);
                s = fmaf(qq.z, kk.z, s); s = fmaf(qq.w, kk.w, s);
            }
            float nm = fmaxf(mx, s);
            float corr = __expf(mx - nm);
            float p = __expf(s - nm);
            sm = sm * corr + p;
#pragma unroll
            for (int c = 0; c < 8; c++) {
                float4 vv = V4[m * 8 + c];
                float4 a = acc[c];
                a.x = fmaf(p, vv.x, a.x * corr);
                a.y = fmaf(p, vv.y, a.y * corr);
                a.z = fmaf(p, vv.z, a.z * corr);
                a.w = fmaf(p, vv.w, a.w * corr);
                acc[c] = a;
            }
            mx = nm;
        }
        float inv = 1.f / sm;
#pragma unroll
        for (int c = 0; c < 8; c++)
            res[c] = make_float4(acc[c].x * inv, acc[c].y * inv, acc[c].z * inv, acc[c].w * inv);
        if (l == len) {
#pragma unroll
            for (int c = 0; c < 8; c++) pad_out[c] = res[c];
        }
    }
    __syncthreads();
    if (l > len) {
#pragma unroll
        for (int c = 0; c < 8; c++) res[c] = pad_out[c];
    }
    __half2* op2 = (__half2*)oh + (((long)l * NG + g) * EMBD + hd * DHD) / 2;
#pragma unroll
    for (int c = 0; c < 8; c++) {
        op2[2 * c]     = __floats2half2_rn(res[c].x, res[c].y);
        op2[2 * c + 1] = __floats2half2_rn(res[c].z, res[c].w);
    }
}

// ---------------- residual add + LayerNorm (row = 256), dual output ---------
__global__ void add_ln_kernel(float* __restrict__ h, __half* __restrict__ hh,
                              const float* __restrict__ t,
                              const float* __restrict__ gamma, const float* __restrict__ beta) {
    long row = blockIdx.x;
    int c = threadIdx.x;
    float val = h[row * EMBD + c] + t[row * EMBD + c];

    __shared__ float red[8];
    __shared__ float smean, srstd;
    int lane = c & 31, warp = c >> 5;

    float s = val;
#pragma unroll
    for (int off = 16; off; off >>= 1) s += __shfl_xor_sync(0xffffffffu, s, off);
    if (lane == 0) red[warp] = s;
    __syncthreads();
    if (c == 0) {
        float tot = 0.0f;
        for (int i = 0; i < 8; i++) tot += red[i];
        smean = tot * (1.0f / EMBD);
    }
    __syncthreads();
    float d = val - smean;
    float s2 = d * d;
#pragma unroll
    for (int off = 16; off; off >>= 1) s2 += __shfl_xor_sync(0xffffffffu, s2, off);
    if (lane == 0) red[warp] = s2;
    __syncthreads();
    if (c == 0) {
        float tot = 0.0f;
        for (int i = 0; i < 8; i++) tot += red[i];
        srstd = rsqrtf(tot * (1.0f / EMBD) + 1e-5f);
    }
    __syncthreads();
    float out = d * srstd * gamma[c] + beta[c];
    h[row * EMBD + c] = out;
    hh[row * EMBD + c] = __float2half(out);
}

// ---------------- host orchestration ----------------------------------------
static const int ATTN_SMEM = (2 * LMAXC * DHD + 32) * (int)sizeof(float);

static void run_hgemm(const __half* A, const __half* Bt, const float* bias, void* C,
                      int M, int N, int K, int lda, int ldc, int relu, int outh) {
    dim3 grid(N / 128, M / 128);
    hgemm<<<grid, 256, HSMEM>>>(A, Bt, bias, C, M, N, K, lda, ldc, relu, outh);
}

extern "C" void kernel_launch(void* const* d_in, const int* in_sizes, int n_in,
                              void* d_out, int out_size) {
    const float* x       = (const float*)d_in[0];
    const int*   ei      = (const int*)d_in[1];
    const int*   batches = (const int*)d_in[2];

    int wi = 3;
    if (n_in >= 29 && in_sizes[3] == 1) wi = 4;  // skip scalar L_max if present

    const float* sW0  = (const float*)d_in[wi++];
    const float* sWn0 = (const float*)d_in[wi++];
    const float* sb0  = (const float*)d_in[wi++];
    const float* sW1  = (const float*)d_in[wi++];
    const float* sWn1 = (const float*)d_in[wi++];
    const float* sb1  = (const float*)d_in[wi++];
    const float* sW2  = (const float*)d_in[wi++];
    const float* sWn2 = (const float*)d_in[wi++];
    const float* sb2  = (const float*)d_in[wi++];
    const float* Wq   = (const float*)d_in[wi++];
    const float* Wk   = (const float*)d_in[wi++];
    const float* Wv   = (const float*)d_in[wi++];
    const float* bq   = (const float*)d_in[wi++];
    const float* bk   = (const float*)d_in[wi++];
    const float* bv   = (const float*)d_in[wi++];
    const float* Wo   = (const float*)d_in[wi++];
    const float* bo   = (const float*)d_in[wi++];
    const float* ln1g = (const float*)d_in[wi++];
    const float* ln1b = (const float*)d_in[wi++];
    const float* ln2g = (const float*)d_in[wi++];
    const float* ln2b = (const float*)d_in[wi++];
    const float* W1   = (const float*)d_in[wi++];
    const float* b1   = (const float*)d_in[wi++];
    const float* W2   = (const float*)d_in[wi++];
    const float* b2   = (const float*)d_in[wi++];

    int *rowptr, *cnt, *csrc;
    float *comb0, *wsg0, *ha, *hp, *qkv, *tmp, *bqkv;
    __half *comb1h, *comb2h, *hph, *oh, *midh;
    __half *wsg1t, *wsg2t, *wqkvt, *wot, *w1t, *w2t;
    cudaGetSymbolAddress((void**)&rowptr, g_rowptr);
    cudaGetSymbolAddress((void**)&cnt,    g_cnt);
    cudaGetSymbolAddress((void**)&csrc,   g_csrc);
    cudaGetSymbolAddress((void**)&comb0,  g_comb0);
    cudaGetSymbolAddress((void**)&wsg0,   g_wsg0);
    cudaGetSymbolAddress((void**)&comb1h, g_comb1h);
    cudaGetSymbolAddress((void**)&comb2h, g_comb2h);
    cudaGetSymbolAddress((void**)&ha,     g_ha);
    cudaGetSymbolAddress((void**)&hp,     g_hp);
    cudaGetSymbolAddress((void**)&hph,    g_hph);
    cudaGetSymbolAddress((void**)&qkv,    g_qkv);
    cudaGetSymbolAddress((void**)&oh,     g_oh);
    cudaGetSymbolAddress((void**)&tmp,    g_tmp);
    cudaGetSymbolAddress((void**)&midh,   g_midh);
    cudaGetSymbolAddress((void**)&wsg1t,  g_wsg1t);
    cudaGetSymbolAddress((void**)&wsg2t,  g_wsg2t);
    cudaGetSymbolAddress((void**)&wqkvt,  g_wqkvt);
    cudaGetSymbolAddress((void**)&wot,    g_wot);
    cudaGetSymbolAddress((void**)&w1t,    g_w1t);
    cudaGetSymbolAddress((void**)&w2t,    g_w2t);
    cudaGetSymbolAddress((void**)&bqkv,   g_bqkv);

    cudaFuncSetAttribute(attn_kernel, cudaFuncAttributeMaxDynamicSharedMemorySize, ATTN_SMEM);
    cudaFuncSetAttribute(hgemm, cudaFuncAttributeMaxDynamicSharedMemorySize, HSMEM);

    dim3 t328(32, 8);
    // ---- weight packing: transpose to half [N][K] ----
    pack0_kernel<<<32, 256>>>(sW0, sWn0, wsg0);
    transpose_h<<<dim3(8, 8, 1), t328>>>(sW1,  wsg1t,       256, 0, 0, 512);
    transpose_h<<<dim3(8, 8, 1), t328>>>(sWn1, wsg1t + 256, 256, 0, 0, 512);
    transpose_h<<<dim3(8, 8, 1), t328>>>(sW2,  wsg2t,       256, 0, 0, 512);
    transpose_h<<<dim3(8, 8, 1), t328>>>(sWn2, wsg2t + 256, 256, 0, 0, 512);
    transpose_h<<<dim3(8, 8, 4), t328>>>(Wq, wqkvt,               256, 65536, 196608, 256);
    transpose_h<<<dim3(8, 8, 4), t328>>>(Wk, wqkvt + 256 * 256,   256, 65536, 196608, 256);
    transpose_h<<<dim3(8, 8, 4), t328>>>(Wv, wqkvt + 2 * 256 * 256, 256, 65536, 196608, 256);
    transpose_h<<<dim3(8, 8, 4), t328>>>(Wo, wot, 256, 65536, 65536, 256);
    transpose_h<<<dim3(32, 8, 4), t328>>>(W1, w1t, 1024, 262144, 262144, 256);
    transpose_h<<<dim3(8, 32, 4), t328>>>(W2, w2t, 256, 262144, 262144, 1024);
    pack_bqkv<<<dim3(3, 4), 256>>>(bq, bk, bv, bqkv);

    // ---- CSR build ----
    cudaMemsetAsync(cnt, 0, NN * sizeof(int), 0);
    degi_kernel<<<(NE + 255) / 256, 256>>>(ei, cnt);
    scan_kernel<<<1, 1024>>>(cnt, rowptr);
    fill_kernel<<<(NE + 255) / 256, 256>>>(ei, cnt, csrc);

    // ---- SAGE layer 0: [x | agg(x)] @ [sW0;sWn0] -> comb1h cols[0:256) ----
    agg0_kernel<<<NN / 8, 256>>>(x, comb0);
    gemm32h_kernel<<<dim3(256 / BN, NN / BM), 256>>>(comb0, wsg0, sb0, comb1h, 512);

    // ---- SAGE layer 1 ----
    agg_csr_h<<<NN, 128>>>(comb1h);
    run_hgemm(comb1h, wsg1t, sb1, comb2h, NN, 256, 512, 512, 512, 1, 1);

    // ---- SAGE layer 2 ----
    agg_csr_h<<<NN, 128>>>(comb2h);
    run_hgemm(comb2h, wsg2t, sb2, ha, NN, 256, 512, 512, 256, 0, 0);

    // ---- pack & pad ----
    pack_kernel<<<dim3(LMAXC, NG), EMBD>>>(ha, batches, hp, hph);

    // ---- 4 transformer layers ----
    for (int l = 0; l < 4; l++) {
        run_hgemm(hph, wqkvt + (long)l * 196608, bqkv + l * 768, qkv,
                  NTOK, 768, 256, 256, 768, 0, 0);

        attn_kernel<<<dim3(NG, NHD), LMAXC, ATTN_SMEM>>>(qkv, batches, oh);

        run_hgemm(oh, wot + (long)l * 65536, bo + l * 256, tmp,
                  NTOK, 256, 256, 256, 256, 0, 0);
        add_ln_kernel<<<NTOK, EMBD>>>(hp, hph, tmp, ln1g + l * EMBD, ln1b + l * EMBD);

        run_hgemm(hph, w1t + (long)l * 262144, b1 + l * FFND, midh,
                  NTOK, 1024, 256, 256, 1024, 1, 1);
        run_hgemm(midh, w2t + (long)l * 262144, b2 + l * EMBD, tmp,
                  NTOK, 256, 1024, 1024, 256, 0, 0);
        add_ln_kernel<<<NTOK, EMBD>>>(hp, hph, tmp, ln2g + l * EMBD, ln2b + l * EMBD);
    }

    cudaMemcpyAsync(d_out, hp, (size_t)NTOK * EMBD * sizeof(float),
                    cudaMemcpyDeviceToDevice, 0);
}

// round 5
// speedup vs baseline: 5.3627x; 1.6692x over previous
#include <cuda_runtime.h>
#include <cuda_fp16.h>
#include <math.h>
#include <stdint.h>

#define NN   16384
#define NE   262144
#define NG   64
#define LMAXC 320
#define EMBD 256
#define FFND 1024
#define NHD  8
#define DHD  32
#define NTOK (LMAXC*NG)

// ---------------- scratch (device globals; no allocation allowed) ----------
__device__ int   g_rowptr[NN + 1];
__device__ int   g_cnt[NN];
__device__ int   g_csrc[NE];
__device__ float g_comb0[NN*32];
__device__ float g_wsg0[32*256];
__device__ __align__(256) __half g_comb1h[NN*512];
__device__ __align__(256) __half g_comb2h[NN*512];
__device__ float g_ha [NN*EMBD];
__device__ float g_hp [NTOK*EMBD];
__device__ __align__(256) __half g_hph[NTOK*EMBD];
__device__ __align__(256) __half g_qkvh[NTOK*768];
__device__ __align__(256) __half g_oh[NTOK*EMBD];
__device__ float g_tmp[NTOK*EMBD];
__device__ __align__(256) __half g_midh[NTOK*FFND];
__device__ __align__(256) __half g_wsg1t[256*512];
__device__ __align__(256) __half g_wsg2t[256*512];
__device__ __align__(256) __half g_wqkvt[4*768*256];
__device__ __align__(256) __half g_wot[4*256*256];
__device__ __align__(256) __half g_w1t[4*1024*256];
__device__ __align__(256) __half g_w2t[4*256*1024];
__device__ float g_bqkv[4*768];

// =================== CSR build =============================================
__global__ void degi_kernel(const int* __restrict__ ei, int* __restrict__ cnt) {
    int e = blockIdx.x * blockDim.x + threadIdx.x;
    if (e < NE) atomicAdd(&cnt[ei[NE + e]], 1);
}

__global__ void scan_kernel(int* __restrict__ cnt, int* __restrict__ rowptr) {
    __shared__ int wsum[32];
    int t = threadIdx.x;
    int base = t * 16;
    int loc[16];
    int s = 0;
#pragma unroll
    for (int i = 0; i < 16; i++) { loc[i] = s; s += cnt[base + i]; }
    int lane = t & 31, w = t >> 5;
    int inc = s;
#pragma unroll
    for (int off = 1; off < 32; off <<= 1) {
        int v = __shfl_up_sync(0xffffffffu, inc, off);
        if (lane >= off) inc += v;
    }
    if (lane == 31) wsum[w] = inc;
    __syncthreads();
    if (w == 0) {
        int v = wsum[lane];
#pragma unroll
        for (int off = 1; off < 32; off <<= 1) {
            int u = __shfl_up_sync(0xffffffffu, v, off);
            if (lane >= off) v += u;
        }
        wsum[lane] = v;
    }
    __syncthreads();
    int pre = inc - s + (w > 0 ? wsum[w - 1] : 0);
#pragma unroll
    for (int i = 0; i < 16; i++) { rowptr[base + i] = pre + loc[i]; cnt[base + i] = 0; }
    if (t == 1023) rowptr[NN] = pre + s;
}

__global__ void fill_kernel(const int* __restrict__ ei, int* __restrict__ cnt,
                            int* __restrict__ csrc) {
    int e = blockIdx.x * blockDim.x + threadIdx.x;
    if (e >= NE) return;
    int d = ei[NE + e];
    int pos = atomicAdd(&cnt[d], 1);
    csrc[g_rowptr[d] + pos] = ei[e];
}

// =================== SAGE layer-0 input assembly ===========================
__global__ void agg0_kernel(const float* __restrict__ x, float* __restrict__ comb0) {
    int w = threadIdx.x >> 5;
    int lane = threadIdx.x & 31;
    int node = blockIdx.x * 8 + w;
    if (lane >= 16) return;
    int s0 = g_rowptr[node], s1 = g_rowptr[node + 1];
    float sum = 0.f;
    for (int j = s0; j < s1; j++) sum += x[g_csrc[j] * 16 + lane];
    comb0[node * 32 + lane] = x[node * 16 + lane];
    comb0[node * 32 + 16 + lane] = sum / fmaxf((float)(s1 - s0), 1.f);
}

// mean agg over half features: feat [NN x 512], cols 0-255 in -> cols 256-511 out
__global__ void agg_csr_h(__half* __restrict__ feat) {
    int node = blockIdx.x;
    int c = threadIdx.x;
    const __half2* f2 = (const __half2*)feat;
    int s0 = g_rowptr[node], s1 = g_rowptr[node + 1];
    float sx = 0.f, sy = 0.f;
    int j = s0;
    for (; j + 2 <= s1; j += 2) {
        int n0 = g_csrc[j], n1 = g_csrc[j + 1];
        float2 a = __half22float2(f2[(long)n0 * 256 + c]);
        float2 b = __half22float2(f2[(long)n1 * 256 + c]);
        sx += a.x + b.x; sy += a.y + b.y;
    }
    for (; j < s1; j++) {
        float2 a = __half22float2(f2[(long)g_csrc[j] * 256 + c]);
        sx += a.x; sy += a.y;
    }
    float inv = 1.f / fmaxf((float)(s1 - s0), 1.f);
    ((__half2*)feat)[(long)node * 256 + 128 + c] = __floats2half2_rn(sx * inv, sy * inv);
}

// =================== weight packing ========================================
__global__ void pack0_kernel(const float* __restrict__ Ws, const float* __restrict__ Wn,
                             float* __restrict__ out) {
    int k = blockIdx.x;
    int n = threadIdx.x;
    out[k * 256 + n] = (k < 16) ? Ws[k * 256 + n] : Wn[(k - 16) * 256 + n];
}

__global__ void pack_bqkv(const float* __restrict__ bq, const float* __restrict__ bk,
                          const float* __restrict__ bv, float* __restrict__ b) {
    int c = threadIdx.x, s = blockIdx.x, l = blockIdx.y;
    const float* src = (s == 0) ? bq : ((s == 1) ? bk : bv);
    b[l * 768 + s * 256 + c] = src[l * 256 + c];
}

__global__ void transpose_h(const float* __restrict__ src, __half* __restrict__ dst,
                            int N, long src_lstride, long dst_lstride, int ldd) {
    __shared__ float t[32][33];
    const float* s = src + blockIdx.z * src_lstride;
    __half* d = dst + blockIdx.z * dst_lstride;
    int k0 = blockIdx.y * 32, n0 = blockIdx.x * 32;
    int tx = threadIdx.x, ty = threadIdx.y;
#pragma unroll
    for (int i = 0; i < 32; i += 8)
        t[ty + i][tx] = s[(long)(k0 + ty + i) * N + n0 + tx];
    __syncthreads();
#pragma unroll
    for (int i = 0; i < 32; i += 8)
        d[(long)(n0 + ty + i) * ldd + k0 + tx] = __float2half(t[tx][ty + i]);
}

// ================= fp32 GEMM K=32 for SAGE layer 0, half output =============
#define BM 64
#define BN 64
__global__ void gemm32h_kernel(const float* __restrict__ A, const float* __restrict__ B,
                               const float* __restrict__ bias, __half* __restrict__ C,
                               int ldc) {
    __shared__ float As[16][BM + 1];
    __shared__ float Bs[16][BN];
    int bm = blockIdx.y * BM;
    int bn = blockIdx.x * BN;
    int tid = threadIdx.x;
    int tx = tid & 15;
    int ty = tid >> 4;
    float r[4][4];
#pragma unroll
    for (int i = 0; i < 4; i++)
#pragma unroll
        for (int j = 0; j < 4; j++) r[i][j] = 0.0f;

    for (int k0 = 0; k0 < 32; k0 += 16) {
#pragma unroll
        for (int i = 0; i < 4; i++) {
            int idx = tid + i * 256;
            int rr = idx >> 4, cc = idx & 15;
            As[cc][rr] = A[(long)(bm + rr) * 32 + k0 + cc];
        }
#pragma unroll
        for (int i = 0; i < 4; i++) {
            int idx = tid + i * 256;
            int rr = idx >> 6, cc = idx & 63;
            Bs[rr][cc] = B[(long)(k0 + rr) * 256 + bn + cc];
        }
        __syncthreads();
#pragma unroll
        for (int kk = 0; kk < 16; kk++) {
            float a[4], b[4];
#pragma unroll
            for (int i = 0; i < 4; i++) a[i] = As[kk][ty * 4 + i];
#pragma unroll
            for (int j = 0; j < 4; j++) b[j] = Bs[kk][tx * 4 + j];
#pragma unroll
            for (int i = 0; i < 4; i++)
#pragma unroll
                for (int j = 0; j < 4; j++) r[i][j] = fmaf(a[i], b[j], r[i][j]);
        }
        __syncthreads();
    }
#pragma unroll
    for (int i = 0; i < 4; i++) {
        long row = bm + ty * 4 + i;
        __half2* C2 = (__half2*)(C + row * ldc + bn + tx * 4);
#pragma unroll
        for (int j = 0; j < 4; j += 2) {
            int col = bn + tx * 4 + j;
            float v0 = fmaxf(r[i][j] + bias[col], 0.f);
            float v1 = fmaxf(r[i][j + 1] + bias[col + 1], 0.f);
            C2[j >> 1] = __floats2half2_rn(v0, v1);
        }
    }
}

// ================= FP16 tensor-core GEMM (ldmatrix + m16n8k16) ==============
#define HSTR 72
#define HBUF (128*HSTR)
#define HSMEM (4*HBUF*2)

#define CPA16(dst, src) asm volatile("cp.async.cg.shared.global [%0], [%1], 16;" :: "r"(dst), "l"(src))

__device__ __forceinline__ void ldsm4(uint32_t (&r)[4], uint32_t addr) {
    asm volatile("ldmatrix.sync.aligned.m8n8.x4.shared.b16 {%0,%1,%2,%3}, [%4];"
                 : "=r"(r[0]), "=r"(r[1]), "=r"(r[2]), "=r"(r[3]) : "r"(addr));
}
__device__ __forceinline__ void ldsm2(uint32_t (&r)[2], uint32_t addr) {
    asm volatile("ldmatrix.sync.aligned.m8n8.x2.shared.b16 {%0,%1}, [%2];"
                 : "=r"(r[0]), "=r"(r[1]) : "r"(addr));
}
__device__ __forceinline__ void ldsm4t(uint32_t (&r)[4], uint32_t addr) {
    asm volatile("ldmatrix.sync.aligned.m8n8.x4.trans.shared.b16 {%0,%1,%2,%3}, [%4];"
                 : "=r"(r[0]), "=r"(r[1]), "=r"(r[2]), "=r"(r[3]) : "r"(addr));
}

#define HMMA(d, a, b0, b1) asm volatile( \
    "mma.sync.aligned.m16n8k16.row.col.f32.f16.f16.f32 " \
    "{%0,%1,%2,%3}, {%4,%5,%6,%7}, {%8,%9}, {%0,%1,%2,%3};" \
    : "+f"(d[0]), "+f"(d[1]), "+f"(d[2]), "+f"(d[3]) \
    : "r"(a[0]), "r"(a[1]), "r"(a[2]), "r"(a[3]), "r"(b0), "r"(b1))

__device__ __forceinline__ uint32_t packh2(float a, float b) {
    __half2 h = __floats2half2_rn(a, b);
    return *(uint32_t*)&h;
}

__global__ void __launch_bounds__(256, 2)
hgemm(const __half* __restrict__ A, const __half* __restrict__ Bt,
      const float* __restrict__ bias, void* __restrict__ Cv,
      int M, int N, int K, int lda, int ldc, int relu, int outh) {
    extern __shared__ __half shh[];
    const int tid  = threadIdx.x;
    const int lane = tid & 31;
    const int wid  = tid >> 5;
    const int wr   = wid >> 2;
    const int wc   = wid & 3;
    const int bm   = blockIdx.y * 128;
    const int bn   = blockIdx.x * 128;

    uint32_t sbase = (uint32_t)__cvta_generic_to_shared(shh);

    float acc[4][4][4];
#pragma unroll
    for (int mt = 0; mt < 4; mt++)
#pragma unroll
        for (int nt = 0; nt < 4; nt++)
#pragma unroll
            for (int r = 0; r < 4; r++) acc[mt][nt][r] = 0.0f;

#define HLOAD(buf, k0)                                                          \
    do {                                                                        \
        _Pragma("unroll")                                                       \
        for (int i = 0; i < 4; i++) {                                           \
            int idx = tid + i * 256;                                            \
            int r = idx >> 3, c = (idx & 7) << 3;                               \
            CPA16(sbase + (uint32_t)((buf) * HBUF + r * HSTR + c) * 2u,         \
                  A + (long)(bm + r) * lda + (k0) + c);                         \
        }                                                                       \
        _Pragma("unroll")                                                       \
        for (int i = 0; i < 4; i++) {                                           \
            int idx = tid + i * 256;                                            \
            int r = idx >> 3, c = (idx & 7) << 3;                               \
            CPA16(sbase + (uint32_t)((2 + (buf)) * HBUF + r * HSTR + c) * 2u,   \
                  Bt + (long)(bn + r) * K + (k0) + c);                          \
        }                                                                       \
        asm volatile("cp.async.commit_group;");                                 \
    } while (0)

    const int nk = K >> 6;
    HLOAD(0, 0);

    const int arow = wr * 64 + (lane & 15);
    const int ach  = (lane >> 4) << 3;
    const int brow = wc * 32 + (lane & 7);
    const int bch  = ((lane >> 3) & 1) << 3;

    for (int it = 0; it < nk; it++) {
        int cur = it & 1;
        if (it + 1 < nk) {
            HLOAD(cur ^ 1, (it + 1) << 6);
            asm volatile("cp.async.wait_group 1;");
        } else {
            asm volatile("cp.async.wait_group 0;");
        }
        __syncthreads();

        uint32_t aB = sbase + (uint32_t)(cur * HBUF) * 2u;
        uint32_t bB = sbase + (uint32_t)((2 + cur) * HBUF) * 2u;

#pragma unroll
        for (int ks = 0; ks < 4; ks++) {
            uint32_t af[4][4], bf[4][2];
#pragma unroll
            for (int mt = 0; mt < 4; mt++)
                ldsm4(af[mt], aB + (uint32_t)((arow + mt * 16) * HSTR + ks * 16 + ach) * 2u);
#pragma unroll
            for (int nt = 0; nt < 4; nt++)
                ldsm2(bf[nt], bB + (uint32_t)((brow + nt * 8) * HSTR + ks * 16 + bch) * 2u);
#pragma unroll
            for (int mt = 0; mt < 4; mt++)
#pragma unroll
                for (int nt = 0; nt < 4; nt++)
                    HMMA(acc[mt][nt], af[mt], bf[nt][0], bf[nt][1]);
        }
        __syncthreads();
    }

#pragma unroll
    for (int mt = 0; mt < 4; mt++) {
        int row = bm + wr * 64 + mt * 16 + (lane >> 2);
#pragma unroll
        for (int nt = 0; nt < 4; nt++) {
            int col = bn + wc * 32 + nt * 8 + ((lane & 3) << 1);
            float b0 = bias[col], b1 = bias[col + 1];
            float v0 = acc[mt][nt][0] + b0, v1 = acc[mt][nt][1] + b1;
            float v2 = acc[mt][nt][2] + b0, v3 = acc[mt][nt][3] + b1;
            if (relu) { v0 = fmaxf(v0, 0.f); v1 = fmaxf(v1, 0.f);
                        v2 = fmaxf(v2, 0.f); v3 = fmaxf(v3, 0.f); }
            if (outh) {
                __half2* C2 = (__half2*)Cv;
                C2[((long)row * ldc + col) >> 1]       = __floats2half2_rn(v0, v1);
                C2[((long)(row + 8) * ldc + col) >> 1] = __floats2half2_rn(v2, v3);
            } else {
                float* C = (float*)Cv;
                long i0 = (long)row * ldc + col;
                long i1 = i0 + 8L * ldc;
                C[i0] = v0; C[i0 + 1] = v1; C[i1] = v2; C[i1 + 1] = v3;
            }
        }
    }
#undef HLOAD
}

// ---------------- pack nodes into [LMAX, NG, EMB] (zero padding) ------------
__global__ void pack_kernel(const float* __restrict__ z, const int* __restrict__ batches,
                            float* __restrict__ hp, __half* __restrict__ hph) {
    int l = blockIdx.x;
    int g = blockIdx.y;
    int st = batches[g];
    int len = batches[g + 1] - st;
    long o = ((long)l * NG + g) * EMBD + threadIdx.x;
    float v = (l < len) ? z[(long)(st + l) * EMBD + threadIdx.x] : 0.0f;
    hp[o] = v;
    hph[o] = __float2half(v);
}

// ============ tensor-core flash attention: one block per (graph, head) ======
// Q,K,V half [320 x 32] staged in smem (row stride 40 halves -> conflict-free
// ldmatrix). 4 warps x 5 m-tiles of 16 q-rows; online softmax over 64-key chunks.
#define ATT_SMEM (3*320*40*2)

__global__ void __launch_bounds__(128, 2)
attn_mma(const __half* __restrict__ qkv, const int* __restrict__ batches,
         __half* __restrict__ oh) {
    int g = blockIdx.x, h = blockIdx.y;
    int len = batches[g + 1] - batches[g];
    extern __shared__ __half smh[];
    uint32_t sb = (uint32_t)__cvta_generic_to_shared(smh);
    const uint32_t koff = 320 * 40 * 2u;
    const uint32_t voff = 2u * 320 * 40 * 2u;

    int tid = threadIdx.x;
    // stage Q,K,V: 3840 x 16B
    for (int idx = tid; idx < 3840; idx += 128) {
        int mat = idx / 1280;
        int rem = idx - mat * 1280;
        int l = rem >> 2, c = rem & 3;
        const __half* src = qkv + ((long)l * NG + g) * 768 + mat * 256 + h * 32 + c * 8;
        uint32_t dst = sb + (uint32_t)(mat * 320 * 40 + l * 40 + c * 8) * 2u;
        CPA16(dst, src);
    }
    asm volatile("cp.async.commit_group;");
    asm volatile("cp.async.wait_group 0;");
    __syncthreads();

    const int w = tid >> 5, lane = tid & 31;
    const int r = lane >> 2, t = lane & 3;
    const int nch = (len + 63) >> 6;
    const float scale = 0.17677669529663687f;

    for (int mt = 0; mt < 5; mt++) {
        int m0 = w * 80 + mt * 16;
        uint32_t qf[2][4];
        {
            uint32_t qrow = (uint32_t)((m0 + (lane & 15)) * 40 + ((lane >> 4) << 3));
            ldsm4(qf[0], sb + qrow * 2u);
            ldsm4(qf[1], sb + (qrow + 16u) * 2u);
        }
        float o_[4][4];
#pragma unroll
        for (int nt = 0; nt < 4; nt++)
#pragma unroll
            for (int j = 0; j < 4; j++) o_[nt][j] = 0.f;
        float mx0 = -3e38f, mx1 = -3e38f, sm0 = 0.f, sm1 = 0.f;

        for (int ch = 0; ch < nch; ch++) {
            int base = ch << 6;
            float s[8][4];
#pragma unroll
            for (int nt = 0; nt < 8; nt++)
#pragma unroll
                for (int j = 0; j < 4; j++) s[nt][j] = 0.f;

#pragma unroll
            for (int ks = 0; ks < 2; ks++) {
#pragma unroll
                for (int np = 0; np < 4; np++) {
                    uint32_t kf[4];
                    int krow = base + np * 16 + (lane & 7) + ((lane >> 4) << 3);
                    int kcol = ks * 16 + (lane & 8);
                    ldsm4(kf, sb + koff + (uint32_t)(krow * 40 + kcol) * 2u);
                    HMMA(s[2 * np],     qf[ks], kf[0], kf[1]);
                    HMMA(s[2 * np + 1], qf[ks], kf[2], kf[3]);
                }
            }

            if (base + 64 > len) {
#pragma unroll
                for (int nt = 0; nt < 8; nt++) {
                    int c0 = base + nt * 8 + 2 * t;
                    if (c0 >= len)     { s[nt][0] = -3e38f; s[nt][2] = -3e38f; }
                    if (c0 + 1 >= len) { s[nt][1] = -3e38f; s[nt][3] = -3e38f; }
                }
            }

            // chunk row max
            float cm0 = -3e38f, cm1 = -3e38f;
#pragma unroll
            for (int nt = 0; nt < 8; nt++) {
                cm0 = fmaxf(cm0, fmaxf(s[nt][0], s[nt][1]));
                cm1 = fmaxf(cm1, fmaxf(s[nt][2], s[nt][3]));
            }
            cm0 = fmaxf(cm0, __shfl_xor_sync(0xffffffffu, cm0, 1));
            cm0 = fmaxf(cm0, __shfl_xor_sync(0xffffffffu, cm0, 2));
            cm1 = fmaxf(cm1, __shfl_xor_sync(0xffffffffu, cm1, 1));
            cm1 = fmaxf(cm1, __shfl_xor_sync(0xffffffffu, cm1, 2));
            float nm0 = fmaxf(mx0, cm0), nm1 = fmaxf(mx1, cm1);
            float corr0 = __expf((mx0 - nm0) * scale);
            float corr1 = __expf((mx1 - nm1) * scale);
            mx0 = nm0; mx1 = nm1;

            // p = exp((s-max)*scale), pack P fragments, partial sums
            uint32_t pf[4][4];
            float ps0 = 0.f, ps1 = 0.f;
#pragma unroll
            for (int kf = 0; kf < 4; kf++) {
                float p00 = __expf((s[2 * kf][0] - nm0) * scale);
                float p01 = __expf((s[2 * kf][1] - nm0) * scale);
                float p02 = __expf((s[2 * kf][2] - nm1) * scale);
                float p03 = __expf((s[2 * kf][3] - nm1) * scale);
                float p10 = __expf((s[2 * kf + 1][0] - nm0) * scale);
                float p11 = __expf((s[2 * kf + 1][1] - nm0) * scale);
                float p12 = __expf((s[2 * kf + 1][2] - nm1) * scale);
                float p13 = __expf((s[2 * kf + 1][3] - nm1) * scale);
                ps0 += (p00 + p01) + (p10 + p11);
                ps1 += (p02 + p03) + (p12 + p13);
                pf[kf][0] = packh2(p00, p01);
                pf[kf][1] = packh2(p02, p03);
                pf[kf][2] = packh2(p10, p11);
                pf[kf][3] = packh2(p12, p13);
            }
            sm0 = sm0 * corr0 + ps0;
            sm1 = sm1 * corr1 + ps1;
#pragma unroll
            for (int nt = 0; nt < 4; nt++) {
                o_[nt][0] *= corr0; o_[nt][1] *= corr0;
                o_[nt][2] *= corr1; o_[nt][3] *= corr1;
            }

            // O += P @ V
#pragma unroll
            for (int kf = 0; kf < 4; kf++) {
                int k0 = base + kf * 16;
                uint32_t vrow = (uint32_t)((k0 + (lane & 15)) * 40 + ((lane >> 4) << 3));
                uint32_t vf[4];
                ldsm4t(vf, sb + voff + vrow * 2u);
                HMMA(o_[0], pf[kf], vf[0], vf[1]);
                HMMA(o_[1], pf[kf], vf[2], vf[3]);
                ldsm4t(vf, sb + voff + (vrow + 16u) * 2u);
                HMMA(o_[2], pf[kf], vf[0], vf[1]);
                HMMA(o_[3], pf[kf], vf[2], vf[3]);
            }
        }

        // finalize: row sums across quad, normalize, store half
        float rs0 = sm0 + __shfl_xor_sync(0xffffffffu, sm0, 1);
        rs0 += __shfl_xor_sync(0xffffffffu, rs0, 2);
        float rs1 = sm1 + __shfl_xor_sync(0xffffffffu, sm1, 1);
        rs1 += __shfl_xor_sync(0xffffffffu, rs1, 2);
        float inv0 = 1.f / rs0, inv1 = 1.f / rs1;
        long r0base = ((long)(m0 + r) * NG + g) * 256 + h * 32 + 2 * t;
        long r1base = ((long)(m0 + r + 8) * NG + g) * 256 + h * 32 + 2 * t;
#pragma unroll
        for (int nt = 0; nt < 4; nt++) {
            *(__half2*)(oh + r0base + nt * 8) = __floats2half2_rn(o_[nt][0] * inv0, o_[nt][1] * inv0);
            *(__half2*)(oh + r1base + nt * 8) = __floats2half2_rn(o_[nt][2] * inv1, o_[nt][3] * inv1);
        }
    }
}

// ---------------- residual add + LayerNorm (row = 256), dual output ---------
__global__ void add_ln_kernel(float* __restrict__ h, __half* __restrict__ hh,
                              const float* __restrict__ t,
                              const float* __restrict__ gamma, const float* __restrict__ beta) {
    long row = blockIdx.x;
    int c = threadIdx.x;
    float val = h[row * EMBD + c] + t[row * EMBD + c];

    __shared__ float red[8];
    __shared__ float smean, srstd;
    int lane = c & 31, warp = c >> 5;

    float s = val;
#pragma unroll
    for (int off = 16; off; off >>= 1) s += __shfl_xor_sync(0xffffffffu, s, off);
    if (lane == 0) red[warp] = s;
    __syncthreads();
    if (c == 0) {
        float tot = 0.0f;
        for (int i = 0; i < 8; i++) tot += red[i];
        smean = tot * (1.0f / EMBD);
    }
    __syncthreads();
    float d = val - smean;
    float s2 = d * d;
#pragma unroll
    for (int off = 16; off; off >>= 1) s2 += __shfl_xor_sync(0xffffffffu, s2, off);
    if (lane == 0) red[warp] = s2;
    __syncthreads();
    if (c == 0) {
        float tot = 0.0f;
        for (int i = 0; i < 8; i++) tot += red[i];
        srstd = rsqrtf(tot * (1.0f / EMBD) + 1e-5f);
    }
    __syncthreads();
    float out = d * srstd * gamma[c] + beta[c];
    h[row * EMBD + c] = out;
    hh[row * EMBD + c] = __float2half(out);
}

// ---------------- host orchestration ----------------------------------------
static void run_hgemm(const __half* A, const __half* Bt, const float* bias, void* C,
                      int M, int N, int K, int lda, int ldc, int relu, int outh) {
    dim3 grid(N / 128, M / 128);
    hgemm<<<grid, 256, HSMEM>>>(A, Bt, bias, C, M, N, K, lda, ldc, relu, outh);
}

extern "C" void kernel_launch(void* const* d_in, const int* in_sizes, int n_in,
                              void* d_out, int out_size) {
    const float* x       = (const float*)d_in[0];
    const int*   ei      = (const int*)d_in[1];
    const int*   batches = (const int*)d_in[2];

    int wi = 3;
    if (n_in >= 29 && in_sizes[3] == 1) wi = 4;

    const float* sW0  = (const float*)d_in[wi++];
    const float* sWn0 = (const float*)d_in[wi++];
    const float* sb0  = (const float*)d_in[wi++];
    const float* sW1  = (const float*)d_in[wi++];
    const float* sWn1 = (const float*)d_in[wi++];
    const float* sb1  = (const float*)d_in[wi++];
    const float* sW2  = (const float*)d_in[wi++];
    const float* sWn2 = (const float*)d_in[wi++];
    const float* sb2  = (const float*)d_in[wi++];
    const float* Wq   = (const float*)d_in[wi++];
    const float* Wk   = (const float*)d_in[wi++];
    const float* Wv   = (const float*)d_in[wi++];
    const float* bq   = (const float*)d_in[wi++];
    const float* bk   = (const float*)d_in[wi++];
    const float* bv   = (const float*)d_in[wi++];
    const float* Wo   = (const float*)d_in[wi++];
    const float* bo   = (const float*)d_in[wi++];
    const float* ln1g = (const float*)d_in[wi++];
    const float* ln1b = (const float*)d_in[wi++];
    const float* ln2g = (const float*)d_in[wi++];
    const float* ln2b = (const float*)d_in[wi++];
    const float* W1   = (const float*)d_in[wi++];
    const float* b1   = (const float*)d_in[wi++];
    const float* W2   = (const float*)d_in[wi++];
    const float* b2   = (const float*)d_in[wi++];

    int *rowptr, *cnt, *csrc;
    float *comb0, *wsg0, *ha, *hp, *tmp, *bqkv;
    __half *comb1h, *comb2h, *hph, *qkvh, *oh, *midh;
    __half *wsg1t, *wsg2t, *wqkvt, *wot, *w1t, *w2t;
    cudaGetSymbolAddress((void**)&rowptr, g_rowptr);
    cudaGetSymbolAddress((void**)&cnt,    g_cnt);
    cudaGetSymbolAddress((void**)&csrc,   g_csrc);
    cudaGetSymbolAddress((void**)&comb0,  g_comb0);
    cudaGetSymbolAddress((void**)&wsg0,   g_wsg0);
    cudaGetSymbolAddress((void**)&comb1h, g_comb1h);
    cudaGetSymbolAddress((void**)&comb2h, g_comb2h);
    cudaGetSymbolAddress((void**)&ha,     g_ha);
    cudaGetSymbolAddress((void**)&hp,     g_hp);
    cudaGetSymbolAddress((void**)&hph,    g_hph);
    cudaGetSymbolAddress((void**)&qkvh,   g_qkvh);
    cudaGetSymbolAddress((void**)&oh,     g_oh);
    cudaGetSymbolAddress((void**)&tmp,    g_tmp);
    cudaGetSymbolAddress((void**)&midh,   g_midh);
    cudaGetSymbolAddress((void**)&wsg1t,  g_wsg1t);
    cudaGetSymbolAddress((void**)&wsg2t,  g_wsg2t);
    cudaGetSymbolAddress((void**)&wqkvt,  g_wqkvt);
    cudaGetSymbolAddress((void**)&wot,    g_wot);
    cudaGetSymbolAddress((void**)&w1t,    g_w1t);
    cudaGetSymbolAddress((void**)&w2t,    g_w2t);
    cudaGetSymbolAddress((void**)&bqkv,   g_bqkv);

    cudaFuncSetAttribute(attn_mma, cudaFuncAttributeMaxDynamicSharedMemorySize, ATT_SMEM);
    cudaFuncSetAttribute(hgemm, cudaFuncAttributeMaxDynamicSharedMemorySize, HSMEM);

    dim3 t328(32, 8);
    pack0_kernel<<<32, 256>>>(sW0, sWn0, wsg0);
    transpose_h<<<dim3(8, 8, 1), t328>>>(sW1,  wsg1t,       256, 0, 0, 512);
    transpose_h<<<dim3(8, 8, 1), t328>>>(sWn1, wsg1t + 256, 256, 0, 0, 512);
    transpose_h<<<dim3(8, 8, 1), t328>>>(sW2,  wsg2t,       256, 0, 0, 512);
    transpose_h<<<dim3(8, 8, 1), t328>>>(sWn2, wsg2t + 256, 256, 0, 0, 512);
    transpose_h<<<dim3(8, 8, 4), t328>>>(Wq, wqkvt,                 256, 65536, 196608, 256);
    transpose_h<<<dim3(8, 8, 4), t328>>>(Wk, wqkvt + 256 * 256,     256, 65536, 196608, 256);
    transpose_h<<<dim3(8, 8, 4), t328>>>(Wv, wqkvt + 2 * 256 * 256, 256, 65536, 196608, 256);
    transpose_h<<<dim3(8, 8, 4), t328>>>(Wo, wot, 256, 65536, 65536, 256);
    transpose_h<<<dim3(32, 8, 4), t328>>>(W1, w1t, 1024, 262144, 262144, 256);
    transpose_h<<<dim3(8, 32, 4), t328>>>(W2, w2t, 256, 262144, 262144, 1024);
    pack_bqkv<<<dim3(3, 4), 256>>>(bq, bk, bv, bqkv);

    // ---- CSR build ----
    cudaMemsetAsync(cnt, 0, NN * sizeof(int), 0);
    degi_kernel<<<(NE + 255) / 256, 256>>>(ei, cnt);
    scan_kernel<<<1, 1024>>>(cnt, rowptr);
    fill_kernel<<<(NE + 255) / 256, 256>>>(ei, cnt, csrc);

    // ---- SAGE layer 0 ----
    agg0_kernel<<<NN / 8, 256>>>(x, comb0);
    gemm32h_kernel<<<dim3(256 / BN, NN / BM), 256>>>(comb0, wsg0, sb0, comb1h, 512);

    // ---- SAGE layer 1 ----
    agg_csr_h<<<NN, 128>>>(comb1h);
    run_hgemm(comb1h, wsg1t, sb1, comb2h, NN, 256, 512, 512, 512, 1, 1);

    // ---- SAGE layer 2 ----
    agg_csr_h<<<NN, 128>>>(comb2h);
    run_hgemm(comb2h, wsg2t, sb2, ha, NN, 256, 512, 512, 256, 0, 0);

    // ---- pack & pad ----
    pack_kernel<<<dim3(LMAXC, NG), EMBD>>>(ha, batches, hp, hph);

    // ---- 4 transformer layers ----
    for (int l = 0; l < 4; l++) {
        run_hgemm(hph, wqkvt + (long)l * 196608, bqkv + l * 768, qkvh,
                  NTOK, 768, 256, 256, 768, 0, 1);

        attn_mma<<<dim3(NG, NHD), 128, ATT_SMEM>>>(qkvh, batches, oh);

        run_hgemm(oh, wot + (long)l * 65536, bo + l * 256, tmp,
                  NTOK, 256, 256, 256, 256, 0, 0);
        add_ln_kernel<<<NTOK, EMBD>>>(hp, hph, tmp, ln1g + l * EMBD, ln1b + l * EMBD);

        run_hgemm(hph, w1t + (long)l * 262144, b1 + l * FFND, midh,
                  NTOK, 1024, 256, 256, 1024, 1, 1);
        run_hgemm(midh, w2t + (long)l * 262144, b2 + l * EMBD, tmp,
                  NTOK, 256, 1024, 1024, 256, 0, 0);
        add_ln_kernel<<<NTOK, EMBD>>>(hp, hph, tmp, ln2g + l * EMBD, ln2b + l * EMBD);
    }

    cudaMemcpyAsync(d_out, hp, (size_t)NTOK * EMBD * sizeof(float),
                    cudaMemcpyDeviceToDevice, 0);
}

// round 7
// speedup vs baseline: 5.5452x; 1.0340x over previous
#include <cuda_runtime.h>
#include <cuda_fp16.h>
#include <math.h>
#include <stdint.h>

#define NN   16384
#define NE   262144
#define NG   64
#define LMAXC 320
#define EMBD 256
#define FFND 1024
#define NHD  8
#define DHD  32
#define NTOK (LMAXC*NG)

// ---------------- scratch (device globals; no allocation allowed) ----------
__device__ int   g_rowptr[NN + 1];
__device__ int   g_cnt[NN];
__device__ int   g_csrc[NE];
__device__ float g_comb0[NN*32];
__device__ float g_wsg0[32*256];
__device__ __align__(256) __half g_comb1h[NN*512];
__device__ __align__(256) __half g_comb2h[NN*512];
__device__ float g_ha [NN*EMBD];
__device__ float g_hp [NTOK*EMBD];
__device__ __align__(256) __half g_hph[NTOK*EMBD];
__device__ __align__(256) __half g_qkvh[NTOK*768];
__device__ __align__(256) __half g_oh[NTOK*EMBD];
__device__ float g_tmp[NTOK*EMBD];
__device__ __align__(256) __half g_midh[NTOK*FFND];
__device__ __align__(256) __half g_wsg1t[256*512];
__device__ __align__(256) __half g_wsg2t[256*512];
__device__ __align__(256) __half g_wqkvt[4*768*256];
__device__ __align__(256) __half g_wot[4*256*256];
__device__ __align__(256) __half g_w1t[4*1024*256];
__device__ __align__(256) __half g_w2t[4*256*1024];
__device__ float g_bqkv[4*768];

// =================== CSR build =============================================
__global__ void degi_kernel(const int* __restrict__ ei, int* __restrict__ cnt) {
    int e = blockIdx.x * blockDim.x + threadIdx.x;
    if (e < NE) atomicAdd(&cnt[ei[NE + e]], 1);
}

__global__ void scan_kernel(int* __restrict__ cnt, int* __restrict__ rowptr) {
    __shared__ int wsum[32];
    int t = threadIdx.x;
    int base = t * 16;
    int loc[16];
    int s = 0;
#pragma unroll
    for (int i = 0; i < 16; i++) { loc[i] = s; s += cnt[base + i]; }
    int lane = t & 31, w = t >> 5;
    int inc = s;
#pragma unroll
    for (int off = 1; off < 32; off <<= 1) {
        int v = __shfl_up_sync(0xffffffffu, inc, off);
        if (lane >= off) inc += v;
    }
    if (lane == 31) wsum[w] = inc;
    __syncthreads();
    if (w == 0) {
        int v = wsum[lane];
#pragma unroll
        for (int off = 1; off < 32; off <<= 1) {
            int u = __shfl_up_sync(0xffffffffu, v, off);
            if (lane >= off) v += u;
        }
        wsum[lane] = v;
    }
    __syncthreads();
    int pre = inc - s + (w > 0 ? wsum[w - 1] : 0);
#pragma unroll
    for (int i = 0; i < 16; i++) { rowptr[base + i] = pre + loc[i]; cnt[base + i] = 0; }
    if (t == 1023) rowptr[NN] = pre + s;
}

__global__ void fill_kernel(const int* __restrict__ ei, int* __restrict__ cnt,
                            int* __restrict__ csrc) {
    int e = blockIdx.x * blockDim.x + threadIdx.x;
    if (e >= NE) return;
    int d = ei[NE + e];
    int pos = atomicAdd(&cnt[d], 1);
    csrc[g_rowptr[d] + pos] = ei[e];
}

// =================== SAGE layer-0 input assembly ===========================
__global__ void agg0_kernel(const float* __restrict__ x, float* __restrict__ comb0) {
    int w = threadIdx.x >> 5;
    int lane = threadIdx.x & 31;
    int node = blockIdx.x * 8 + w;
    if (lane >= 16) return;
    int s0 = g_rowptr[node], s1 = g_rowptr[node + 1];
    float sum = 0.f;
    for (int j = s0; j < s1; j++) sum += x[g_csrc[j] * 16 + lane];
    comb0[node * 32 + lane] = x[node * 16 + lane];
    comb0[node * 32 + 16 + lane] = sum / fmaxf((float)(s1 - s0), 1.f);
}

__global__ void agg_csr_h(__half* __restrict__ feat) {
    int node = blockIdx.x;
    int c = threadIdx.x;
    const __half2* f2 = (const __half2*)feat;
    int s0 = g_rowptr[node], s1 = g_rowptr[node + 1];
    float sx = 0.f, sy = 0.f;
    int j = s0;
    for (; j + 2 <= s1; j += 2) {
        int n0 = g_csrc[j], n1 = g_csrc[j + 1];
        float2 a = __half22float2(f2[(long)n0 * 256 + c]);
        float2 b = __half22float2(f2[(long)n1 * 256 + c]);
        sx += a.x + b.x; sy += a.y + b.y;
    }
    for (; j < s1; j++) {
        float2 a = __half22float2(f2[(long)g_csrc[j] * 256 + c]);
        sx += a.x; sy += a.y;
    }
    float inv = 1.f / fmaxf((float)(s1 - s0), 1.f);
    ((__half2*)feat)[(long)node * 256 + 128 + c] = __floats2half2_rn(sx * inv, sy * inv);
}

// =================== weight packing ========================================
__global__ void pack0_kernel(const float* __restrict__ Ws, const float* __restrict__ Wn,
                             float* __restrict__ out) {
    int k = blockIdx.x;
    int n = threadIdx.x;
    out[k * 256 + n] = (k < 16) ? Ws[k * 256 + n] : Wn[(k - 16) * 256 + n];
}

__global__ void pack_bqkv(const float* __restrict__ bq, const float* __restrict__ bk,
                          const float* __restrict__ bv, float* __restrict__ b) {
    int c = threadIdx.x, s = blockIdx.x, l = blockIdx.y;
    const float* src = (s == 0) ? bq : ((s == 1) ? bk : bv);
    b[l * 768 + s * 256 + c] = src[l * 256 + c];
}

// ---- all 10 weight transposes (fp32 [K,N] -> half [N,K]) in ONE launch ----
struct TJobs {
    const float* src[10];
    __half*      dst[10];
    int gx[10], gy[10], N[10], ldd[10];
    long sls[10], dls[10];
    int base[11];
};

__global__ void transpose_all(TJobs J) {
    __shared__ float t[32][33];
    int b = blockIdx.x;
    int j = 0;
#pragma unroll
    for (int i = 0; i < 10; i++) if (b >= J.base[i + 1]) j = i + 1;
    int local = b - J.base[j];
    int tpz = J.gx[j] * J.gy[j];
    int z = local / tpz, rem = local - z * tpz;
    int ky = rem / J.gx[j], nx = rem - ky * J.gx[j];
    const float* s = J.src[j] + (long)z * J.sls[j];
    __half* d = J.dst[j] + (long)z * J.dls[j];
    int N = J.N[j], ldd = J.ldd[j];
    int k0 = ky * 32, n0 = nx * 32;
    int tx = threadIdx.x, ty = threadIdx.y;
#pragma unroll
    for (int i = 0; i < 32; i += 8)
        t[ty + i][tx] = s[(long)(k0 + ty + i) * N + n0 + tx];
    __syncthreads();
#pragma unroll
    for (int i = 0; i < 32; i += 8)
        d[(long)(n0 + ty + i) * ldd + k0 + tx] = __float2half(t[tx][ty + i]);
}

// ================= fp32 GEMM K=32 for SAGE layer 0, half output =============
#define BM 64
#define BN 64
__global__ void gemm32h_kernel(const float* __restrict__ A, const float* __restrict__ B,
                               const float* __restrict__ bias, __half* __restrict__ C,
                               int ldc) {
    __shared__ float As[16][BM + 1];
    __shared__ float Bs[16][BN];
    int bm = blockIdx.y * BM;
    int bn = blockIdx.x * BN;
    int tid = threadIdx.x;
    int tx = tid & 15;
    int ty = tid >> 4;
    float r[4][4];
#pragma unroll
    for (int i = 0; i < 4; i++)
#pragma unroll
        for (int j = 0; j < 4; j++) r[i][j] = 0.0f;

    for (int k0 = 0; k0 < 32; k0 += 16) {
#pragma unroll
        for (int i = 0; i < 4; i++) {
            int idx = tid + i * 256;
            int rr = idx >> 4, cc = idx & 15;
            As[cc][rr] = A[(long)(bm + rr) * 32 + k0 + cc];
        }
#pragma unroll
        for (int i = 0; i < 4; i++) {
            int idx = tid + i * 256;
            int rr = idx >> 6, cc = idx & 63;
            Bs[rr][cc] = B[(long)(k0 + rr) * 256 + bn + cc];
        }
        __syncthreads();
#pragma unroll
        for (int kk = 0; kk < 16; kk++) {
            float a[4], b[4];
#pragma unroll
            for (int i = 0; i < 4; i++) a[i] = As[kk][ty * 4 + i];
#pragma unroll
            for (int j = 0; j < 4; j++) b[j] = Bs[kk][tx * 4 + j];
#pragma unroll
            for (int i = 0; i < 4; i++)
#pragma unroll
                for (int j = 0; j < 4; j++) r[i][j] = fmaf(a[i], b[j], r[i][j]);
        }
        __syncthreads();
    }
#pragma unroll
    for (int i = 0; i < 4; i++) {
        long row = bm + ty * 4 + i;
        __half2* C2 = (__half2*)(C + row * ldc + bn + tx * 4);
#pragma unroll
        for (int j = 0; j < 4; j += 2) {
            int col = bn + tx * 4 + j;
            float v0 = fmaxf(r[i][j] + bias[col], 0.f);
            float v1 = fmaxf(r[i][j + 1] + bias[col + 1], 0.f);
            C2[j >> 1] = __floats2half2_rn(v0, v1);
        }
    }
}

// ================= FP16 tensor-core GEMM (ldmatrix + m16n8k16) ==============
#define HSTR 72
#define HBUF (128*HSTR)
#define HSMEM (4*HBUF*2)

#define CPA16(dst, src) asm volatile("cp.async.cg.shared.global [%0], [%1], 16;" :: "r"(dst), "l"(src))

__device__ __forceinline__ void ldsm4(uint32_t (&r)[4], uint32_t addr) {
    asm volatile("ldmatrix.sync.aligned.m8n8.x4.shared.b16 {%0,%1,%2,%3}, [%4];"
                 : "=r"(r[0]), "=r"(r[1]), "=r"(r[2]), "=r"(r[3]) : "r"(addr));
}
__device__ __forceinline__ void ldsm2(uint32_t (&r)[2], uint32_t addr) {
    asm volatile("ldmatrix.sync.aligned.m8n8.x2.shared.b16 {%0,%1}, [%2];"
                 : "=r"(r[0]), "=r"(r[1]) : "r"(addr));
}
__device__ __forceinline__ void ldsm4t(uint32_t (&r)[4], uint32_t addr) {
    asm volatile("ldmatrix.sync.aligned.m8n8.x4.trans.shared.b16 {%0,%1,%2,%3}, [%4];"
                 : "=r"(r[0]), "=r"(r[1]), "=r"(r[2]), "=r"(r[3]) : "r"(addr));
}

#define HMMA(d, a, b0, b1) asm volatile( \
    "mma.sync.aligned.m16n8k16.row.col.f32.f16.f16.f32 " \
    "{%0,%1,%2,%3}, {%4,%5,%6,%7}, {%8,%9}, {%0,%1,%2,%3};" \
    : "+f"(d[0]), "+f"(d[1]), "+f"(d[2]), "+f"(d[3]) \
    : "r"(a[0]), "r"(a[1]), "r"(a[2]), "r"(a[3]), "r"(b0), "r"(b1))

__device__ __forceinline__ uint32_t packh2(float a, float b) {
    __half2 h = __floats2half2_rn(a, b);
    return *(uint32_t*)&h;
}

__global__ void __launch_bounds__(256, 2)
hgemm(const __half* __restrict__ A, const __half* __restrict__ Bt,
      const float* __restrict__ bias, void* __restrict__ Cv,
      int M, int N, int K, int lda, int ldc, int relu, int outh) {
    extern __shared__ __half shh[];
    const int tid  = threadIdx.x;
    const int lane = tid & 31;
    const int wid  = tid >> 5;
    const int wr   = wid >> 2;
    const int wc   = wid & 3;
    const int bm   = blockIdx.y * 128;
    const int bn   = blockIdx.x * 128;

    uint32_t sbase = (uint32_t)__cvta_generic_to_shared(shh);

    float acc[4][4][4];
#pragma unroll
    for (int mt = 0; mt < 4; mt++)
#pragma unroll
        for (int nt = 0; nt < 4; nt++)
#pragma unroll
            for (int r = 0; r < 4; r++) acc[mt][nt][r] = 0.0f;

#define HLOAD(buf, k0)                                                          \
    do {                                                                        \
        _Pragma("unroll")                                                       \
        for (int i = 0; i < 4; i++) {                                           \
            int idx = tid + i * 256;                                            \
            int r = idx >> 3, c = (idx & 7) << 3;                               \
            CPA16(sbase + (uint32_t)((buf) * HBUF + r * HSTR + c) * 2u,         \
                  A + (long)(bm + r) * lda + (k0) + c);                         \
        }                                                                       \
        _Pragma("unroll")                                                       \
        for (int i = 0; i < 4; i++) {                                           \
            int idx = tid + i * 256;                                            \
            int r = idx >> 3, c = (idx & 7) << 3;                               \
            CPA16(sbase + (uint32_t)((2 + (buf)) * HBUF + r * HSTR + c) * 2u,   \
                  Bt + (long)(bn + r) * K + (k0) + c);                          \
        }                                                                       \
        asm volatile("cp.async.commit_group;");                                 \
    } while (0)

    const int nk = K >> 6;
    HLOAD(0, 0);

    const int arow = wr * 64 + (lane & 15);
    const int ach  = (lane >> 4) << 3;
    const int brow = wc * 32 + (lane & 7);
    const int bch  = ((lane >> 3) & 1) << 3;

    for (int it = 0; it < nk; it++) {
        int cur = it & 1;
        if (it + 1 < nk) {
            HLOAD(cur ^ 1, (it + 1) << 6);
            asm volatile("cp.async.wait_group 1;");
        } else {
            asm volatile("cp.async.wait_group 0;");
        }
        __syncthreads();

        uint32_t aB = sbase + (uint32_t)(cur * HBUF) * 2u;
        uint32_t bB = sbase + (uint32_t)((2 + cur) * HBUF) * 2u;

#pragma unroll
        for (int ks = 0; ks < 4; ks++) {
            uint32_t af[4][4], bf[4][2];
#pragma unroll
            for (int mt = 0; mt < 4; mt++)
                ldsm4(af[mt], aB + (uint32_t)((arow + mt * 16) * HSTR + ks * 16 + ach) * 2u);
#pragma unroll
            for (int nt = 0; nt < 4; nt++)
                ldsm2(bf[nt], bB + (uint32_t)((brow + nt * 8) * HSTR + ks * 16 + bch) * 2u);
#pragma unroll
            for (int mt = 0; mt < 4; mt++)
#pragma unroll
                for (int nt = 0; nt < 4; nt++)
                    HMMA(acc[mt][nt], af[mt], bf[nt][0], bf[nt][1]);
        }
        __syncthreads();
    }

#pragma unroll
    for (int mt = 0; mt < 4; mt++) {
        int row = bm + wr * 64 + mt * 16 + (lane >> 2);
#pragma unroll
        for (int nt = 0; nt < 4; nt++) {
            int col = bn + wc * 32 + nt * 8 + ((lane & 3) << 1);
            float b0 = bias[col], b1 = bias[col + 1];
            float v0 = acc[mt][nt][0] + b0, v1 = acc[mt][nt][1] + b1;
            float v2 = acc[mt][nt][2] + b0, v3 = acc[mt][nt][3] + b1;
            if (relu) { v0 = fmaxf(v0, 0.f); v1 = fmaxf(v1, 0.f);
                        v2 = fmaxf(v2, 0.f); v3 = fmaxf(v3, 0.f); }
            if (outh) {
                __half2* C2 = (__half2*)Cv;
                C2[((long)row * ldc + col) >> 1]       = __floats2half2_rn(v0, v1);
                C2[((long)(row + 8) * ldc + col) >> 1] = __floats2half2_rn(v2, v3);
            } else {
                float* C = (float*)Cv;
                long i0 = (long)row * ldc + col;
                long i1 = i0 + 8L * ldc;
                C[i0] = v0; C[i0 + 1] = v1; C[i1] = v2; C[i1 + 1] = v3;
            }
        }
    }
#undef HLOAD
}

// ---------------- pack nodes into [LMAX, NG, EMB] (zero padding) ------------
__global__ void pack_kernel(const float* __restrict__ z, const int* __restrict__ batches,
                            float* __restrict__ hp, __half* __restrict__ hph) {
    int l = blockIdx.x;
    int g = blockIdx.y;
    int st = batches[g];
    int len = batches[g + 1] - st;
    long o = ((long)l * NG + g) * EMBD + threadIdx.x;
    float v = (l < len) ? z[(long)(st + l) * EMBD + threadIdx.x] : 0.0f;
    hp[o] = v;
    hph[o] = __float2half(v);
}

// ============ tensor-core flash attention: one block per (graph, head) ======
// K,V half [len x 32] staged in smem (row stride 40 -> conflict-free ldmatrix).
// Q fragments loaded directly from gmem. 4 warps x 5 m-tiles of 16 q-rows.
#define ATT_SMEM (2*320*40*2)

__global__ void __launch_bounds__(128, 4)
attn_mma(const __half* __restrict__ qkv, const int* __restrict__ batches,
         __half* __restrict__ oh) {
    int g = blockIdx.x, h = blockIdx.y;
    int len = batches[g + 1] - batches[g];
    extern __shared__ __half smh[];
    uint32_t sb = (uint32_t)__cvta_generic_to_shared(smh);   // K base
    const uint32_t voff = 320u * 40u * 2u;

    int tid = threadIdx.x;
    // stage K,V rows [0, len): 4 chunks of 16B per row (32 halves = one head)
    for (int idx = tid; idx < len * 4; idx += 128) {
        int l = idx >> 2, c = idx & 3;
        const __half* srcK = qkv + ((long)l * NG + g) * 768 + 256 + h * 32 + c * 8;
        uint32_t d = (uint32_t)(l * 40 + c * 8) * 2u;
        CPA16(sb + d, srcK);
        CPA16(sb + voff + d, srcK + 256);
    }
    asm volatile("cp.async.commit_group;");
    asm volatile("cp.async.wait_group 0;");
    __syncthreads();

    const int w = tid >> 5, lane = tid & 31;
    const int r = lane >> 2, t = lane & 3;
    const int nch = (len + 63) >> 6;
    const float scale = 0.17677669529663687f;

    for (int mt = 0; mt < 5; mt++) {
        int m0 = w * 80 + mt * 16;
        // Q fragments direct from gmem (same mapping ldsm4 would produce)
        uint32_t qf[2][4];
        {
            const __half* q0 = qkv + ((long)(m0 + r) * NG + g) * 768 + h * 32;
            const __half* q1 = q0 + 8L * NG * 768;
#pragma unroll
            for (int ks = 0; ks < 2; ks++) {
                int c0 = ks * 16 + 2 * t;
                qf[ks][0] = *(const uint32_t*)(q0 + c0);
                qf[ks][1] = *(const uint32_t*)(q1 + c0);
                qf[ks][2] = *(const uint32_t*)(q0 + c0 + 8);
                qf[ks][3] = *(const uint32_t*)(q1 + c0 + 8);
            }
        }
        float o_[4][4];
#pragma unroll
        for (int nt = 0; nt < 4; nt++)
#pragma unroll
            for (int j = 0; j < 4; j++) o_[nt][j] = 0.f;
        float mx0 = -3e38f, mx1 = -3e38f, sm0 = 0.f, sm1 = 0.f;

        for (int ch = 0; ch < nch; ch++) {
            int base = ch << 6;
            float s[8][4];
#pragma unroll
            for (int nt = 0; nt < 8; nt++)
#pragma unroll
                for (int j = 0; j < 4; j++) s[nt][j] = 0.f;

#pragma unroll
            for (int ks = 0; ks < 2; ks++) {
#pragma unroll
                for (int np = 0; np < 4; np++) {
                    uint32_t kf[4];
                    int krow = base + np * 16 + (lane & 7) + ((lane >> 4) << 3);
                    int kcol = ks * 16 + (lane & 8);
                    ldsm4(kf, sb + (uint32_t)(krow * 40 + kcol) * 2u);
                    HMMA(s[2 * np],     qf[ks], kf[0], kf[1]);
                    HMMA(s[2 * np + 1], qf[ks], kf[2], kf[3]);
                }
            }

            if (base + 64 > len) {
#pragma unroll
                for (int nt = 0; nt < 8; nt++) {
                    int c0 = base + nt * 8 + 2 * t;
                    if (c0 >= len)     { s[nt][0] = -3e38f; s[nt][2] = -3e38f; }
                    if (c0 + 1 >= len) { s[nt][1] = -3e38f; s[nt][3] = -3e38f; }
                }
            }

            float cm0 = -3e38f, cm1 = -3e38f;
#pragma unroll
            for (int nt = 0; nt < 8; nt++) {
                cm0 = fmaxf(cm0, fmaxf(s[nt][0], s[nt][1]));
                cm1 = fmaxf(cm1, fmaxf(s[nt][2], s[nt][3]));
            }
            cm0 = fmaxf(cm0, __shfl_xor_sync(0xffffffffu, cm0, 1));
            cm0 = fmaxf(cm0, __shfl_xor_sync(0xffffffffu, cm0, 2));
            cm1 = fmaxf(cm1, __shfl_xor_sync(0xffffffffu, cm1, 1));
            cm1 = fmaxf(cm1, __shfl_xor_sync(0xffffffffu, cm1, 2));
            float nm0 = fmaxf(mx0, cm0), nm1 = fmaxf(mx1, cm1);
            float corr0 = __expf((mx0 - nm0) * scale);
            float corr1 = __expf((mx1 - nm1) * scale);
            mx0 = nm0; mx1 = nm1;

            uint32_t pf[4][4];
            float ps0 = 0.f, ps1 = 0.f;
#pragma unroll
            for (int kf = 0; kf < 4; kf++) {
                float p00 = __expf((s[2 * kf][0] - nm0) * scale);
                float p01 = __expf((s[2 * kf][1] - nm0) * scale);
                float p02 = __expf((s[2 * kf][2] - nm1) * scale);
                float p03 = __expf((s[2 * kf][3] - nm1) * scale);
                float p10 = __expf((s[2 * kf + 1][0] - nm0) * scale);
                float p11 = __expf((s[2 * kf + 1][1] - nm0) * scale);
                float p12 = __expf((s[2 * kf + 1][2] - nm1) * scale);
                float p13 = __expf((s[2 * kf + 1][3] - nm1) * scale);
                ps0 += (p00 + p01) + (p10 + p11);
                ps1 += (p02 + p03) + (p12 + p13);
                pf[kf][0] = packh2(p00, p01);
                pf[kf][1] = packh2(p02, p03);
                pf[kf][2] = packh2(p10, p11);
                pf[kf][3] = packh2(p12, p13);
            }
            sm0 = sm0 * corr0 + ps0;
            sm1 = sm1 * corr1 + ps1;
#pragma unroll
            for (int nt = 0; nt < 4; nt++) {
                o_[nt][0] *= corr0; o_[nt][1] *= corr0;
                o_[nt][2] *= corr1; o_[nt][3] *= corr1;
            }

#pragma unroll
            for (int kf = 0; kf < 4; kf++) {
                int k0 = base + kf * 16;
                uint32_t vrow = (uint32_t)((k0 + (lane & 15)) * 40 + ((lane >> 4) << 3));
                uint32_t vf[4];
                ldsm4t(vf, sb + voff + vrow * 2u);
                HMMA(o_[0], pf[kf], vf[0], vf[1]);
                HMMA(o_[1], pf[kf], vf[2], vf[3]);
                ldsm4t(vf, sb + voff + (vrow + 16u) * 2u);
                HMMA(o_[2], pf[kf], vf[0], vf[1]);
                HMMA(o_[3], pf[kf], vf[2], vf[3]);
            }
        }

        float rs0 = sm0 + __shfl_xor_sync(0xffffffffu, sm0, 1);
        rs0 += __shfl_xor_sync(0xffffffffu, rs0, 2);
        float rs1 = sm1 + __shfl_xor_sync(0xffffffffu, sm1, 1);
        rs1 += __shfl_xor_sync(0xffffffffu, rs1, 2);
        float inv0 = 1.f / rs0, inv1 = 1.f / rs1;
        long r0base = ((long)(m0 + r) * NG + g) * 256 + h * 32 + 2 * t;
        long r1base = ((long)(m0 + r + 8) * NG + g) * 256 + h * 32 + 2 * t;
#pragma unroll
        for (int nt = 0; nt < 4; nt++) {
            *(__half2*)(oh + r0base + nt * 8) = __floats2half2_rn(o_[nt][0] * inv0, o_[nt][1] * inv0);
            *(__half2*)(oh + r1base + nt * 8) = __floats2half2_rn(o_[nt][2] * inv1, o_[nt][3] * inv1);
        }
    }
}

// ---------------- residual add + LayerNorm (row = 256), dual output ---------
__global__ void add_ln_kernel(float* __restrict__ h, __half* __restrict__ hh,
                              const float* __restrict__ t,
                              const float* __restrict__ gamma, const float* __restrict__ beta) {
    long row = blockIdx.x;
    int c = threadIdx.x;
    float val = h[row * EMBD + c] + t[row * EMBD + c];

    __shared__ float red[8];
    __shared__ float smean, srstd;
    int lane = c & 31, warp = c >> 5;

    float s = val;
#pragma unroll
    for (int off = 16; off; off >>= 1) s += __shfl_xor_sync(0xffffffffu, s, off);
    if (lane == 0) red[warp] = s;
    __syncthreads();
    if (c == 0) {
        float tot = 0.0f;
        for (int i = 0; i < 8; i++) tot += red[i];
        smean = tot * (1.0f / EMBD);
    }
    __syncthreads();
    float d = val - smean;
    float s2 = d * d;
#pragma unroll
    for (int off = 16; off; off >>= 1) s2 += __shfl_xor_sync(0xffffffffu, s2, off);
    if (lane == 0) red[warp] = s2;
    __syncthreads();
    if (c == 0) {
        float tot = 0.0f;
        for (int i = 0; i < 8; i++) tot += red[i];
        srstd = rsqrtf(tot * (1.0f / EMBD) + 1e-5f);
    }
    __syncthreads();
    float out = d * srstd * gamma[c] + beta[c];
    h[row * EMBD + c] = out;
    hh[row * EMBD + c] = __float2half(out);
}

// final layer: residual+LN straight to d_out (fp32)
__global__ void add_ln_out(const float* __restrict__ h, const float* __restrict__ t,
                           const float* __restrict__ gamma, const float* __restrict__ beta,
                           float* __restrict__ out) {
    long row = blockIdx.x;
    int c = threadIdx.x;
    float val = h[row * EMBD + c] + t[row * EMBD + c];

    __shared__ float red[8];
    __shared__ float smean, srstd;
    int lane = c & 31, warp = c >> 5;

    float s = val;
#pragma unroll
    for (int off = 16; off; off >>= 1) s += __shfl_xor_sync(0xffffffffu, s, off);
    if (lane == 0) red[warp] = s;
    __syncthreads();
    if (c == 0) {
        float tot = 0.0f;
        for (int i = 0; i < 8; i++) tot += red[i];
        smean = tot * (1.0f / EMBD);
    }
    __syncthreads();
    float d = val - smean;
    float s2 = d * d;
#pragma unroll
    for (int off = 16; off; off >>= 1) s2 += __shfl_xor_sync(0xffffffffu, s2, off);
    if (lane == 0) red[warp] = s2;
    __syncthreads();
    if (c == 0) {
        float tot = 0.0f;
        for (int i = 0; i < 8; i++) tot += red[i];
        srstd = rsqrtf(tot * (1.0f / EMBD) + 1e-5f);
    }
    __syncthreads();
    out[row * EMBD + c] = d * srstd * gamma[c] + beta[c];
}

// ---------------- host orchestration ----------------------------------------
static void run_hgemm(const __half* A, const __half* Bt, const float* bias, void* C,
                      int M, int N, int K, int lda, int ldc, int relu, int outh) {
    dim3 grid(N / 128, M / 128);
    hgemm<<<grid, 256, HSMEM>>>(A, Bt, bias, C, M, N, K, lda, ldc, relu, outh);
}

extern "C" void kernel_launch(void* const* d_in, const int* in_sizes, int n_in,
                              void* d_out, int out_size) {
    const float* x       = (const float*)d_in[0];
    const int*   ei      = (const int*)d_in[1];
    const int*   batches = (const int*)d_in[2];

    int wi = 3;
    if (n_in >= 29 && in_sizes[3] == 1) wi = 4;

    const float* sW0  = (const float*)d_in[wi++];
    const float* sWn0 = (const float*)d_in[wi++];
    const float* sb0  = (const float*)d_in[wi++];
    const float* sW1  = (const float*)d_in[wi++];
    const float* sWn1 = (const float*)d_in[wi++];
    const float* sb1  = (const float*)d_in[wi++];
    const float* sW2  = (const float*)d_in[wi++];
    const float* sWn2 = (const float*)d_in[wi++];
    const float* sb2  = (const float*)d_in[wi++];
    const float* Wq   = (const float*)d_in[wi++];
    const float* Wk   = (const float*)d_in[wi++];
    const float* Wv   = (const float*)d_in[wi++];
    const float* bq   = (const float*)d_in[wi++];
    const float* bk   = (const float*)d_in[wi++];
    const float* bv   = (const float*)d_in[wi++];
    const float* Wo   = (const float*)d_in[wi++];
    const float* bo   = (const float*)d_in[wi++];
    const float* ln1g = (const float*)d_in[wi++];
    const float* ln1b = (const float*)d_in[wi++];
    const float* ln2g = (const float*)d_in[wi++];
    const float* ln2b = (const float*)d_in[wi++];
    const float* W1   = (const float*)d_in[wi++];
    const float* b1   = (const float*)d_in[wi++];
    const float* W2   = (const float*)d_in[wi++];
    const float* b2   = (const float*)d_in[wi++];

    int *rowptr, *cnt, *csrc;
    float *comb0, *wsg0, *ha, *hp, *tmp, *bqkv;
    __half *comb1h, *comb2h, *hph, *qkvh, *oh, *midh;
    __half *wsg1t, *wsg2t, *wqkvt, *wot, *w1t, *w2t;
    cudaGetSymbolAddress((void**)&rowptr, g_rowptr);
    cudaGetSymbolAddress((void**)&cnt,    g_cnt);
    cudaGetSymbolAddress((void**)&csrc,   g_csrc);
    cudaGetSymbolAddress((void**)&comb0,  g_comb0);
    cudaGetSymbolAddress((void**)&wsg0,   g_wsg0);
    cudaGetSymbolAddress((void**)&comb1h, g_comb1h);
    cudaGetSymbolAddress((void**)&comb2h, g_comb2h);
    cudaGetSymbolAddress((void**)&ha,     g_ha);
    cudaGetSymbolAddress((void**)&hp,     g_hp);
    cudaGetSymbolAddress((void**)&hph,    g_hph);
    cudaGetSymbolAddress((void**)&qkvh,   g_qkvh);
    cudaGetSymbolAddress((void**)&oh,     g_oh);
    cudaGetSymbolAddress((void**)&tmp,    g_tmp);
    cudaGetSymbolAddress((void**)&midh,   g_midh);
    cudaGetSymbolAddress((void**)&wsg1t,  g_wsg1t);
    cudaGetSymbolAddress((void**)&wsg2t,  g_wsg2t);
    cudaGetSymbolAddress((void**)&wqkvt,  g_wqkvt);
    cudaGetSymbolAddress((void**)&wot,    g_wot);
    cudaGetSymbolAddress((void**)&w1t,    g_w1t);
    cudaGetSymbolAddress((void**)&w2t,    g_w2t);
    cudaGetSymbolAddress((void**)&bqkv,   g_bqkv);

    cudaFuncSetAttribute(attn_mma, cudaFuncAttributeMaxDynamicSharedMemorySize, ATT_SMEM);
    cudaFuncSetAttribute(hgemm, cudaFuncAttributeMaxDynamicSharedMemorySize, HSMEM);

    // ---- all weight transposes in one launch ----
    TJobs J;
    const float* srcs[10] = {sW1, sWn1, sW2, sWn2, Wq, Wk, Wv, Wo, W1, W2};
    __half* dsts[10] = {wsg1t, wsg1t + 256, wsg2t, wsg2t + 256,
                        wqkvt, wqkvt + 65536, wqkvt + 131072, wot, w1t, w2t};
    int gxs[10]  = {8, 8, 8, 8, 8, 8, 8, 8, 32, 8};
    int gys[10]  = {8, 8, 8, 8, 8, 8, 8, 8, 8, 32};
    int nzs[10]  = {1, 1, 1, 1, 4, 4, 4, 4, 4, 4};
    int Ns[10]   = {256, 256, 256, 256, 256, 256, 256, 256, 1024, 256};
    int ldds[10] = {512, 512, 512, 512, 256, 256, 256, 256, 256, 1024};
    long slss[10] = {0, 0, 0, 0, 65536, 65536, 65536, 65536, 262144, 262144};
    long dlss[10] = {0, 0, 0, 0, 196608, 196608, 196608, 65536, 262144, 262144};
    int acc = 0;
    for (int i = 0; i < 10; i++) {
        J.src[i] = srcs[i]; J.dst[i] = dsts[i];
        J.gx[i] = gxs[i]; J.gy[i] = gys[i]; J.N[i] = Ns[i]; J.ldd[i] = ldds[i];
        J.sls[i] = slss[i]; J.dls[i] = dlss[i];
        J.base[i] = acc;
        acc += gxs[i] * gys[i] * nzs[i];
    }
    J.base[10] = acc;
    transpose_all<<<acc, dim3(32, 8)>>>(J);
    pack0_kernel<<<32, 256>>>(sW0, sWn0, wsg0);
    pack_bqkv<<<dim3(3, 4), 256>>>(bq, bk, bv, bqkv);

    // ---- CSR build ----
    cudaMemsetAsync(cnt, 0, NN * sizeof(int), 0);
    degi_kernel<<<(NE + 255) / 256, 256>>>(ei, cnt);
    scan_kernel<<<1, 1024>>>(cnt, rowptr);
    fill_kernel<<<(NE + 255) / 256, 256>>>(ei, cnt, csrc);

    // ---- SAGE layer 0 ----
    agg0_kernel<<<NN / 8, 256>>>(x, comb0);
    gemm32h_kernel<<<dim3(256 / BN, NN / BM), 256>>>(comb0, wsg0, sb0, comb1h, 512);

    // ---- SAGE layer 1 ----
    agg_csr_h<<<NN, 128>>>(comb1h);
    run_hgemm(comb1h, wsg1t, sb1, comb2h, NN, 256, 512, 512, 512, 1, 1);

    // ---- SAGE layer 2 ----
    agg_csr_h<<<NN, 128>>>(comb2h);
    run_hgemm(comb2h, wsg2t, sb2, ha, NN, 256, 512, 512, 256, 0, 0);

    // ---- pack & pad ----
    pack_kernel<<<dim3(LMAXC, NG), EMBD>>>(ha, batches, hp, hph);

    // ---- 4 transformer layers ----
    for (int l = 0; l < 4; l++) {
        run_hgemm(hph, wqkvt + (long)l * 196608, bqkv + l * 768, qkvh,
                  NTOK, 768, 256, 256, 768, 0, 1);

        attn_mma<<<dim3(NG, NHD), 128, ATT_SMEM>>>(qkvh, batches, oh);

        run_hgemm(oh, wot + (long)l * 65536, bo + l * 256, tmp,
                  NTOK, 256, 256, 256, 256, 0, 0);
        add_ln_kernel<<<NTOK, EMBD>>>(hp, hph, tmp, ln1g + l * EMBD, ln1b + l * EMBD);

        run_hgemm(hph, w1t + (long)l * 262144, b1 + l * FFND, midh,
                  NTOK, 1024, 256, 256, 1024, 1, 1);
        run_hgemm(midh, w2t + (long)l * 262144, b2 + l * EMBD, tmp,
                  NTOK, 256, 1024, 1024, 256, 0, 0);
        if (l < 3) {
            add_ln_kernel<<<NTOK, EMBD>>>(hp, hph, tmp, ln2g + l * EMBD, ln2b + l * EMBD);
        } else {
            add_ln_out<<<NTOK, EMBD>>>(hp, tmp, ln2g + l * EMBD, ln2b + l * EMBD,
                                       (float*)d_out);
        }
    }
}

// round 8
// speedup vs baseline: 5.9143x; 1.0666x over previous
#include <cuda_runtime.h>
#include <cuda_fp16.h>
#include <math.h>
#include <stdint.h>

#define NN   16384
#define NE   262144
#define NG   64
#define LMAXC 320
#define EMBD 256
#define FFND 1024
#define NHD  8
#define DHD  32
#define NTOK (LMAXC*NG)

// ---------------- scratch (device globals; no allocation allowed) ----------
__device__ int   g_rowptr[NN + 1];
__device__ int   g_cnt[NN];
__device__ int   g_csrc[NE];
__device__ float g_comb0[NN*32];
__device__ float g_wsg0[32*256];
__device__ __align__(256) __half g_comb1h[NN*512];
__device__ __align__(256) __half g_comb2h[NN*512];
__device__ float g_ha [NN*EMBD];
__device__ float g_hp [NTOK*EMBD];
__device__ __align__(256) __half g_hph[NTOK*EMBD];
__device__ __align__(256) __half g_qkvh[NTOK*768];
__device__ __align__(256) __half g_oh[NTOK*EMBD];
__device__ float g_tmp[NTOK*EMBD];
__device__ __align__(256) __half g_midh[NTOK*FFND];
__device__ __align__(256) __half g_wsg1t[256*512];
__device__ __align__(256) __half g_wsg2t[256*512];
__device__ __align__(256) __half g_wqkvt[4*768*256];
__device__ __align__(256) __half g_wot[4*256*256];
__device__ __align__(256) __half g_w1t[4*1024*256];
__device__ __align__(256) __half g_w2t[4*256*1024];
__device__ float g_bqkv[4*768];

// =================== CSR build =============================================
__global__ void degi_kernel(const int* __restrict__ ei, int* __restrict__ cnt) {
    int e = blockIdx.x * blockDim.x + threadIdx.x;
    if (e < NE) atomicAdd(&cnt[ei[NE + e]], 1);
}

__global__ void scan_kernel(int* __restrict__ cnt, int* __restrict__ rowptr) {
    __shared__ int wsum[32];
    int t = threadIdx.x;
    int base = t * 16;
    int loc[16];
    int s = 0;
#pragma unroll
    for (int i = 0; i < 16; i++) { loc[i] = s; s += cnt[base + i]; }
    int lane = t & 31, w = t >> 5;
    int inc = s;
#pragma unroll
    for (int off = 1; off < 32; off <<= 1) {
        int v = __shfl_up_sync(0xffffffffu, inc, off);
        if (lane >= off) inc += v;
    }
    if (lane == 31) wsum[w] = inc;
    __syncthreads();
    if (w == 0) {
        int v = wsum[lane];
#pragma unroll
        for (int off = 1; off < 32; off <<= 1) {
            int u = __shfl_up_sync(0xffffffffu, v, off);
            if (lane >= off) v += u;
        }
        wsum[lane] = v;
    }
    __syncthreads();
    int pre = inc - s + (w > 0 ? wsum[w - 1] : 0);
#pragma unroll
    for (int i = 0; i < 16; i++) { rowptr[base + i] = pre + loc[i]; cnt[base + i] = 0; }
    if (t == 1023) rowptr[NN] = pre + s;
}

__global__ void fill_kernel(const int* __restrict__ ei, int* __restrict__ cnt,
                            int* __restrict__ csrc) {
    int e = blockIdx.x * blockDim.x + threadIdx.x;
    if (e >= NE) return;
    int d = ei[NE + e];
    int pos = atomicAdd(&cnt[d], 1);
    csrc[g_rowptr[d] + pos] = ei[e];
}

// =================== SAGE layer-0 input assembly ===========================
__global__ void agg0_kernel(const float* __restrict__ x, float* __restrict__ comb0) {
    int w = threadIdx.x >> 5;
    int lane = threadIdx.x & 31;
    int node = blockIdx.x * 8 + w;
    if (lane >= 16) return;
    int s0 = g_rowptr[node], s1 = g_rowptr[node + 1];
    float sum = 0.f;
    for (int j = s0; j < s1; j++) sum += x[g_csrc[j] * 16 + lane];
    comb0[node * 32 + lane] = x[node * 16 + lane];
    comb0[node * 32 + 16 + lane] = sum / fmaxf((float)(s1 - s0), 1.f);
}

__global__ void agg_csr_h(__half* __restrict__ feat) {
    int node = blockIdx.x;
    int c = threadIdx.x;
    const __half2* f2 = (const __half2*)feat;
    int s0 = g_rowptr[node], s1 = g_rowptr[node + 1];
    float sx = 0.f, sy = 0.f;
    int j = s0;
    for (; j + 2 <= s1; j += 2) {
        int n0 = g_csrc[j], n1 = g_csrc[j + 1];
        float2 a = __half22float2(f2[(long)n0 * 256 + c]);
        float2 b = __half22float2(f2[(long)n1 * 256 + c]);
        sx += a.x + b.x; sy += a.y + b.y;
    }
    for (; j < s1; j++) {
        float2 a = __half22float2(f2[(long)g_csrc[j] * 256 + c]);
        sx += a.x; sy += a.y;
    }
    float inv = 1.f / fmaxf((float)(s1 - s0), 1.f);
    ((__half2*)feat)[(long)node * 256 + 128 + c] = __floats2half2_rn(sx * inv, sy * inv);
}

// =================== weight packing ========================================
__global__ void pack0_kernel(const float* __restrict__ Ws, const float* __restrict__ Wn,
                             float* __restrict__ out) {
    int k = blockIdx.x;
    int n = threadIdx.x;
    out[k * 256 + n] = (k < 16) ? Ws[k * 256 + n] : Wn[(k - 16) * 256 + n];
}

__global__ void pack_bqkv(const float* __restrict__ bq, const float* __restrict__ bk,
                          const float* __restrict__ bv, float* __restrict__ b) {
    int c = threadIdx.x, s = blockIdx.x, l = blockIdx.y;
    const float* src = (s == 0) ? bq : ((s == 1) ? bk : bv);
    b[l * 768 + s * 256 + c] = src[l * 256 + c];
}

// ---- all 10 weight transposes (fp32 [K,N] -> half [N,K]) in ONE launch ----
struct TJobs {
    const float* src[10];
    __half*      dst[10];
    int gx[10], gy[10], N[10], ldd[10];
    long sls[10], dls[10];
    int base[11];
};

__global__ void transpose_all(TJobs J) {
    __shared__ float t[32][33];
    int b = blockIdx.x;
    int j = 0;
#pragma unroll
    for (int i = 0; i < 10; i++) if (b >= J.base[i + 1]) j = i + 1;
    int local = b - J.base[j];
    int tpz = J.gx[j] * J.gy[j];
    int z = local / tpz, rem = local - z * tpz;
    int ky = rem / J.gx[j], nx = rem - ky * J.gx[j];
    const float* s = J.src[j] + (long)z * J.sls[j];
    __half* d = J.dst[j] + (long)z * J.dls[j];
    int N = J.N[j], ldd = J.ldd[j];
    int k0 = ky * 32, n0 = nx * 32;
    int tx = threadIdx.x, ty = threadIdx.y;
#pragma unroll
    for (int i = 0; i < 32; i += 8)
        t[ty + i][tx] = s[(long)(k0 + ty + i) * N + n0 + tx];
    __syncthreads();
#pragma unroll
    for (int i = 0; i < 32; i += 8)
        d[(long)(n0 + ty + i) * ldd + k0 + tx] = __float2half(t[tx][ty + i]);
}

// ================= fp32 GEMM K=32 for SAGE layer 0, half output =============
#define BM 64
#define BN 64
__global__ void gemm32h_kernel(const float* __restrict__ A, const float* __restrict__ B,
                               const float* __restrict__ bias, __half* __restrict__ C,
                               int ldc) {
    __shared__ float As[16][BM + 1];
    __shared__ float Bs[16][BN];
    int bm = blockIdx.y * BM;
    int bn = blockIdx.x * BN;
    int tid = threadIdx.x;
    int tx = tid & 15;
    int ty = tid >> 4;
    float r[4][4];
#pragma unroll
    for (int i = 0; i < 4; i++)
#pragma unroll
        for (int j = 0; j < 4; j++) r[i][j] = 0.0f;

    for (int k0 = 0; k0 < 32; k0 += 16) {
#pragma unroll
        for (int i = 0; i < 4; i++) {
            int idx = tid + i * 256;
            int rr = idx >> 4, cc = idx & 15;
            As[cc][rr] = A[(long)(bm + rr) * 32 + k0 + cc];
        }
#pragma unroll
        for (int i = 0; i < 4; i++) {
            int idx = tid + i * 256;
            int rr = idx >> 6, cc = idx & 63;
            Bs[rr][cc] = B[(long)(k0 + rr) * 256 + bn + cc];
        }
        __syncthreads();
#pragma unroll
        for (int kk = 0; kk < 16; kk++) {
            float a[4], b[4];
#pragma unroll
            for (int i = 0; i < 4; i++) a[i] = As[kk][ty * 4 + i];
#pragma unroll
            for (int j = 0; j < 4; j++) b[j] = Bs[kk][tx * 4 + j];
#pragma unroll
            for (int i = 0; i < 4; i++)
#pragma unroll
                for (int j = 0; j < 4; j++) r[i][j] = fmaf(a[i], b[j], r[i][j]);
        }
        __syncthreads();
    }
#pragma unroll
    for (int i = 0; i < 4; i++) {
        long row = bm + ty * 4 + i;
        __half2* C2 = (__half2*)(C + row * ldc + bn + tx * 4);
#pragma unroll
        for (int j = 0; j < 4; j += 2) {
            int col = bn + tx * 4 + j;
            float v0 = fmaxf(r[i][j] + bias[col], 0.f);
            float v1 = fmaxf(r[i][j + 1] + bias[col + 1], 0.f);
            C2[j >> 1] = __floats2half2_rn(v0, v1);
        }
    }
}

// ================= FP16 tensor-core GEMM common helpers ======================
#define HSTR 72
#define HBUF (128*HSTR)
#define HSMEM (4*HBUF*2)

#define CPA16(dst, src) asm volatile("cp.async.cg.shared.global [%0], [%1], 16;" :: "r"(dst), "l"(src))

__device__ __forceinline__ void ldsm4(uint32_t (&r)[4], uint32_t addr) {
    asm volatile("ldmatrix.sync.aligned.m8n8.x4.shared.b16 {%0,%1,%2,%3}, [%4];"
                 : "=r"(r[0]), "=r"(r[1]), "=r"(r[2]), "=r"(r[3]) : "r"(addr));
}
__device__ __forceinline__ void ldsm2(uint32_t (&r)[2], uint32_t addr) {
    asm volatile("ldmatrix.sync.aligned.m8n8.x2.shared.b16 {%0,%1}, [%2];"
                 : "=r"(r[0]), "=r"(r[1]) : "r"(addr));
}
__device__ __forceinline__ void ldsm4t(uint32_t (&r)[4], uint32_t addr) {
    asm volatile("ldmatrix.sync.aligned.m8n8.x4.trans.shared.b16 {%0,%1,%2,%3}, [%4];"
                 : "=r"(r[0]), "=r"(r[1]), "=r"(r[2]), "=r"(r[3]) : "r"(addr));
}

#define HMMA(d, a, b0, b1) asm volatile( \
    "mma.sync.aligned.m16n8k16.row.col.f32.f16.f16.f32 " \
    "{%0,%1,%2,%3}, {%4,%5,%6,%7}, {%8,%9}, {%0,%1,%2,%3};" \
    : "+f"(d[0]), "+f"(d[1]), "+f"(d[2]), "+f"(d[3]) \
    : "r"(a[0]), "r"(a[1]), "r"(a[2]), "r"(a[3]), "r"(b0), "r"(b1))

__device__ __forceinline__ uint32_t packh2(float a, float b) {
    __half2 h = __floats2half2_rn(a, b);
    return *(uint32_t*)&h;
}

// ================= hgemm: 128x128 tile (for N=768/1024 GEMMs) ===============
__global__ void __launch_bounds__(256, 2)
hgemm(const __half* __restrict__ A, const __half* __restrict__ Bt,
      const float* __restrict__ bias, void* __restrict__ Cv,
      int M, int N, int K, int lda, int ldc, int relu, int outh) {
    extern __shared__ __half shh[];
    const int tid  = threadIdx.x;
    const int lane = tid & 31;
    const int wid  = tid >> 5;
    const int wr   = wid >> 2;
    const int wc   = wid & 3;
    const int bm   = blockIdx.y * 128;
    const int bn   = blockIdx.x * 128;

    uint32_t sbase = (uint32_t)__cvta_generic_to_shared(shh);

    float acc[4][4][4];
#pragma unroll
    for (int mt = 0; mt < 4; mt++)
#pragma unroll
        for (int nt = 0; nt < 4; nt++)
#pragma unroll
            for (int r = 0; r < 4; r++) acc[mt][nt][r] = 0.0f;

#define HLOAD(buf, k0)                                                          \
    do {                                                                        \
        _Pragma("unroll")                                                       \
        for (int i = 0; i < 4; i++) {                                           \
            int idx = tid + i * 256;                                            \
            int r = idx >> 3, c = (idx & 7) << 3;                               \
            CPA16(sbase + (uint32_t)((buf) * HBUF + r * HSTR + c) * 2u,         \
                  A + (long)(bm + r) * lda + (k0) + c);                         \
        }                                                                       \
        _Pragma("unroll")                                                       \
        for (int i = 0; i < 4; i++) {                                           \
            int idx = tid + i * 256;                                            \
            int r = idx >> 3, c = (idx & 7) << 3;                               \
            CPA16(sbase + (uint32_t)((2 + (buf)) * HBUF + r * HSTR + c) * 2u,   \
                  Bt + (long)(bn + r) * K + (k0) + c);                          \
        }                                                                       \
        asm volatile("cp.async.commit_group;");                                 \
    } while (0)

    const int nk = K >> 6;
    HLOAD(0, 0);

    const int arow = wr * 64 + (lane & 15);
    const int ach  = (lane >> 4) << 3;
    const int brow = wc * 32 + (lane & 7);
    const int bch  = ((lane >> 3) & 1) << 3;

    for (int it = 0; it < nk; it++) {
        int cur = it & 1;
        if (it + 1 < nk) {
            HLOAD(cur ^ 1, (it + 1) << 6);
            asm volatile("cp.async.wait_group 1;");
        } else {
            asm volatile("cp.async.wait_group 0;");
        }
        __syncthreads();

        uint32_t aB = sbase + (uint32_t)(cur * HBUF) * 2u;
        uint32_t bB = sbase + (uint32_t)((2 + cur) * HBUF) * 2u;

#pragma unroll
        for (int ks = 0; ks < 4; ks++) {
            uint32_t af[4][4], bf[4][2];
#pragma unroll
            for (int mt = 0; mt < 4; mt++)
                ldsm4(af[mt], aB + (uint32_t)((arow + mt * 16) * HSTR + ks * 16 + ach) * 2u);
#pragma unroll
            for (int nt = 0; nt < 4; nt++)
                ldsm2(bf[nt], bB + (uint32_t)((brow + nt * 8) * HSTR + ks * 16 + bch) * 2u);
#pragma unroll
            for (int mt = 0; mt < 4; mt++)
#pragma unroll
                for (int nt = 0; nt < 4; nt++)
                    HMMA(acc[mt][nt], af[mt], bf[nt][0], bf[nt][1]);
        }
        __syncthreads();
    }

#pragma unroll
    for (int mt = 0; mt < 4; mt++) {
        int row = bm + wr * 64 + mt * 16 + (lane >> 2);
#pragma unroll
        for (int nt = 0; nt < 4; nt++) {
            int col = bn + wc * 32 + nt * 8 + ((lane & 3) << 1);
            float b0 = bias[col], b1 = bias[col + 1];
            float v0 = acc[mt][nt][0] + b0, v1 = acc[mt][nt][1] + b1;
            float v2 = acc[mt][nt][2] + b0, v3 = acc[mt][nt][3] + b1;
            if (relu) { v0 = fmaxf(v0, 0.f); v1 = fmaxf(v1, 0.f);
                        v2 = fmaxf(v2, 0.f); v3 = fmaxf(v3, 0.f); }
            if (outh) {
                __half2* C2 = (__half2*)Cv;
                C2[((long)row * ldc + col) >> 1]       = __floats2half2_rn(v0, v1);
                C2[((long)(row + 8) * ldc + col) >> 1] = __floats2half2_rn(v2, v3);
            } else {
                float* C = (float*)Cv;
                long i0 = (long)row * ldc + col;
                long i1 = i0 + 8L * ldc;
                C[i0] = v0; C[i0 + 1] = v1; C[i1] = v2; C[i1 + 1] = v3;
            }
        }
    }
#undef HLOAD
}

// ========== hgemm64: 128x64 tile (kills wave quantization for N=256) ========
#define A64BUF (128*HSTR)
#define B64BUF (64*HSTR)
#define HSMEM64 ((2*A64BUF + 2*B64BUF)*2)

__global__ void __launch_bounds__(256, 2)
hgemm64(const __half* __restrict__ A, const __half* __restrict__ Bt,
        const float* __restrict__ bias, void* __restrict__ Cv,
        int M, int N, int K, int lda, int ldc, int relu, int outh) {
    extern __shared__ __half shh[];
    const int tid  = threadIdx.x;
    const int lane = tid & 31;
    const int wid  = tid >> 5;
    const int wr   = wid >> 1;   // 0..3 (32 rows each)
    const int wc   = wid & 1;    // 0..1 (32 cols each)
    const int bm   = blockIdx.y * 128;
    const int bn   = blockIdx.x * 64;

    uint32_t sbase = (uint32_t)__cvta_generic_to_shared(shh);

    float acc[2][4][4];
#pragma unroll
    for (int mt = 0; mt < 2; mt++)
#pragma unroll
        for (int nt = 0; nt < 4; nt++)
#pragma unroll
            for (int r = 0; r < 4; r++) acc[mt][nt][r] = 0.0f;

#define HLOAD64(buf, k0)                                                        \
    do {                                                                        \
        _Pragma("unroll")                                                       \
        for (int i = 0; i < 4; i++) {                                           \
            int idx = tid + i * 256;                                            \
            int r = idx >> 3, c = (idx & 7) << 3;                               \
            CPA16(sbase + (uint32_t)((buf) * A64BUF + r * HSTR + c) * 2u,       \
                  A + (long)(bm + r) * lda + (k0) + c);                         \
        }                                                                       \
        _Pragma("unroll")                                                       \
        for (int i = 0; i < 2; i++) {                                           \
            int idx = tid + i * 256;                                            \
            int r = idx >> 3, c = (idx & 7) << 3;                               \
            CPA16(sbase + (uint32_t)(2 * A64BUF + (buf) * B64BUF + r * HSTR + c) * 2u, \
                  Bt + (long)(bn + r) * K + (k0) + c);                          \
        }                                                                       \
        asm volatile("cp.async.commit_group;");                                 \
    } while (0)

    const int nk = K >> 6;
    HLOAD64(0, 0);

    const int arow = wr * 32 + (lane & 15);
    const int ach  = (lane >> 4) << 3;
    const int brow = wc * 32 + (lane & 7);
    const int bch  = ((lane >> 3) & 1) << 3;

    for (int it = 0; it < nk; it++) {
        int cur = it & 1;
        if (it + 1 < nk) {
            HLOAD64(cur ^ 1, (it + 1) << 6);
            asm volatile("cp.async.wait_group 1;");
        } else {
            asm volatile("cp.async.wait_group 0;");
        }
        __syncthreads();

        uint32_t aB = sbase + (uint32_t)(cur * A64BUF) * 2u;
        uint32_t bB = sbase + (uint32_t)(2 * A64BUF + cur * B64BUF) * 2u;

#pragma unroll
        for (int ks = 0; ks < 4; ks++) {
            uint32_t af[2][4], bf[4][2];
#pragma unroll
            for (int mt = 0; mt < 2; mt++)
                ldsm4(af[mt], aB + (uint32_t)((arow + mt * 16) * HSTR + ks * 16 + ach) * 2u);
#pragma unroll
            for (int nt = 0; nt < 4; nt++)
                ldsm2(bf[nt], bB + (uint32_t)((brow + nt * 8) * HSTR + ks * 16 + bch) * 2u);
#pragma unroll
            for (int mt = 0; mt < 2; mt++)
#pragma unroll
                for (int nt = 0; nt < 4; nt++)
                    HMMA(acc[mt][nt], af[mt], bf[nt][0], bf[nt][1]);
        }
        __syncthreads();
    }

#pragma unroll
    for (int mt = 0; mt < 2; mt++) {
        int row = bm + wr * 32 + mt * 16 + (lane >> 2);
#pragma unroll
        for (int nt = 0; nt < 4; nt++) {
            int col = bn + wc * 32 + nt * 8 + ((lane & 3) << 1);
            float b0 = bias[col], b1 = bias[col + 1];
            float v0 = acc[mt][nt][0] + b0, v1 = acc[mt][nt][1] + b1;
            float v2 = acc[mt][nt][2] + b0, v3 = acc[mt][nt][3] + b1;
            if (relu) { v0 = fmaxf(v0, 0.f); v1 = fmaxf(v1, 0.f);
                        v2 = fmaxf(v2, 0.f); v3 = fmaxf(v3, 0.f); }
            if (outh) {
                __half2* C2 = (__half2*)Cv;
                C2[((long)row * ldc + col) >> 1]       = __floats2half2_rn(v0, v1);
                C2[((long)(row + 8) * ldc + col) >> 1] = __floats2half2_rn(v2, v3);
            } else {
                float* C = (float*)Cv;
                long i0 = (long)row * ldc + col;
                long i1 = i0 + 8L * ldc;
                C[i0] = v0; C[i0 + 1] = v1; C[i1] = v2; C[i1 + 1] = v3;
            }
        }
    }
#undef HLOAD64
}

// ---------------- pack nodes into [LMAX, NG, EMB] (zero padding) ------------
__global__ void pack_kernel(const float* __restrict__ z, const int* __restrict__ batches,
                            float* __restrict__ hp, __half* __restrict__ hph) {
    int l = blockIdx.x;
    int g = blockIdx.y;
    int st = batches[g];
    int len = batches[g + 1] - st;
    long o = ((long)l * NG + g) * EMBD + threadIdx.x;
    float v = (l < len) ? z[(long)(st + l) * EMBD + threadIdx.x] : 0.0f;
    hp[o] = v;
    hph[o] = __float2half(v);
}

// ============ tensor-core flash attention: one block per (graph, head) ======
#define ATT_SMEM (2*320*40*2)

__global__ void __launch_bounds__(128, 4)
attn_mma(const __half* __restrict__ qkv, const int* __restrict__ batches,
         __half* __restrict__ oh) {
    int g = blockIdx.x, h = blockIdx.y;
    int len = batches[g + 1] - batches[g];
    extern __shared__ __half smh[];
    uint32_t sb = (uint32_t)__cvta_generic_to_shared(smh);   // K base
    const uint32_t voff = 320u * 40u * 2u;

    int tid = threadIdx.x;
    for (int idx = tid; idx < len * 4; idx += 128) {
        int l = idx >> 2, c = idx & 3;
        const __half* srcK = qkv + ((long)l * NG + g) * 768 + 256 + h * 32 + c * 8;
        uint32_t d = (uint32_t)(l * 40 + c * 8) * 2u;
        CPA16(sb + d, srcK);
        CPA16(sb + voff + d, srcK + 256);
    }
    asm volatile("cp.async.commit_group;");
    asm volatile("cp.async.wait_group 0;");
    __syncthreads();

    const int w = tid >> 5, lane = tid & 31;
    const int r = lane >> 2, t = lane & 3;
    const int nch = (len + 63) >> 6;
    const float scale = 0.17677669529663687f;

    for (int mt = 0; mt < 5; mt++) {
        int m0 = w * 80 + mt * 16;
        uint32_t qf[2][4];
        {
            const __half* q0 = qkv + ((long)(m0 + r) * NG + g) * 768 + h * 32;
            const __half* q1 = q0 + 8L * NG * 768;
#pragma unroll
            for (int ks = 0; ks < 2; ks++) {
                int c0 = ks * 16 + 2 * t;
                qf[ks][0] = *(const uint32_t*)(q0 + c0);
                qf[ks][1] = *(const uint32_t*)(q1 + c0);
                qf[ks][2] = *(const uint32_t*)(q0 + c0 + 8);
                qf[ks][3] = *(const uint32_t*)(q1 + c0 + 8);
            }
        }
        float o_[4][4];
#pragma unroll
        for (int nt = 0; nt < 4; nt++)
#pragma unroll
            for (int j = 0; j < 4; j++) o_[nt][j] = 0.f;
        float mx0 = -3e38f, mx1 = -3e38f, sm0 = 0.f, sm1 = 0.f;

        for (int ch = 0; ch < nch; ch++) {
            int base = ch << 6;
            float s[8][4];
#pragma unroll
            for (int nt = 0; nt < 8; nt++)
#pragma unroll
                for (int j = 0; j < 4; j++) s[nt][j] = 0.f;

#pragma unroll
            for (int ks = 0; ks < 2; ks++) {
#pragma unroll
                for (int np = 0; np < 4; np++) {
                    uint32_t kf[4];
                    int krow = base + np * 16 + (lane & 7) + ((lane >> 4) << 3);
                    int kcol = ks * 16 + (lane & 8);
                    ldsm4(kf, sb + (uint32_t)(krow * 40 + kcol) * 2u);
                    HMMA(s[2 * np],     qf[ks], kf[0], kf[1]);
                    HMMA(s[2 * np + 1], qf[ks], kf[2], kf[3]);
                }
            }

            if (base + 64 > len) {
#pragma unroll
                for (int nt = 0; nt < 8; nt++) {
                    int c0 = base + nt * 8 + 2 * t;
                    if (c0 >= len)     { s[nt][0] = -3e38f; s[nt][2] = -3e38f; }
                    if (c0 + 1 >= len) { s[nt][1] = -3e38f; s[nt][3] = -3e38f; }
                }
            }

            float cm0 = -3e38f, cm1 = -3e38f;
#pragma unroll
            for (int nt = 0; nt < 8; nt++) {
                cm0 = fmaxf(cm0, fmaxf(s[nt][0], s[nt][1]));
                cm1 = fmaxf(cm1, fmaxf(s[nt][2], s[nt][3]));
            }
            cm0 = fmaxf(cm0, __shfl_xor_sync(0xffffffffu, cm0, 1));
            cm0 = fmaxf(cm0, __shfl_xor_sync(0xffffffffu, cm0, 2));
            cm1 = fmaxf(cm1, __shfl_xor_sync(0xffffffffu, cm1, 1));
            cm1 = fmaxf(cm1, __shfl_xor_sync(0xffffffffu, cm1, 2));
            float nm0 = fmaxf(mx0, cm0), nm1 = fmaxf(mx1, cm1);
            float corr0 = __expf((mx0 - nm0) * scale);
            float corr1 = __expf((mx1 - nm1) * scale);
            mx0 = nm0; mx1 = nm1;

            uint32_t pf[4][4];
            float ps0 = 0.f, ps1 = 0.f;
#pragma unroll
            for (int kf = 0; kf < 4; kf++) {
                float p00 = __expf((s[2 * kf][0] - nm0) * scale);
                float p01 = __expf((s[2 * kf][1] - nm0) * scale);
                float p02 = __expf((s[2 * kf][2] - nm1) * scale);
                float p03 = __expf((s[2 * kf][3] - nm1) * scale);
                float p10 = __expf((s[2 * kf + 1][0] - nm0) * scale);
                float p11 = __expf((s[2 * kf + 1][1] - nm0) * scale);
                float p12 = __expf((s[2 * kf + 1][2] - nm1) * scale);
                float p13 = __expf((s[2 * kf + 1][3] - nm1) * scale);
                ps0 += (p00 + p01) + (p10 + p11);
                ps1 += (p02 + p03) + (p12 + p13);
                pf[kf][0] = packh2(p00, p01);
                pf[kf][1] = packh2(p02, p03);
                pf[kf][2] = packh2(p10, p11);
                pf[kf][3] = packh2(p12, p13);
            }
            sm0 = sm0 * corr0 + ps0;
            sm1 = sm1 * corr1 + ps1;
#pragma unroll
            for (int nt = 0; nt < 4; nt++) {
                o_[nt][0] *= corr0; o_[nt][1] *= corr0;
                o_[nt][2] *= corr1; o_[nt][3] *= corr1;
            }

#pragma unroll
            for (int kf = 0; kf < 4; kf++) {
                int k0 = base + kf * 16;
                uint32_t vrow = (uint32_t)((k0 + (lane & 15)) * 40 + ((lane >> 4) << 3));
                uint32_t vf[4];
                ldsm4t(vf, sb + voff + vrow * 2u);
                HMMA(o_[0], pf[kf], vf[0], vf[1]);
                HMMA(o_[1], pf[kf], vf[2], vf[3]);
                ldsm4t(vf, sb + voff + (vrow + 16u) * 2u);
                HMMA(o_[2], pf[kf], vf[0], vf[1]);
                HMMA(o_[3], pf[kf], vf[2], vf[3]);
            }
        }

        float rs0 = sm0 + __shfl_xor_sync(0xffffffffu, sm0, 1);
        rs0 += __shfl_xor_sync(0xffffffffu, rs0, 2);
        float rs1 = sm1 + __shfl_xor_sync(0xffffffffu, sm1, 1);
        rs1 += __shfl_xor_sync(0xffffffffu, rs1, 2);
        float inv0 = 1.f / rs0, inv1 = 1.f / rs1;
        long r0base = ((long)(m0 + r) * NG + g) * 256 + h * 32 + 2 * t;
        long r1base = ((long)(m0 + r + 8) * NG + g) * 256 + h * 32 + 2 * t;
#pragma unroll
        for (int nt = 0; nt < 4; nt++) {
            *(__half2*)(oh + r0base + nt * 8) = __floats2half2_rn(o_[nt][0] * inv0, o_[nt][1] * inv0);
            *(__half2*)(oh + r1base + nt * 8) = __floats2half2_rn(o_[nt][2] * inv1, o_[nt][3] * inv1);
        }
    }
}

// ------- residual add + LayerNorm: one WARP per row, shfl-only reductions ---
__device__ __forceinline__ void warp_ln_row(const float* __restrict__ h,
                                            const float* __restrict__ t,
                                            const float* __restrict__ gamma,
                                            const float* __restrict__ beta,
                                            long row, int lane,
                                            float* __restrict__ outf,
                                            __half* __restrict__ outh) {
    const float4* h4 = (const float4*)(h + row * EMBD) + lane * 2;
    const float4* t4 = (const float4*)(t + row * EMBD) + lane * 2;
    float4 a0 = h4[0], a1 = h4[1];
    float4 b0 = t4[0], b1 = t4[1];
    float v[8];
    v[0] = a0.x + b0.x; v[1] = a0.y + b0.y; v[2] = a0.z + b0.z; v[3] = a0.w + b0.w;
    v[4] = a1.x + b1.x; v[5] = a1.y + b1.y; v[6] = a1.z + b1.z; v[7] = a1.w + b1.w;

    float s = ((v[0] + v[1]) + (v[2] + v[3])) + ((v[4] + v[5]) + (v[6] + v[7]));
#pragma unroll
    for (int off = 16; off; off >>= 1) s += __shfl_xor_sync(0xffffffffu, s, off);
    float mean = s * (1.0f / EMBD);

    float s2 = 0.f;
#pragma unroll
    for (int i = 0; i < 8; i++) { float d = v[i] - mean; s2 += d * d; }
#pragma unroll
    for (int off = 16; off; off >>= 1) s2 += __shfl_xor_sync(0xffffffffu, s2, off);
    float rstd = rsqrtf(s2 * (1.0f / EMBD) + 1e-5f);

    const float4* g4 = (const float4*)gamma + lane * 2;
    const float4* be4 = (const float4*)beta + lane * 2;
    float4 g0 = g4[0], g1 = g4[1];
    float4 e0 = be4[0], e1 = be4[1];
    float o[8];
    o[0] = (v[0] - mean) * rstd * g0.x + e0.x;
    o[1] = (v[1] - mean) * rstd * g0.y + e0.y;
    o[2] = (v[2] - mean) * rstd * g0.z + e0.z;
    o[3] = (v[3] - mean) * rstd * g0.w + e0.w;
    o[4] = (v[4] - mean) * rstd * g1.x + e1.x;
    o[5] = (v[5] - mean) * rstd * g1.y + e1.y;
    o[6] = (v[6] - mean) * rstd * g1.z + e1.z;
    o[7] = (v[7] - mean) * rstd * g1.w + e1.w;

    float4* of4 = (float4*)(outf + row * EMBD) + lane * 2;
    of4[0] = make_float4(o[0], o[1], o[2], o[3]);
    of4[1] = make_float4(o[4], o[5], o[6], o[7]);
    if (outh) {
        __half2* oh2 = (__half2*)(outh + row * EMBD) + lane * 4;
        oh2[0] = __floats2half2_rn(o[0], o[1]);
        oh2[1] = __floats2half2_rn(o[2], o[3]);
        oh2[2] = __floats2half2_rn(o[4], o[5]);
        oh2[3] = __floats2half2_rn(o[6], o[7]);
    }
}

__global__ void add_ln_warp(float* __restrict__ h, __half* __restrict__ hh,
                            const float* __restrict__ t,
                            const float* __restrict__ gamma, const float* __restrict__ beta) {
    long row = (long)blockIdx.x * 8 + (threadIdx.x >> 5);
    warp_ln_row(h, t, gamma, beta, row, threadIdx.x & 31, h, hh);
}

__global__ void add_ln_warp_out(const float* __restrict__ h, const float* __restrict__ t,
                                const float* __restrict__ gamma, const float* __restrict__ beta,
                                float* __restrict__ out) {
    long row = (long)blockIdx.x * 8 + (threadIdx.x >> 5);
    warp_ln_row(h, t, gamma, beta, row, threadIdx.x & 31, out, nullptr);
}

// ---------------- host orchestration ----------------------------------------
static void run_hgemm(const __half* A, const __half* Bt, const float* bias, void* C,
                      int M, int N, int K, int lda, int ldc, int relu, int outh) {
    dim3 grid(N / 128, M / 128);
    hgemm<<<grid, 256, HSMEM>>>(A, Bt, bias, C, M, N, K, lda, ldc, relu, outh);
}

static void run_hgemm64(const __half* A, const __half* Bt, const float* bias, void* C,
                        int M, int N, int K, int lda, int ldc, int relu, int outh) {
    dim3 grid(N / 64, M / 128);
    hgemm64<<<grid, 256, HSMEM64>>>(A, Bt, bias, C, M, N, K, lda, ldc, relu, outh);
}

extern "C" void kernel_launch(void* const* d_in, const int* in_sizes, int n_in,
                              void* d_out, int out_size) {
    const float* x       = (const float*)d_in[0];
    const int*   ei      = (const int*)d_in[1];
    const int*   batches = (const int*)d_in[2];

    int wi = 3;
    if (n_in >= 29 && in_sizes[3] == 1) wi = 4;

    const float* sW0  = (const float*)d_in[wi++];
    const float* sWn0 = (const float*)d_in[wi++];
    const float* sb0  = (const float*)d_in[wi++];
    const float* sW1  = (const float*)d_in[wi++];
    const float* sWn1 = (const float*)d_in[wi++];
    const float* sb1  = (const float*)d_in[wi++];
    const float* sW2  = (const float*)d_in[wi++];
    const float* sWn2 = (const float*)d_in[wi++];
    const float* sb2  = (const float*)d_in[wi++];
    const float* Wq   = (const float*)d_in[wi++];
    const float* Wk   = (const float*)d_in[wi++];
    const float* Wv   = (const float*)d_in[wi++];
    const float* bq   = (const float*)d_in[wi++];
    const float* bk   = (const float*)d_in[wi++];
    const float* bv   = (const float*)d_in[wi++];
    const float* Wo   = (const float*)d_in[wi++];
    const float* bo   = (const float*)d_in[wi++];
    const float* ln1g = (const float*)d_in[wi++];
    const float* ln1b = (const float*)d_in[wi++];
    const float* ln2g = (const float*)d_in[wi++];
    const float* ln2b = (const float*)d_in[wi++];
    const float* W1   = (const float*)d_in[wi++];
    const float* b1   = (const float*)d_in[wi++];
    const float* W2   = (const float*)d_in[wi++];
    const float* b2   = (const float*)d_in[wi++];

    int *rowptr, *cnt, *csrc;
    float *comb0, *wsg0, *ha, *hp, *tmp, *bqkv;
    __half *comb1h, *comb2h, *hph, *qkvh, *oh, *midh;
    __half *wsg1t, *wsg2t, *wqkvt, *wot, *w1t, *w2t;
    cudaGetSymbolAddress((void**)&rowptr, g_rowptr);
    cudaGetSymbolAddress((void**)&cnt,    g_cnt);
    cudaGetSymbolAddress((void**)&csrc,   g_csrc);
    cudaGetSymbolAddress((void**)&comb0,  g_comb0);
    cudaGetSymbolAddress((void**)&wsg0,   g_wsg0);
    cudaGetSymbolAddress((void**)&comb1h, g_comb1h);
    cudaGetSymbolAddress((void**)&comb2h, g_comb2h);
    cudaGetSymbolAddress((void**)&ha,     g_ha);
    cudaGetSymbolAddress((void**)&hp,     g_hp);
    cudaGetSymbolAddress((void**)&hph,    g_hph);
    cudaGetSymbolAddress((void**)&qkvh,   g_qkvh);
    cudaGetSymbolAddress((void**)&oh,     g_oh);
    cudaGetSymbolAddress((void**)&tmp,    g_tmp);
    cudaGetSymbolAddress((void**)&midh,   g_midh);
    cudaGetSymbolAddress((void**)&wsg1t,  g_wsg1t);
    cudaGetSymbolAddress((void**)&wsg2t,  g_wsg2t);
    cudaGetSymbolAddress((void**)&wqkvt,  g_wqkvt);
    cudaGetSymbolAddress((void**)&wot,    g_wot);
    cudaGetSymbolAddress((void**)&w1t,    g_w1t);
    cudaGetSymbolAddress((void**)&w2t,    g_w2t);
    cudaGetSymbolAddress((void**)&bqkv,   g_bqkv);

    cudaFuncSetAttribute(attn_mma, cudaFuncAttributeMaxDynamicSharedMemorySize, ATT_SMEM);
    cudaFuncSetAttribute(hgemm, cudaFuncAttributeMaxDynamicSharedMemorySize, HSMEM);
    cudaFuncSetAttribute(hgemm64, cudaFuncAttributeMaxDynamicSharedMemorySize, HSMEM64);

    // ---- all weight transposes in one launch ----
    TJobs J;
    const float* srcs[10] = {sW1, sWn1, sW2, sWn2, Wq, Wk, Wv, Wo, W1, W2};
    __half* dsts[10] = {wsg1t, wsg1t + 256, wsg2t, wsg2t + 256,
                        wqkvt, wqkvt + 65536, wqkvt + 131072, wot, w1t, w2t};
    int gxs[10]  = {8, 8, 8, 8, 8, 8, 8, 8, 32, 8};
    int gys[10]  = {8, 8, 8, 8, 8, 8, 8, 8, 8, 32};
    int nzs[10]  = {1, 1, 1, 1, 4, 4, 4, 4, 4, 4};
    int Ns[10]   = {256, 256, 256, 256, 256, 256, 256, 256, 1024, 256};
    int ldds[10] = {512, 512, 512, 512, 256, 256, 256, 256, 256, 1024};
    long slss[10] = {0, 0, 0, 0, 65536, 65536, 65536, 65536, 262144, 262144};
    long dlss[10] = {0, 0, 0, 0, 196608, 196608, 196608, 65536, 262144, 262144};
    int acc = 0;
    for (int i = 0; i < 10; i++) {
        J.src[i] = srcs[i]; J.dst[i] = dsts[i];
        J.gx[i] = gxs[i]; J.gy[i] = gys[i]; J.N[i] = Ns[i]; J.ldd[i] = ldds[i];
        J.sls[i] = slss[i]; J.dls[i] = dlss[i];
        J.base[i] = acc;
        acc += gxs[i] * gys[i] * nzs[i];
    }
    J.base[10] = acc;
    transpose_all<<<acc, dim3(32, 8)>>>(J);
    pack0_kernel<<<32, 256>>>(sW0, sWn0, wsg0);
    pack_bqkv<<<dim3(3, 4), 256>>>(bq, bk, bv, bqkv);

    // ---- CSR build ----
    cudaMemsetAsync(cnt, 0, NN * sizeof(int), 0);
    degi_kernel<<<(NE + 255) / 256, 256>>>(ei, cnt);
    scan_kernel<<<1, 1024>>>(cnt, rowptr);
    fill_kernel<<<(NE + 255) / 256, 256>>>(ei, cnt, csrc);

    // ---- SAGE layer 0 ----
    agg0_kernel<<<NN / 8, 256>>>(x, comb0);
    gemm32h_kernel<<<dim3(256 / BN, NN / BM), 256>>>(comb0, wsg0, sb0, comb1h, 512);

    // ---- SAGE layer 1 ----
    agg_csr_h<<<NN, 128>>>(comb1h);
    run_hgemm64(comb1h, wsg1t, sb1, comb2h, NN, 256, 512, 512, 512, 1, 1);

    // ---- SAGE layer 2 ----
    agg_csr_h<<<NN, 128>>>(comb2h);
    run_hgemm64(comb2h, wsg2t, sb2, ha, NN, 256, 512, 512, 256, 0, 0);

    // ---- pack & pad ----
    pack_kernel<<<dim3(LMAXC, NG), EMBD>>>(ha, batches, hp, hph);

    // ---- 4 transformer layers ----
    for (int l = 0; l < 4; l++) {
        run_hgemm(hph, wqkvt + (long)l * 196608, bqkv + l * 768, qkvh,
                  NTOK, 768, 256, 256, 768, 0, 1);

        attn_mma<<<dim3(NG, NHD), 128, ATT_SMEM>>>(qkvh, batches, oh);

        run_hgemm64(oh, wot + (long)l * 65536, bo + l * 256, tmp,
                    NTOK, 256, 256, 256, 256, 0, 0);
        add_ln_warp<<<NTOK / 8, 256>>>(hp, hph, tmp, ln1g + l * EMBD, ln1b + l * EMBD);

        run_hgemm(hph, w1t + (long)l * 262144, b1 + l * FFND, midh,
                  NTOK, 1024, 256, 256, 1024, 1, 1);
        run_hgemm64(midh, w2t + (long)l * 262144, b2 + l * EMBD, tmp,
                    NTOK, 256, 1024, 1024, 256, 0, 0);
        if (l < 3) {
            add_ln_warp<<<NTOK / 8, 256>>>(hp, hph, tmp, ln2g + l * EMBD, ln2b + l * EMBD);
        } else {
            add_ln_warp_out<<<NTOK / 8, 256>>>(hp, tmp, ln2g + l * EMBD, ln2b + l * EMBD,
                                               (float*)d_out);
        }
    }
}

// round 9
// speedup vs baseline: 6.1335x; 1.0371x over previous
#include <cuda_runtime.h>
#include <cuda_fp16.h>
#include <math.h>
#include <stdint.h>

#define NN   16384
#define NE   262144
#define NG   64
#define LMAXC 320
#define EMBD 256
#define FFND 1024
#define NHD  8
#define DHD  32
#define NTOK (LMAXC*NG)

// ---------------- scratch (device globals; no allocation allowed) ----------
__device__ int   g_rowptr[NN + 1];
__device__ int   g_cnt[NN];
__device__ int   g_csrc[NE];
__device__ float g_comb0[NN*32];
__device__ float g_wsg0[32*256];
__device__ __align__(256) __half g_comb1h[NN*512];
__device__ __align__(256) __half g_comb2h[NN*512];
__device__ float g_ha [NN*EMBD];
__device__ float g_hp [NTOK*EMBD];
__device__ __align__(256) __half g_hph[NTOK*EMBD];
__device__ __align__(256) __half g_qkvh[NTOK*768];
__device__ __align__(256) __half g_oh[NTOK*EMBD];
__device__ __align__(256) __half g_midh[NTOK*FFND];
__device__ __align__(256) __half g_wsg1t[256*512];
__device__ __align__(256) __half g_wsg2t[256*512];
__device__ __align__(256) __half g_wqkvt[4*768*256];
__device__ __align__(256) __half g_wot[4*256*256];
__device__ __align__(256) __half g_w1t[4*1024*256];
__device__ __align__(256) __half g_w2t[4*256*1024];
__device__ float g_bqkv[4*768];

// =================== CSR build =============================================
__global__ void degi_kernel(const int* __restrict__ ei, int* __restrict__ cnt) {
    int e = blockIdx.x * blockDim.x + threadIdx.x;
    if (e < NE) atomicAdd(&cnt[ei[NE + e]], 1);
}

__global__ void scan_kernel(int* __restrict__ cnt, int* __restrict__ rowptr) {
    __shared__ int wsum[32];
    int t = threadIdx.x;
    int base = t * 16;
    int loc[16];
    int s = 0;
#pragma unroll
    for (int i = 0; i < 16; i++) { loc[i] = s; s += cnt[base + i]; }
    int lane = t & 31, w = t >> 5;
    int inc = s;
#pragma unroll
    for (int off = 1; off < 32; off <<= 1) {
        int v = __shfl_up_sync(0xffffffffu, inc, off);
        if (lane >= off) inc += v;
    }
    if (lane == 31) wsum[w] = inc;
    __syncthreads();
    if (w == 0) {
        int v = wsum[lane];
#pragma unroll
        for (int off = 1; off < 32; off <<= 1) {
            int u = __shfl_up_sync(0xffffffffu, v, off);
            if (lane >= off) v += u;
        }
        wsum[lane] = v;
    }
    __syncthreads();
    int pre = inc - s + (w > 0 ? wsum[w - 1] : 0);
#pragma unroll
    for (int i = 0; i < 16; i++) { rowptr[base + i] = pre + loc[i]; cnt[base + i] = 0; }
    if (t == 1023) rowptr[NN] = pre + s;
}

__global__ void fill_kernel(const int* __restrict__ ei, int* __restrict__ cnt,
                            int* __restrict__ csrc) {
    int e = blockIdx.x * blockDim.x + threadIdx.x;
    if (e >= NE) return;
    int d = ei[NE + e];
    int pos = atomicAdd(&cnt[d], 1);
    csrc[g_rowptr[d] + pos] = ei[e];
}

// =================== SAGE layer-0 input assembly ===========================
__global__ void agg0_kernel(const float* __restrict__ x, float* __restrict__ comb0) {
    int w = threadIdx.x >> 5;
    int lane = threadIdx.x & 31;
    int node = blockIdx.x * 8 + w;
    if (lane >= 16) return;
    int s0 = g_rowptr[node], s1 = g_rowptr[node + 1];
    float sum = 0.f;
    for (int j = s0; j < s1; j++) sum += x[g_csrc[j] * 16 + lane];
    comb0[node * 32 + lane] = x[node * 16 + lane];
    comb0[node * 32 + 16 + lane] = sum / fmaxf((float)(s1 - s0), 1.f);
}

__global__ void agg_csr_h(__half* __restrict__ feat) {
    int node = blockIdx.x;
    int c = threadIdx.x;
    const __half2* f2 = (const __half2*)feat;
    int s0 = g_rowptr[node], s1 = g_rowptr[node + 1];
    float sx = 0.f, sy = 0.f;
    int j = s0;
    for (; j + 4 <= s1; j += 4) {
        int n0 = g_csrc[j], n1 = g_csrc[j + 1], n2 = g_csrc[j + 2], n3 = g_csrc[j + 3];
        float2 a = __half22float2(f2[(long)n0 * 256 + c]);
        float2 b = __half22float2(f2[(long)n1 * 256 + c]);
        float2 d = __half22float2(f2[(long)n2 * 256 + c]);
        float2 e = __half22float2(f2[(long)n3 * 256 + c]);
        sx += (a.x + b.x) + (d.x + e.x); sy += (a.y + b.y) + (d.y + e.y);
    }
    for (; j < s1; j++) {
        float2 a = __half22float2(f2[(long)g_csrc[j] * 256 + c]);
        sx += a.x; sy += a.y;
    }
    float inv = 1.f / fmaxf((float)(s1 - s0), 1.f);
    ((__half2*)feat)[(long)node * 256 + 128 + c] = __floats2half2_rn(sx * inv, sy * inv);
}

// =================== weight packing ========================================
__global__ void pack0_kernel(const float* __restrict__ Ws, const float* __restrict__ Wn,
                             float* __restrict__ out) {
    int k = blockIdx.x;
    int n = threadIdx.x;
    out[k * 256 + n] = (k < 16) ? Ws[k * 256 + n] : Wn[(k - 16) * 256 + n];
}

__global__ void pack_bqkv(const float* __restrict__ bq, const float* __restrict__ bk,
                          const float* __restrict__ bv, float* __restrict__ b) {
    int c = threadIdx.x, s = blockIdx.x, l = blockIdx.y;
    const float* src = (s == 0) ? bq : ((s == 1) ? bk : bv);
    b[l * 768 + s * 256 + c] = src[l * 256 + c];
}

// ---- all 10 weight transposes (fp32 [K,N] -> half [N,K]) in ONE launch ----
struct TJobs {
    const float* src[10];
    __half*      dst[10];
    int gx[10], gy[10], N[10], ldd[10];
    long sls[10], dls[10];
    int base[11];
};

__global__ void transpose_all(TJobs J) {
    __shared__ float t[32][33];
    int b = blockIdx.x;
    int j = 0;
#pragma unroll
    for (int i = 0; i < 10; i++) if (b >= J.base[i + 1]) j = i + 1;
    int local = b - J.base[j];
    int tpz = J.gx[j] * J.gy[j];
    int z = local / tpz, rem = local - z * tpz;
    int ky = rem / J.gx[j], nx = rem - ky * J.gx[j];
    const float* s = J.src[j] + (long)z * J.sls[j];
    __half* d = J.dst[j] + (long)z * J.dls[j];
    int N = J.N[j], ldd = J.ldd[j];
    int k0 = ky * 32, n0 = nx * 32;
    int tx = threadIdx.x, ty = threadIdx.y;
#pragma unroll
    for (int i = 0; i < 32; i += 8)
        t[ty + i][tx] = s[(long)(k0 + ty + i) * N + n0 + tx];
    __syncthreads();
#pragma unroll
    for (int i = 0; i < 32; i += 8)
        d[(long)(n0 + ty + i) * ldd + k0 + tx] = __float2half(t[tx][ty + i]);
}

// ================= fp32 GEMM K=32 for SAGE layer 0, half output =============
#define BM 64
#define BN 64
__global__ void gemm32h_kernel(const float* __restrict__ A, const float* __restrict__ B,
                               const float* __restrict__ bias, __half* __restrict__ C,
                               int ldc) {
    __shared__ float As[16][BM + 1];
    __shared__ float Bs[16][BN];
    int bm = blockIdx.y * BM;
    int bn = blockIdx.x * BN;
    int tid = threadIdx.x;
    int tx = tid & 15;
    int ty = tid >> 4;
    float r[4][4];
#pragma unroll
    for (int i = 0; i < 4; i++)
#pragma unroll
        for (int j = 0; j < 4; j++) r[i][j] = 0.0f;

    for (int k0 = 0; k0 < 32; k0 += 16) {
#pragma unroll
        for (int i = 0; i < 4; i++) {
            int idx = tid + i * 256;
            int rr = idx >> 4, cc = idx & 15;
            As[cc][rr] = A[(long)(bm + rr) * 32 + k0 + cc];
        }
#pragma unroll
        for (int i = 0; i < 4; i++) {
            int idx = tid + i * 256;
            int rr = idx >> 6, cc = idx & 63;
            Bs[rr][cc] = B[(long)(k0 + rr) * 256 + bn + cc];
        }
        __syncthreads();
#pragma unroll
        for (int kk = 0; kk < 16; kk++) {
            float a[4], b[4];
#pragma unroll
            for (int i = 0; i < 4; i++) a[i] = As[kk][ty * 4 + i];
#pragma unroll
            for (int j = 0; j < 4; j++) b[j] = Bs[kk][tx * 4 + j];
#pragma unroll
            for (int i = 0; i < 4; i++)
#pragma unroll
                for (int j = 0; j < 4; j++) r[i][j] = fmaf(a[i], b[j], r[i][j]);
        }
        __syncthreads();
    }
#pragma unroll
    for (int i = 0; i < 4; i++) {
        long row = bm + ty * 4 + i;
        __half2* C2 = (__half2*)(C + row * ldc + bn + tx * 4);
#pragma unroll
        for (int j = 0; j < 4; j += 2) {
            int col = bn + tx * 4 + j;
            float v0 = fmaxf(r[i][j] + bias[col], 0.f);
            float v1 = fmaxf(r[i][j + 1] + bias[col + 1], 0.f);
            C2[j >> 1] = __floats2half2_rn(v0, v1);
        }
    }
}

// ================= FP16 tensor-core GEMM common helpers ======================
#define HSTR 72
#define HBUF (128*HSTR)
#define HSMEM (4*HBUF*2)

#define CPA16(dst, src) asm volatile("cp.async.cg.shared.global [%0], [%1], 16;" :: "r"(dst), "l"(src))

__device__ __forceinline__ void ldsm4(uint32_t (&r)[4], uint32_t addr) {
    asm volatile("ldmatrix.sync.aligned.m8n8.x4.shared.b16 {%0,%1,%2,%3}, [%4];"
                 : "=r"(r[0]), "=r"(r[1]), "=r"(r[2]), "=r"(r[3]) : "r"(addr));
}
__device__ __forceinline__ void ldsm2(uint32_t (&r)[2], uint32_t addr) {
    asm volatile("ldmatrix.sync.aligned.m8n8.x2.shared.b16 {%0,%1}, [%2];"
                 : "=r"(r[0]), "=r"(r[1]) : "r"(addr));
}
__device__ __forceinline__ void ldsm4t(uint32_t (&r)[4], uint32_t addr) {
    asm volatile("ldmatrix.sync.aligned.m8n8.x4.trans.shared.b16 {%0,%1,%2,%3}, [%4];"
                 : "=r"(r[0]), "=r"(r[1]), "=r"(r[2]), "=r"(r[3]) : "r"(addr));
}

#define HMMA(d, a, b0, b1) asm volatile( \
    "mma.sync.aligned.m16n8k16.row.col.f32.f16.f16.f32 " \
    "{%0,%1,%2,%3}, {%4,%5,%6,%7}, {%8,%9}, {%0,%1,%2,%3};" \
    : "+f"(d[0]), "+f"(d[1]), "+f"(d[2]), "+f"(d[3]) \
    : "r"(a[0]), "r"(a[1]), "r"(a[2]), "r"(a[3]), "r"(b0), "r"(b1))

__device__ __forceinline__ uint32_t packh2(float a, float b) {
    __half2 h = __floats2half2_rn(a, b);
    return *(uint32_t*)&h;
}

// ================= hgemm: 128x128 tile (for N=768/1024 GEMMs) ===============
__global__ void __launch_bounds__(256, 2)
hgemm(const __half* __restrict__ A, const __half* __restrict__ Bt,
      const float* __restrict__ bias, void* __restrict__ Cv,
      int M, int N, int K, int lda, int ldc, int relu, int outh) {
    extern __shared__ __half shh[];
    const int tid  = threadIdx.x;
    const int lane = tid & 31;
    const int wid  = tid >> 5;
    const int wr   = wid >> 2;
    const int wc   = wid & 3;
    const int bm   = blockIdx.y * 128;
    const int bn   = blockIdx.x * 128;

    uint32_t sbase = (uint32_t)__cvta_generic_to_shared(shh);

    float acc[4][4][4];
#pragma unroll
    for (int mt = 0; mt < 4; mt++)
#pragma unroll
        for (int nt = 0; nt < 4; nt++)
#pragma unroll
            for (int r = 0; r < 4; r++) acc[mt][nt][r] = 0.0f;

#define HLOAD(buf, k0)                                                          \
    do {                                                                        \
        _Pragma("unroll")                                                       \
        for (int i = 0; i < 4; i++) {                                           \
            int idx = tid + i * 256;                                            \
            int r = idx >> 3, c = (idx & 7) << 3;                               \
            CPA16(sbase + (uint32_t)((buf) * HBUF + r * HSTR + c) * 2u,         \
                  A + (long)(bm + r) * lda + (k0) + c);                         \
        }                                                                       \
        _Pragma("unroll")                                                       \
        for (int i = 0; i < 4; i++) {                                           \
            int idx = tid + i * 256;                                            \
            int r = idx >> 3, c = (idx & 7) << 3;                               \
            CPA16(sbase + (uint32_t)((2 + (buf)) * HBUF + r * HSTR + c) * 2u,   \
                  Bt + (long)(bn + r) * K + (k0) + c);                          \
        }                                                                       \
        asm volatile("cp.async.commit_group;");                                 \
    } while (0)

    const int nk = K >> 6;
    HLOAD(0, 0);

    const int arow = wr * 64 + (lane & 15);
    const int ach  = (lane >> 4) << 3;
    const int brow = wc * 32 + (lane & 7);
    const int bch  = ((lane >> 3) & 1) << 3;

    for (int it = 0; it < nk; it++) {
        int cur = it & 1;
        if (it + 1 < nk) {
            HLOAD(cur ^ 1, (it + 1) << 6);
            asm volatile("cp.async.wait_group 1;");
        } else {
            asm volatile("cp.async.wait_group 0;");
        }
        __syncthreads();

        uint32_t aB = sbase + (uint32_t)(cur * HBUF) * 2u;
        uint32_t bB = sbase + (uint32_t)((2 + cur) * HBUF) * 2u;

#pragma unroll
        for (int ks = 0; ks < 4; ks++) {
            uint32_t af[4][4], bf[4][2];
#pragma unroll
            for (int mt = 0; mt < 4; mt++)
                ldsm4(af[mt], aB + (uint32_t)((arow + mt * 16) * HSTR + ks * 16 + ach) * 2u);
#pragma unroll
            for (int nt = 0; nt < 4; nt++)
                ldsm2(bf[nt], bB + (uint32_t)((brow + nt * 8) * HSTR + ks * 16 + bch) * 2u);
#pragma unroll
            for (int mt = 0; mt < 4; mt++)
#pragma unroll
                for (int nt = 0; nt < 4; nt++)
                    HMMA(acc[mt][nt], af[mt], bf[nt][0], bf[nt][1]);
        }
        __syncthreads();
    }

#pragma unroll
    for (int mt = 0; mt < 4; mt++) {
        int row = bm + wr * 64 + mt * 16 + (lane >> 2);
#pragma unroll
        for (int nt = 0; nt < 4; nt++) {
            int col = bn + wc * 32 + nt * 8 + ((lane & 3) << 1);
            float b0 = bias[col], b1 = bias[col + 1];
            float v0 = acc[mt][nt][0] + b0, v1 = acc[mt][nt][1] + b1;
            float v2 = acc[mt][nt][2] + b0, v3 = acc[mt][nt][3] + b1;
            if (relu) { v0 = fmaxf(v0, 0.f); v1 = fmaxf(v1, 0.f);
                        v2 = fmaxf(v2, 0.f); v3 = fmaxf(v3, 0.f); }
            if (outh) {
                __half2* C2 = (__half2*)Cv;
                C2[((long)row * ldc + col) >> 1]       = __floats2half2_rn(v0, v1);
                C2[((long)(row + 8) * ldc + col) >> 1] = __floats2half2_rn(v2, v3);
            } else {
                float* C = (float*)Cv;
                long i0 = (long)row * ldc + col;
                long i1 = i0 + 8L * ldc;
                C[i0] = v0; C[i0 + 1] = v1; C[i1] = v2; C[i1 + 1] = v3;
            }
        }
    }
#undef HLOAD
}

// ========== hgemm64: 128x64 tile (SAGE layers, N=256) ========================
#define A64BUF (128*HSTR)
#define B64BUF (64*HSTR)
#define HSMEM64 ((2*A64BUF + 2*B64BUF)*2)

__global__ void __launch_bounds__(256, 2)
hgemm64(const __half* __restrict__ A, const __half* __restrict__ Bt,
        const float* __restrict__ bias, void* __restrict__ Cv,
        int M, int N, int K, int lda, int ldc, int relu, int outh) {
    extern __shared__ __half shh[];
    const int tid  = threadIdx.x;
    const int lane = tid & 31;
    const int wid  = tid >> 5;
    const int wr   = wid >> 1;
    const int wc   = wid & 1;
    const int bm   = blockIdx.y * 128;
    const int bn   = blockIdx.x * 64;

    uint32_t sbase = (uint32_t)__cvta_generic_to_shared(shh);

    float acc[2][4][4];
#pragma unroll
    for (int mt = 0; mt < 2; mt++)
#pragma unroll
        for (int nt = 0; nt < 4; nt++)
#pragma unroll
            for (int r = 0; r < 4; r++) acc[mt][nt][r] = 0.0f;

#define HLOAD64(buf, k0)                                                        \
    do {                                                                        \
        _Pragma("unroll")                                                       \
        for (int i = 0; i < 4; i++) {                                           \
            int idx = tid + i * 256;                                            \
            int r = idx >> 3, c = (idx & 7) << 3;                               \
            CPA16(sbase + (uint32_t)((buf) * A64BUF + r * HSTR + c) * 2u,       \
                  A + (long)(bm + r) * lda + (k0) + c);                         \
        }                                                                       \
        _Pragma("unroll")                                                       \
        for (int i = 0; i < 2; i++) {                                           \
            int idx = tid + i * 256;                                            \
            int r = idx >> 3, c = (idx & 7) << 3;                               \
            CPA16(sbase + (uint32_t)(2 * A64BUF + (buf) * B64BUF + r * HSTR + c) * 2u, \
                  Bt + (long)(bn + r) * K + (k0) + c);                          \
        }                                                                       \
        asm volatile("cp.async.commit_group;");                                 \
    } while (0)

    const int nk = K >> 6;
    HLOAD64(0, 0);

    const int arow = wr * 32 + (lane & 15);
    const int ach  = (lane >> 4) << 3;
    const int brow = wc * 32 + (lane & 7);
    const int bch  = ((lane >> 3) & 1) << 3;

    for (int it = 0; it < nk; it++) {
        int cur = it & 1;
        if (it + 1 < nk) {
            HLOAD64(cur ^ 1, (it + 1) << 6);
            asm volatile("cp.async.wait_group 1;");
        } else {
            asm volatile("cp.async.wait_group 0;");
        }
        __syncthreads();

        uint32_t aB = sbase + (uint32_t)(cur * A64BUF) * 2u;
        uint32_t bB = sbase + (uint32_t)(2 * A64BUF + cur * B64BUF) * 2u;

#pragma unroll
        for (int ks = 0; ks < 4; ks++) {
            uint32_t af[2][4], bf[4][2];
#pragma unroll
            for (int mt = 0; mt < 2; mt++)
                ldsm4(af[mt], aB + (uint32_t)((arow + mt * 16) * HSTR + ks * 16 + ach) * 2u);
#pragma unroll
            for (int nt = 0; nt < 4; nt++)
                ldsm2(bf[nt], bB + (uint32_t)((brow + nt * 8) * HSTR + ks * 16 + bch) * 2u);
#pragma unroll
            for (int mt = 0; mt < 2; mt++)
#pragma unroll
                for (int nt = 0; nt < 4; nt++)
                    HMMA(acc[mt][nt], af[mt], bf[nt][0], bf[nt][1]);
        }
        __syncthreads();
    }

#pragma unroll
    for (int mt = 0; mt < 2; mt++) {
        int row = bm + wr * 32 + mt * 16 + (lane >> 2);
#pragma unroll
        for (int nt = 0; nt < 4; nt++) {
            int col = bn + wc * 32 + nt * 8 + ((lane & 3) << 1);
            float b0 = bias[col], b1 = bias[col + 1];
            float v0 = acc[mt][nt][0] + b0, v1 = acc[mt][nt][1] + b1;
            float v2 = acc[mt][nt][2] + b0, v3 = acc[mt][nt][3] + b1;
            if (relu) { v0 = fmaxf(v0, 0.f); v1 = fmaxf(v1, 0.f);
                        v2 = fmaxf(v2, 0.f); v3 = fmaxf(v3, 0.f); }
            if (outh) {
                __half2* C2 = (__half2*)Cv;
                C2[((long)row * ldc + col) >> 1]       = __floats2half2_rn(v0, v1);
                C2[((long)(row + 8) * ldc + col) >> 1] = __floats2half2_rn(v2, v3);
            } else {
                float* C = (float*)Cv;
                long i0 = (long)row * ldc + col;
                long i1 = i0 + 8L * ldc;
                C[i0] = v0; C[i0 + 1] = v1; C[i1] = v2; C[i1 + 1] = v3;
            }
        }
    }
#undef HLOAD64
}

// ===== hgemm_ln: 64x256 tile GEMM + bias + residual + LayerNorm epilogue ====
// C row = LN(resid_row + A_row@Bt^T + bias); writes fp32 (outf) and opt half.
#define LNA (64*HSTR)
#define LNB (256*HSTR)
#define HSMEM_LN ((2*LNA + 2*LNB)*2)

__global__ void __launch_bounds__(256, 2)
hgemm_ln(const __half* __restrict__ A, const __half* __restrict__ Bt,
         const float* __restrict__ bias, const float* __restrict__ resid,
         const float* __restrict__ gamma, const float* __restrict__ beta,
         float* __restrict__ outf, __half* __restrict__ outh, int K) {
    extern __shared__ __half shh[];
    __shared__ float red[64][4];
    const int tid  = threadIdx.x;
    const int lane = tid & 31;
    const int wid  = tid >> 5;
    const int wr   = wid >> 2;   // 0..1 (32 rows each)
    const int wc   = wid & 3;    // 0..3 (64 cols each)
    const long bm  = (long)blockIdx.x * 64;

    uint32_t sbase = (uint32_t)__cvta_generic_to_shared(shh);

    float acc[2][8][4];
#pragma unroll
    for (int mt = 0; mt < 2; mt++)
#pragma unroll
        for (int nt = 0; nt < 8; nt++)
#pragma unroll
            for (int r = 0; r < 4; r++) acc[mt][nt][r] = 0.0f;

#define LNLOAD(buf, k0)                                                         \
    do {                                                                        \
        _Pragma("unroll")                                                       \
        for (int i = 0; i < 2; i++) {                                           \
            int idx = tid + i * 256;                                            \
            int r = idx >> 3, c = (idx & 7) << 3;                               \
            CPA16(sbase + (uint32_t)((buf) * LNA + r * HSTR + c) * 2u,          \
                  A + (bm + r) * K + (k0) + c);                                 \
        }                                                                       \
        _Pragma("unroll")                                                       \
        for (int i = 0; i < 8; i++) {                                           \
            int idx = tid + i * 256;                                            \
            int r = idx >> 3, c = (idx & 7) << 3;                               \
            CPA16(sbase + (uint32_t)(2 * LNA + (buf) * LNB + r * HSTR + c) * 2u,\
                  Bt + (long)r * K + (k0) + c);                                 \
        }                                                                       \
        asm volatile("cp.async.commit_group;");                                 \
    } while (0)

    const int nk = K >> 6;
    LNLOAD(0, 0);

    const int arowb = wr * 32 + (lane & 15);
    const int ach   = (lane >> 4) << 3;
    const int browb = wc * 64 + (lane & 7) + ((lane >> 4) << 3);
    const int bch   = lane & 8;

    for (int it = 0; it < nk; it++) {
        int cur = it & 1;
        if (it + 1 < nk) {
            LNLOAD(cur ^ 1, (it + 1) << 6);
            asm volatile("cp.async.wait_group 1;");
        } else {
            asm volatile("cp.async.wait_group 0;");
        }
        __syncthreads();

        uint32_t aB = sbase + (uint32_t)(cur * LNA) * 2u;
        uint32_t bB = sbase + (uint32_t)(2 * LNA + cur * LNB) * 2u;

#pragma unroll
        for (int ks = 0; ks < 4; ks++) {
            uint32_t af[2][4];
#pragma unroll
            for (int mt = 0; mt < 2; mt++)
                ldsm4(af[mt], aB + (uint32_t)((arowb + mt * 16) * HSTR + ks * 16 + ach) * 2u);
#pragma unroll
            for (int np = 0; np < 4; np++) {
                uint32_t kf[4];
                ldsm4(kf, bB + (uint32_t)((browb + np * 16) * HSTR + ks * 16 + bch) * 2u);
#pragma unroll
                for (int mt = 0; mt < 2; mt++) {
                    HMMA(acc[mt][2 * np],     af[mt], kf[0], kf[1]);
                    HMMA(acc[mt][2 * np + 1], af[mt], kf[2], kf[3]);
                }
            }
        }
        __syncthreads();
    }

    // ---- fused epilogue: bias + residual, then LayerNorm over the 256-row --
    const int q = lane >> 2, t2 = (lane & 3) << 1;
    // phase 1: add bias+residual in place, per-warp row partial sums
#pragma unroll
    for (int mt = 0; mt < 2; mt++) {
        long r0 = bm + wr * 32 + mt * 16 + q;
        long r1 = r0 + 8;
        float s0 = 0.f, s1 = 0.f;
#pragma unroll
        for (int nt = 0; nt < 8; nt++) {
            int col = wc * 64 + nt * 8 + t2;
            float b0 = bias[col], b1 = bias[col + 1];
            float2 q0 = *(const float2*)(resid + r0 * 256 + col);
            float2 q1 = *(const float2*)(resid + r1 * 256 + col);
            acc[mt][nt][0] += b0 + q0.x; acc[mt][nt][1] += b1 + q0.y;
            acc[mt][nt][2] += b0 + q1.x; acc[mt][nt][3] += b1 + q1.y;
            s0 += acc[mt][nt][0] + acc[mt][nt][1];
            s1 += acc[mt][nt][2] + acc[mt][nt][3];
        }
        s0 += __shfl_xor_sync(0xffffffffu, s0, 1);
        s0 += __shfl_xor_sync(0xffffffffu, s0, 2);
        s1 += __shfl_xor_sync(0xffffffffu, s1, 1);
        s1 += __shfl_xor_sync(0xffffffffu, s1, 2);
        int lr = wr * 32 + mt * 16 + q;
        if ((lane & 3) == 0) { red[lr][wc] = s0; red[lr + 8][wc] = s1; }
    }
    __syncthreads();
    float mean[2][2];
#pragma unroll
    for (int mt = 0; mt < 2; mt++) {
        int lr = wr * 32 + mt * 16 + q;
        mean[mt][0] = (red[lr][0] + red[lr][1] + red[lr][2] + red[lr][3]) * (1.0f / EMBD);
        mean[mt][1] = (red[lr + 8][0] + red[lr + 8][1] + red[lr + 8][2] + red[lr + 8][3]) * (1.0f / EMBD);
    }
    __syncthreads();
    // phase 2: variance
#pragma unroll
    for (int mt = 0; mt < 2; mt++) {
        float s0 = 0.f, s1 = 0.f;
#pragma unroll
        for (int nt = 0; nt < 8; nt++) {
            float d0 = acc[mt][nt][0] - mean[mt][0];
            float d1 = acc[mt][nt][1] - mean[mt][0];
            float d2 = acc[mt][nt][2] - mean[mt][1];
            float d3 = acc[mt][nt][3] - mean[mt][1];
            s0 += d0 * d0 + d1 * d1;
            s1 += d2 * d2 + d3 * d3;
        }
        s0 += __shfl_xor_sync(0xffffffffu, s0, 1);
        s0 += __shfl_xor_sync(0xffffffffu, s0, 2);
        s1 += __shfl_xor_sync(0xffffffffu, s1, 1);
        s1 += __shfl_xor_sync(0xffffffffu, s1, 2);
        int lr = wr * 32 + mt * 16 + q;
        if ((lane & 3) == 0) { red[lr][wc] = s0; red[lr + 8][wc] = s1; }
    }
    __syncthreads();
#pragma unroll
    for (int mt = 0; mt < 2; mt++) {
        int lr = wr * 32 + mt * 16 + q;
        float rstd0 = rsqrtf((red[lr][0] + red[lr][1] + red[lr][2] + red[lr][3]) * (1.0f / EMBD) + 1e-5f);
        float rstd1 = rsqrtf((red[lr + 8][0] + red[lr + 8][1] + red[lr + 8][2] + red[lr + 8][3]) * (1.0f / EMBD) + 1e-5f);
        long r0 = bm + lr;
        long r1 = r0 + 8;
#pragma unroll
        for (int nt = 0; nt < 8; nt++) {
            int col = wc * 64 + nt * 8 + t2;
            float g0 = gamma[col], g1 = gamma[col + 1];
            float e0 = beta[col],  e1 = beta[col + 1];
            float o0 = (acc[mt][nt][0] - mean[mt][0]) * rstd0 * g0 + e0;
            float o1 = (acc[mt][nt][1] - mean[mt][0]) * rstd0 * g1 + e1;
            float o2 = (acc[mt][nt][2] - mean[mt][1]) * rstd1 * g0 + e0;
            float o3 = (acc[mt][nt][3] - mean[mt][1]) * rstd1 * g1 + e1;
            *(float2*)(outf + r0 * 256 + col) = make_float2(o0, o1);
            *(float2*)(outf + r1 * 256 + col) = make_float2(o2, o3);
            if (outh) {
                *(__half2*)(outh + r0 * 256 + col) = __floats2half2_rn(o0, o1);
                *(__half2*)(outh + r1 * 256 + col) = __floats2half2_rn(o2, o3);
            }
        }
    }
#undef LNLOAD
}

// ---------------- pack nodes into [LMAX, NG, EMB] (zero padding) ------------
__global__ void pack_kernel(const float* __restrict__ z, const int* __restrict__ batches,
                            float* __restrict__ hp, __half* __restrict__ hph) {
    int l = blockIdx.x;
    int g = blockIdx.y;
    int st = batches[g];
    int len = batches[g + 1] - st;
    long o = ((long)l * NG + g) * EMBD + threadIdx.x;
    float v = (l < len) ? z[(long)(st + l) * EMBD + threadIdx.x] : 0.0f;
    hp[o] = v;
    hph[o] = __float2half(v);
}

// ============ tensor-core flash attention: one block per (graph, head) ======
#define ATT_SMEM (2*320*40*2)

__global__ void __launch_bounds__(128, 4)
attn_mma(const __half* __restrict__ qkv, const int* __restrict__ batches,
         __half* __restrict__ oh) {
    int g = blockIdx.x, h = blockIdx.y;
    int len = batches[g + 1] - batches[g];
    extern __shared__ __half smh[];
    uint32_t sb = (uint32_t)__cvta_generic_to_shared(smh);
    const uint32_t voff = 320u * 40u * 2u;

    int tid = threadIdx.x;
    for (int idx = tid; idx < len * 4; idx += 128) {
        int l = idx >> 2, c = idx & 3;
        const __half* srcK = qkv + ((long)l * NG + g) * 768 + 256 + h * 32 + c * 8;
        uint32_t d = (uint32_t)(l * 40 + c * 8) * 2u;
        CPA16(sb + d, srcK);
        CPA16(sb + voff + d, srcK + 256);
    }
    asm volatile("cp.async.commit_group;");
    asm volatile("cp.async.wait_group 0;");
    __syncthreads();

    const int w = tid >> 5, lane = tid & 31;
    const int r = lane >> 2, t = lane & 3;
    const int nch = (len + 63) >> 6;
    const float scale = 0.17677669529663687f;

    for (int mt = 0; mt < 5; mt++) {
        int m0 = w * 80 + mt * 16;
        uint32_t qf[2][4];
        {
            const __half* q0 = qkv + ((long)(m0 + r) * NG + g) * 768 + h * 32;
            const __half* q1 = q0 + 8L * NG * 768;
#pragma unroll
            for (int ks = 0; ks < 2; ks++) {
                int c0 = ks * 16 + 2 * t;
                qf[ks][0] = *(const uint32_t*)(q0 + c0);
                qf[ks][1] = *(const uint32_t*)(q1 + c0);
                qf[ks][2] = *(const uint32_t*)(q0 + c0 + 8);
                qf[ks][3] = *(const uint32_t*)(q1 + c0 + 8);
            }
        }
        float o_[4][4];
#pragma unroll
        for (int nt = 0; nt < 4; nt++)
#pragma unroll
            for (int j = 0; j < 4; j++) o_[nt][j] = 0.f;
        float mx0 = -3e38f, mx1 = -3e38f, sm0 = 0.f, sm1 = 0.f;

        for (int ch = 0; ch < nch; ch++) {
            int base = ch << 6;
            float s[8][4];
#pragma unroll
            for (int nt = 0; nt < 8; nt++)
#pragma unroll
                for (int j = 0; j < 4; j++) s[nt][j] = 0.f;

#pragma unroll
            for (int ks = 0; ks < 2; ks++) {
#pragma unroll
                for (int np = 0; np < 4; np++) {
                    uint32_t kf[4];
                    int krow = base + np * 16 + (lane & 7) + ((lane >> 4) << 3);
                    int kcol = ks * 16 + (lane & 8);
                    ldsm4(kf, sb + (uint32_t)(krow * 40 + kcol) * 2u);
                    HMMA(s[2 * np],     qf[ks], kf[0], kf[1]);
                    HMMA(s[2 * np + 1], qf[ks], kf[2], kf[3]);
                }
            }

            if (base + 64 > len) {
#pragma unroll
                for (int nt = 0; nt < 8; nt++) {
                    int c0 = base + nt * 8 + 2 * t;
                    if (c0 >= len)     { s[nt][0] = -3e38f; s[nt][2] = -3e38f; }
                    if (c0 + 1 >= len) { s[nt][1] = -3e38f; s[nt][3] = -3e38f; }
                }
            }

            float cm0 = -3e38f, cm1 = -3e38f;
#pragma unroll
            for (int nt = 0; nt < 8; nt++) {
                cm0 = fmaxf(cm0, fmaxf(s[nt][0], s[nt][1]));
                cm1 = fmaxf(cm1, fmaxf(s[nt][2], s[nt][3]));
            }
            cm0 = fmaxf(cm0, __shfl_xor_sync(0xffffffffu, cm0, 1));
            cm0 = fmaxf(cm0, __shfl_xor_sync(0xffffffffu, cm0, 2));
            cm1 = fmaxf(cm1, __shfl_xor_sync(0xffffffffu, cm1, 1));
            cm1 = fmaxf(cm1, __shfl_xor_sync(0xffffffffu, cm1, 2));
            float nm0 = fmaxf(mx0, cm0), nm1 = fmaxf(mx1, cm1);
            float corr0 = __expf((mx0 - nm0) * scale);
            float corr1 = __expf((mx1 - nm1) * scale);
            mx0 = nm0; mx1 = nm1;

            uint32_t pf[4][4];
            float ps0 = 0.f, ps1 = 0.f;
#pragma unroll
            for (int kf = 0; kf < 4; kf++) {
                float p00 = __expf((s[2 * kf][0] - nm0) * scale);
                float p01 = __expf((s[2 * kf][1] - nm0) * scale);
                float p02 = __expf((s[2 * kf][2] - nm1) * scale);
                float p03 = __expf((s[2 * kf][3] - nm1) * scale);
                float p10 = __expf((s[2 * kf + 1][0] - nm0) * scale);
                float p11 = __expf((s[2 * kf + 1][1] - nm0) * scale);
                float p12 = __expf((s[2 * kf + 1][2] - nm1) * scale);
                float p13 = __expf((s[2 * kf + 1][3] - nm1) * scale);
                ps0 += (p00 + p01) + (p10 + p11);
                ps1 += (p02 + p03) + (p12 + p13);
                pf[kf][0] = packh2(p00, p01);
                pf[kf][1] = packh2(p02, p03);
                pf[kf][2] = packh2(p10, p11);
                pf[kf][3] = packh2(p12, p13);
            }
            sm0 = sm0 * corr0 + ps0;
            sm1 = sm1 * corr1 + ps1;
#pragma unroll
            for (int nt = 0; nt < 4; nt++) {
                o_[nt][0] *= corr0; o_[nt][1] *= corr0;
                o_[nt][2] *= corr1; o_[nt][3] *= corr1;
            }

#pragma unroll
            for (int kf = 0; kf < 4; kf++) {
                int k0 = base + kf * 16;
                uint32_t vrow = (uint32_t)((k0 + (lane & 15)) * 40 + ((lane >> 4) << 3));
                uint32_t vf[4];
                ldsm4t(vf, sb + voff + vrow * 2u);
                HMMA(o_[0], pf[kf], vf[0], vf[1]);
                HMMA(o_[1], pf[kf], vf[2], vf[3]);
                ldsm4t(vf, sb + voff + (vrow + 16u) * 2u);
                HMMA(o_[2], pf[kf], vf[0], vf[1]);
                HMMA(o_[3], pf[kf], vf[2], vf[3]);
            }
        }

        float rs0 = sm0 + __shfl_xor_sync(0xffffffffu, sm0, 1);
        rs0 += __shfl_xor_sync(0xffffffffu, rs0, 2);
        float rs1 = sm1 + __shfl_xor_sync(0xffffffffu, sm1, 1);
        rs1 += __shfl_xor_sync(0xffffffffu, rs1, 2);
        float inv0 = 1.f / rs0, inv1 = 1.f / rs1;
        long r0base = ((long)(m0 + r) * NG + g) * 256 + h * 32 + 2 * t;
        long r1base = ((long)(m0 + r + 8) * NG + g) * 256 + h * 32 + 2 * t;
#pragma unroll
        for (int nt = 0; nt < 4; nt++) {
            *(__half2*)(oh + r0base + nt * 8) = __floats2half2_rn(o_[nt][0] * inv0, o_[nt][1] * inv0);
            *(__half2*)(oh + r1base + nt * 8) = __floats2half2_rn(o_[nt][2] * inv1, o_[nt][3] * inv1);
        }
    }
}

// ---------------- host orchestration ----------------------------------------
static void run_hgemm(const __half* A, const __half* Bt, const float* bias, void* C,
                      int M, int N, int K, int lda, int ldc, int relu, int outh) {
    dim3 grid(N / 128, M / 128);
    hgemm<<<grid, 256, HSMEM>>>(A, Bt, bias, C, M, N, K, lda, ldc, relu, outh);
}

static void run_hgemm64(const __half* A, const __half* Bt, const float* bias, void* C,
                        int M, int N, int K, int lda, int ldc, int relu, int outh) {
    dim3 grid(N / 64, M / 128);
    hgemm64<<<grid, 256, HSMEM64>>>(A, Bt, bias, C, M, N, K, lda, ldc, relu, outh);
}

extern "C" void kernel_launch(void* const* d_in, const int* in_sizes, int n_in,
                              void* d_out, int out_size) {
    const float* x       = (const float*)d_in[0];
    const int*   ei      = (const int*)d_in[1];
    const int*   batches = (const int*)d_in[2];

    int wi = 3;
    if (n_in >= 29 && in_sizes[3] == 1) wi = 4;

    const float* sW0  = (const float*)d_in[wi++];
    const float* sWn0 = (const float*)d_in[wi++];
    const float* sb0  = (const float*)d_in[wi++];
    const float* sW1  = (const float*)d_in[wi++];
    const float* sWn1 = (const float*)d_in[wi++];
    const float* sb1  = (const float*)d_in[wi++];
    const float* sW2  = (const float*)d_in[wi++];
    const float* sWn2 = (const float*)d_in[wi++];
    const float* sb2  = (const float*)d_in[wi++];
    const float* Wq   = (const float*)d_in[wi++];
    const float* Wk   = (const float*)d_in[wi++];
    const float* Wv   = (const float*)d_in[wi++];
    const float* bq   = (const float*)d_in[wi++];
    const float* bk   = (const float*)d_in[wi++];
    const float* bv   = (const float*)d_in[wi++];
    const float* Wo   = (const float*)d_in[wi++];
    const float* bo   = (const float*)d_in[wi++];
    const float* ln1g = (const float*)d_in[wi++];
    const float* ln1b = (const float*)d_in[wi++];
    const float* ln2g = (const float*)d_in[wi++];
    const float* ln2b = (const float*)d_in[wi++];
    const float* W1   = (const float*)d_in[wi++];
    const float* b1   = (const float*)d_in[wi++];
    const float* W2   = (const float*)d_in[wi++];
    const float* b2   = (const float*)d_in[wi++];

    int *rowptr, *cnt, *csrc;
    float *comb0, *wsg0, *ha, *hp, *bqkv;
    __half *comb1h, *comb2h, *hph, *qkvh, *oh, *midh;
    __half *wsg1t, *wsg2t, *wqkvt, *wot, *w1t, *w2t;
    cudaGetSymbolAddress((void**)&rowptr, g_rowptr);
    cudaGetSymbolAddress((void**)&cnt,    g_cnt);
    cudaGetSymbolAddress((void**)&csrc,   g_csrc);
    cudaGetSymbolAddress((void**)&comb0,  g_comb0);
    cudaGetSymbolAddress((void**)&wsg0,   g_wsg0);
    cudaGetSymbolAddress((void**)&comb1h, g_comb1h);
    cudaGetSymbolAddress((void**)&comb2h, g_comb2h);
    cudaGetSymbolAddress((void**)&ha,     g_ha);
    cudaGetSymbolAddress((void**)&hp,     g_hp);
    cudaGetSymbolAddress((void**)&hph,    g_hph);
    cudaGetSymbolAddress((void**)&qkvh,   g_qkvh);
    cudaGetSymbolAddress((void**)&oh,     g_oh);
    cudaGetSymbolAddress((void**)&midh,   g_midh);
    cudaGetSymbolAddress((void**)&wsg1t,  g_wsg1t);
    cudaGetSymbolAddress((void**)&wsg2t,  g_wsg2t);
    cudaGetSymbolAddress((void**)&wqkvt,  g_wqkvt);
    cudaGetSymbolAddress((void**)&wot,    g_wot);
    cudaGetSymbolAddress((void**)&w1t,    g_w1t);
    cudaGetSymbolAddress((void**)&w2t,    g_w2t);
    cudaGetSymbolAddress((void**)&bqkv,   g_bqkv);

    cudaFuncSetAttribute(attn_mma, cudaFuncAttributeMaxDynamicSharedMemorySize, ATT_SMEM);
    cudaFuncSetAttribute(hgemm, cudaFuncAttributeMaxDynamicSharedMemorySize, HSMEM);
    cudaFuncSetAttribute(hgemm64, cudaFuncAttributeMaxDynamicSharedMemorySize, HSMEM64);
    cudaFuncSetAttribute(hgemm_ln, cudaFuncAttributeMaxDynamicSharedMemorySize, HSMEM_LN);

    // ---- all weight transposes in one launch ----
    TJobs J;
    const float* srcs[10] = {sW1, sWn1, sW2, sWn2, Wq, Wk, Wv, Wo, W1, W2};
    __half* dsts[10] = {wsg1t, wsg1t + 256, wsg2t, wsg2t + 256,
                        wqkvt, wqkvt + 65536, wqkvt + 131072, wot, w1t, w2t};
    int gxs[10]  = {8, 8, 8, 8, 8, 8, 8, 8, 32, 8};
    int gys[10]  = {8, 8, 8, 8, 8, 8, 8, 8, 8, 32};
    int nzs[10]  = {1, 1, 1, 1, 4, 4, 4, 4, 4, 4};
    int Ns[10]   = {256, 256, 256, 256, 256, 256, 256, 256, 1024, 256};
    int ldds[10] = {512, 512, 512, 512, 256, 256, 256, 256, 256, 1024};
    long slss[10] = {0, 0, 0, 0, 65536, 65536, 65536, 65536, 262144, 262144};
    long dlss[10] = {0, 0, 0, 0, 196608, 196608, 196608, 65536, 262144, 262144};
    int acc = 0;
    for (int i = 0; i < 10; i++) {
        J.src[i] = srcs[i]; J.dst[i] = dsts[i];
        J.gx[i] = gxs[i]; J.gy[i] = gys[i]; J.N[i] = Ns[i]; J.ldd[i] = ldds[i];
        J.sls[i] = slss[i]; J.dls[i] = dlss[i];
        J.base[i] = acc;
        acc += gxs[i] * gys[i] * nzs[i];
    }
    J.base[10] = acc;
    transpose_all<<<acc, dim3(32, 8)>>>(J);
    pack0_kernel<<<32, 256>>>(sW0, sWn0, wsg0);
    pack_bqkv<<<dim3(3, 4), 256>>>(bq, bk, bv, bqkv);

    // ---- CSR build ----
    cudaMemsetAsync(cnt, 0, NN * sizeof(int), 0);
    degi_kernel<<<(NE + 255) / 256, 256>>>(ei, cnt);
    scan_kernel<<<1, 1024>>>(cnt, rowptr);
    fill_kernel<<<(NE + 255) / 256, 256>>>(ei, cnt, csrc);

    // ---- SAGE layer 0 ----
    agg0_kernel<<<NN / 8, 256>>>(x, comb0);
    gemm32h_kernel<<<dim3(256 / BN, NN / BM), 256>>>(comb0, wsg0, sb0, comb1h, 512);

    // ---- SAGE layer 1 ----
    agg_csr_h<<<NN, 128>>>(comb1h);
    run_hgemm64(comb1h, wsg1t, sb1, comb2h, NN, 256, 512, 512, 512, 1, 1);

    // ---- SAGE layer 2 ----
    agg_csr_h<<<NN, 128>>>(comb2h);
    run_hgemm64(comb2h, wsg2t, sb2, ha, NN, 256, 512, 512, 256, 0, 0);

    // ---- pack & pad ----
    pack_kernel<<<dim3(LMAXC, NG), EMBD>>>(ha, batches, hp, hph);

    // ---- 4 transformer layers ----
    for (int l = 0; l < 4; l++) {
        run_hgemm(hph, wqkvt + (long)l * 196608, bqkv + l * 768, qkvh,
                  NTOK, 768, 256, 256, 768, 0, 1);

        attn_mma<<<dim3(NG, NHD), 128, ATT_SMEM>>>(qkvh, batches, oh);

        // Wo GEMM + residual + LN1 fused
        hgemm_ln<<<NTOK / 64, 256, HSMEM_LN>>>(
            oh, wot + (long)l * 65536, bo + l * 256, hp,
            ln1g + l * EMBD, ln1b + l * EMBD, hp, hph, 256);

        run_hgemm(hph, w1t + (long)l * 262144, b1 + l * FFND, midh,
                  NTOK, 1024, 256, 256, 1024, 1, 1);

        // FFN2 GEMM + residual + LN2 fused (final layer -> d_out)
        if (l < 3) {
            hgemm_ln<<<NTOK / 64, 256, HSMEM_LN>>>(
                midh, w2t + (long)l * 262144, b2 + l * 256, hp,
                ln2g + l * EMBD, ln2b + l * EMBD, hp, hph, 1024);
        } else {
            hgemm_ln<<<NTOK / 64, 256, HSMEM_LN>>>(
                midh, w2t + (long)l * 262144, b2 + l * 256, hp,
                ln2g + l * EMBD, ln2b + l * EMBD, (float*)d_out, nullptr, 1024);
        }
    }
}

// round 10
// speedup vs baseline: 6.1436x; 1.0016x over previous
#include <cuda_runtime.h>
#include <cuda_fp16.h>
#include <math.h>
#include <stdint.h>

#define NN   16384
#define NE   262144
#define NG   64
#define LMAXC 320
#define EMBD 256
#define FFND 1024
#define NHD  8
#define DHD  32
#define NTOK (LMAXC*NG)

// ---------------- scratch (device globals; no allocation allowed) ----------
__device__ int   g_rowptr[NN + 1];
__device__ int   g_cnt[NN];
__device__ int   g_csrc[NE];
__device__ int   g_tokmap[NN];
__device__ float g_comb0[NN*32];
__device__ float g_wsg0[32*256];
__device__ __align__(256) __half g_comb1h[NN*512];
__device__ __align__(256) __half g_comb2h[NN*512];
__device__ float g_hp [NTOK*EMBD];
__device__ __align__(256) __half g_hph[NTOK*EMBD];
__device__ __align__(256) __half g_qkvh[NTOK*768];
__device__ __align__(256) __half g_oh[NTOK*EMBD];
__device__ __align__(256) __half g_midh[NTOK*FFND];
__device__ __align__(256) __half g_wsg1t[256*512];
__device__ __align__(256) __half g_wsg2t[256*512];
__device__ __align__(256) __half g_wqkvt[4*768*256];
__device__ __align__(256) __half g_wot[4*256*256];
__device__ __align__(256) __half g_w1t[4*1024*256];
__device__ __align__(256) __half g_w2t[4*256*1024];
__device__ float g_bqkv[4*768];

// =================== CSR build =============================================
__global__ void degi_kernel(const int* __restrict__ ei, int* __restrict__ cnt) {
    int e = blockIdx.x * blockDim.x + threadIdx.x;
    if (e < NE) atomicAdd(&cnt[ei[NE + e]], 1);
}

__global__ void scan_kernel(int* __restrict__ cnt, int* __restrict__ rowptr) {
    __shared__ int wsum[32];
    int t = threadIdx.x;
    int base = t * 16;
    int loc[16];
    int s = 0;
#pragma unroll
    for (int i = 0; i < 16; i++) { loc[i] = s; s += cnt[base + i]; }
    int lane = t & 31, w = t >> 5;
    int inc = s;
#pragma unroll
    for (int off = 1; off < 32; off <<= 1) {
        int v = __shfl_up_sync(0xffffffffu, inc, off);
        if (lane >= off) inc += v;
    }
    if (lane == 31) wsum[w] = inc;
    __syncthreads();
    if (w == 0) {
        int v = wsum[lane];
#pragma unroll
        for (int off = 1; off < 32; off <<= 1) {
            int u = __shfl_up_sync(0xffffffffu, v, off);
            if (lane >= off) v += u;
        }
        wsum[lane] = v;
    }
    __syncthreads();
    int pre = inc - s + (w > 0 ? wsum[w - 1] : 0);
#pragma unroll
    for (int i = 0; i < 16; i++) { rowptr[base + i] = pre + loc[i]; cnt[base + i] = 0; }
    if (t == 1023) rowptr[NN] = pre + s;
}

__global__ void fill_kernel(const int* __restrict__ ei, int* __restrict__ cnt,
                            int* __restrict__ csrc) {
    int e = blockIdx.x * blockDim.x + threadIdx.x;
    if (e >= NE) return;
    int d = ei[NE + e];
    int pos = atomicAdd(&cnt[d], 1);
    csrc[g_rowptr[d] + pos] = ei[e];
}

// node -> packed token row (pos*NG + g)
__global__ void tokmap_kernel(const int* __restrict__ batches, int* __restrict__ map) {
    __shared__ int b[65];
    if (threadIdx.x < 65) b[threadIdx.x] = batches[threadIdx.x];
    __syncthreads();
    int n = blockIdx.x * 256 + threadIdx.x;
    if (n >= NN) return;
    int g = 0;
#pragma unroll 8
    for (int i = 1; i < 64; i++) if (b[i] <= n) g = i;
    map[n] = (n - b[g]) * NG + g;
}

// zero padded token rows of hp/hph
__global__ void zero_pad(const int* __restrict__ batches, float* __restrict__ hp,
                         __half* __restrict__ hph) {
    int l = blockIdx.x;
    int g = blockIdx.y;
    int len = batches[g + 1] - batches[g];
    if (l < len) return;
    long o = ((long)l * NG + g) * EMBD + threadIdx.x;
    hp[o] = 0.0f;
    hph[o] = __float2half(0.0f);
}

// =================== SAGE layer-0 input assembly ===========================
__global__ void agg0_kernel(const float* __restrict__ x, float* __restrict__ comb0) {
    int w = threadIdx.x >> 5;
    int lane = threadIdx.x & 31;
    int node = blockIdx.x * 8 + w;
    if (lane >= 16) return;
    int s0 = g_rowptr[node], s1 = g_rowptr[node + 1];
    float sum = 0.f;
    for (int j = s0; j < s1; j++) sum += x[g_csrc[j] * 16 + lane];
    comb0[node * 32 + lane] = x[node * 16 + lane];
    comb0[node * 32 + 16 + lane] = sum / fmaxf((float)(s1 - s0), 1.f);
}

__global__ void agg_csr_h(__half* __restrict__ feat) {
    int node = blockIdx.x;
    int c = threadIdx.x;
    const __half2* f2 = (const __half2*)feat;
    int s0 = g_rowptr[node], s1 = g_rowptr[node + 1];
    float sx = 0.f, sy = 0.f;
    int j = s0;
    for (; j + 8 <= s1; j += 8) {
        float2 v0 = __half22float2(f2[(long)g_csrc[j]     * 256 + c]);
        float2 v1 = __half22float2(f2[(long)g_csrc[j + 1] * 256 + c]);
        float2 v2 = __half22float2(f2[(long)g_csrc[j + 2] * 256 + c]);
        float2 v3 = __half22float2(f2[(long)g_csrc[j + 3] * 256 + c]);
        float2 v4 = __half22float2(f2[(long)g_csrc[j + 4] * 256 + c]);
        float2 v5 = __half22float2(f2[(long)g_csrc[j + 5] * 256 + c]);
        float2 v6 = __half22float2(f2[(long)g_csrc[j + 6] * 256 + c]);
        float2 v7 = __half22float2(f2[(long)g_csrc[j + 7] * 256 + c]);
        sx += ((v0.x + v1.x) + (v2.x + v3.x)) + ((v4.x + v5.x) + (v6.x + v7.x));
        sy += ((v0.y + v1.y) + (v2.y + v3.y)) + ((v4.y + v5.y) + (v6.y + v7.y));
    }
    for (; j + 2 <= s1; j += 2) {
        float2 a = __half22float2(f2[(long)g_csrc[j] * 256 + c]);
        float2 b = __half22float2(f2[(long)g_csrc[j + 1] * 256 + c]);
        sx += a.x + b.x; sy += a.y + b.y;
    }
    for (; j < s1; j++) {
        float2 a = __half22float2(f2[(long)g_csrc[j] * 256 + c]);
        sx += a.x; sy += a.y;
    }
    float inv = 1.f / fmaxf((float)(s1 - s0), 1.f);
    ((__half2*)feat)[(long)node * 256 + 128 + c] = __floats2half2_rn(sx * inv, sy * inv);
}

// =================== weight packing ========================================
__global__ void pack0_kernel(const float* __restrict__ Ws, const float* __restrict__ Wn,
                             float* __restrict__ out) {
    int k = blockIdx.x;
    int n = threadIdx.x;
    out[k * 256 + n] = (k < 16) ? Ws[k * 256 + n] : Wn[(k - 16) * 256 + n];
}

__global__ void pack_bqkv(const float* __restrict__ bq, const float* __restrict__ bk,
                          const float* __restrict__ bv, float* __restrict__ b) {
    int c = threadIdx.x, s = blockIdx.x, l = blockIdx.y;
    const float* src = (s == 0) ? bq : ((s == 1) ? bk : bv);
    b[l * 768 + s * 256 + c] = src[l * 256 + c];
}

// ---- all 10 weight transposes (fp32 [K,N] -> half [N,K]) in ONE launch ----
struct TJobs {
    const float* src[10];
    __half*      dst[10];
    int gx[10], gy[10], N[10], ldd[10];
    long sls[10], dls[10];
    int base[11];
};

__global__ void transpose_all(TJobs J) {
    __shared__ float t[32][33];
    int b = blockIdx.x;
    int j = 0;
#pragma unroll
    for (int i = 0; i < 10; i++) if (b >= J.base[i + 1]) j = i + 1;
    int local = b - J.base[j];
    int tpz = J.gx[j] * J.gy[j];
    int z = local / tpz, rem = local - z * tpz;
    int ky = rem / J.gx[j], nx = rem - ky * J.gx[j];
    const float* s = J.src[j] + (long)z * J.sls[j];
    __half* d = J.dst[j] + (long)z * J.dls[j];
    int N = J.N[j], ldd = J.ldd[j];
    int k0 = ky * 32, n0 = nx * 32;
    int tx = threadIdx.x, ty = threadIdx.y;
#pragma unroll
    for (int i = 0; i < 32; i += 8)
        t[ty + i][tx] = s[(long)(k0 + ty + i) * N + n0 + tx];
    __syncthreads();
#pragma unroll
    for (int i = 0; i < 32; i += 8)
        d[(long)(n0 + ty + i) * ldd + k0 + tx] = __float2half(t[tx][ty + i]);
}

// ================= fp32 GEMM K=32 for SAGE layer 0, half output =============
#define BM 64
#define BN 64
__global__ void gemm32h_kernel(const float* __restrict__ A, const float* __restrict__ B,
                               const float* __restrict__ bias, __half* __restrict__ C,
                               int ldc) {
    __shared__ float As[16][BM + 1];
    __shared__ float Bs[16][BN];
    int bm = blockIdx.y * BM;
    int bn = blockIdx.x * BN;
    int tid = threadIdx.x;
    int tx = tid & 15;
    int ty = tid >> 4;
    float r[4][4];
#pragma unroll
    for (int i = 0; i < 4; i++)
#pragma unroll
        for (int j = 0; j < 4; j++) r[i][j] = 0.0f;

    for (int k0 = 0; k0 < 32; k0 += 16) {
#pragma unroll
        for (int i = 0; i < 4; i++) {
            int idx = tid + i * 256;
            int rr = idx >> 4, cc = idx & 15;
            As[cc][rr] = A[(long)(bm + rr) * 32 + k0 + cc];
        }
#pragma unroll
        for (int i = 0; i < 4; i++) {
            int idx = tid + i * 256;
            int rr = idx >> 6, cc = idx & 63;
            Bs[rr][cc] = B[(long)(k0 + rr) * 256 + bn + cc];
        }
        __syncthreads();
#pragma unroll
        for (int kk = 0; kk < 16; kk++) {
            float a[4], b[4];
#pragma unroll
            for (int i = 0; i < 4; i++) a[i] = As[kk][ty * 4 + i];
#pragma unroll
            for (int j = 0; j < 4; j++) b[j] = Bs[kk][tx * 4 + j];
#pragma unroll
            for (int i = 0; i < 4; i++)
#pragma unroll
                for (int j = 0; j < 4; j++) r[i][j] = fmaf(a[i], b[j], r[i][j]);
        }
        __syncthreads();
    }
#pragma unroll
    for (int i = 0; i < 4; i++) {
        long row = bm + ty * 4 + i;
        __half2* C2 = (__half2*)(C + row * ldc + bn + tx * 4);
#pragma unroll
        for (int j = 0; j < 4; j += 2) {
            int col = bn + tx * 4 + j;
            float v0 = fmaxf(r[i][j] + bias[col], 0.f);
            float v1 = fmaxf(r[i][j + 1] + bias[col + 1], 0.f);
            C2[j >> 1] = __floats2half2_rn(v0, v1);
        }
    }
}

// ================= FP16 tensor-core GEMM common helpers ======================
#define HSTR 72
#define HBUF (128*HSTR)
#define HSMEM (4*HBUF*2)

#define CPA16(dst, src) asm volatile("cp.async.cg.shared.global [%0], [%1], 16;" :: "r"(dst), "l"(src))

__device__ __forceinline__ void ldsm4(uint32_t (&r)[4], uint32_t addr) {
    asm volatile("ldmatrix.sync.aligned.m8n8.x4.shared.b16 {%0,%1,%2,%3}, [%4];"
                 : "=r"(r[0]), "=r"(r[1]), "=r"(r[2]), "=r"(r[3]) : "r"(addr));
}
__device__ __forceinline__ void ldsm2(uint32_t (&r)[2], uint32_t addr) {
    asm volatile("ldmatrix.sync.aligned.m8n8.x2.shared.b16 {%0,%1}, [%2];"
                 : "=r"(r[0]), "=r"(r[1]) : "r"(addr));
}
__device__ __forceinline__ void ldsm4t(uint32_t (&r)[4], uint32_t addr) {
    asm volatile("ldmatrix.sync.aligned.m8n8.x4.trans.shared.b16 {%0,%1,%2,%3}, [%4];"
                 : "=r"(r[0]), "=r"(r[1]), "=r"(r[2]), "=r"(r[3]) : "r"(addr));
}

#define HMMA(d, a, b0, b1) asm volatile( \
    "mma.sync.aligned.m16n8k16.row.col.f32.f16.f16.f32 " \
    "{%0,%1,%2,%3}, {%4,%5,%6,%7}, {%8,%9}, {%0,%1,%2,%3};" \
    : "+f"(d[0]), "+f"(d[1]), "+f"(d[2]), "+f"(d[3]) \
    : "r"(a[0]), "r"(a[1]), "r"(a[2]), "r"(a[3]), "r"(b0), "r"(b1))

__device__ __forceinline__ uint32_t packh2(float a, float b) {
    __half2 h = __floats2half2_rn(a, b);
    return *(uint32_t*)&h;
}

// ================= hgemm: 128x128 tile (for N=768/1024 GEMMs) ===============
__global__ void __launch_bounds__(256, 2)
hgemm(const __half* __restrict__ A, const __half* __restrict__ Bt,
      const float* __restrict__ bias, void* __restrict__ Cv,
      int M, int N, int K, int lda, int ldc, int relu, int outh) {
    extern __shared__ __half shh[];
    const int tid  = threadIdx.x;
    const int lane = tid & 31;
    const int wid  = tid >> 5;
    const int wr   = wid >> 2;
    const int wc   = wid & 3;
    const int bm   = blockIdx.y * 128;
    const int bn   = blockIdx.x * 128;

    uint32_t sbase = (uint32_t)__cvta_generic_to_shared(shh);

    float acc[4][4][4];
#pragma unroll
    for (int mt = 0; mt < 4; mt++)
#pragma unroll
        for (int nt = 0; nt < 4; nt++)
#pragma unroll
            for (int r = 0; r < 4; r++) acc[mt][nt][r] = 0.0f;

#define HLOAD(buf, k0)                                                          \
    do {                                                                        \
        _Pragma("unroll")                                                       \
        for (int i = 0; i < 4; i++) {                                           \
            int idx = tid + i * 256;                                            \
            int r = idx >> 3, c = (idx & 7) << 3;                               \
            CPA16(sbase + (uint32_t)((buf) * HBUF + r * HSTR + c) * 2u,         \
                  A + (long)(bm + r) * lda + (k0) + c);                         \
        }                                                                       \
        _Pragma("unroll")                                                       \
        for (int i = 0; i < 4; i++) {                                           \
            int idx = tid + i * 256;                                            \
            int r = idx >> 3, c = (idx & 7) << 3;                               \
            CPA16(sbase + (uint32_t)((2 + (buf)) * HBUF + r * HSTR + c) * 2u,   \
                  Bt + (long)(bn + r) * K + (k0) + c);                          \
        }                                                                       \
        asm volatile("cp.async.commit_group;");                                 \
    } while (0)

    const int nk = K >> 6;
    HLOAD(0, 0);

    const int arow = wr * 64 + (lane & 15);
    const int ach  = (lane >> 4) << 3;
    const int brow = wc * 32 + (lane & 7);
    const int bch  = ((lane >> 3) & 1) << 3;

    for (int it = 0; it < nk; it++) {
        int cur = it & 1;
        if (it + 1 < nk) {
            HLOAD(cur ^ 1, (it + 1) << 6);
            asm volatile("cp.async.wait_group 1;");
        } else {
            asm volatile("cp.async.wait_group 0;");
        }
        __syncthreads();

        uint32_t aB = sbase + (uint32_t)(cur * HBUF) * 2u;
        uint32_t bB = sbase + (uint32_t)((2 + cur) * HBUF) * 2u;

#pragma unroll
        for (int ks = 0; ks < 4; ks++) {
            uint32_t af[4][4], bf[4][2];
#pragma unroll
            for (int mt = 0; mt < 4; mt++)
                ldsm4(af[mt], aB + (uint32_t)((arow + mt * 16) * HSTR + ks * 16 + ach) * 2u);
#pragma unroll
            for (int nt = 0; nt < 4; nt++)
                ldsm2(bf[nt], bB + (uint32_t)((brow + nt * 8) * HSTR + ks * 16 + bch) * 2u);
#pragma unroll
            for (int mt = 0; mt < 4; mt++)
#pragma unroll
                for (int nt = 0; nt < 4; nt++)
                    HMMA(acc[mt][nt], af[mt], bf[nt][0], bf[nt][1]);
        }
        __syncthreads();
    }

#pragma unroll
    for (int mt = 0; mt < 4; mt++) {
        int row = bm + wr * 64 + mt * 16 + (lane >> 2);
#pragma unroll
        for (int nt = 0; nt < 4; nt++) {
            int col = bn + wc * 32 + nt * 8 + ((lane & 3) << 1);
            float b0 = bias[col], b1 = bias[col + 1];
            float v0 = acc[mt][nt][0] + b0, v1 = acc[mt][nt][1] + b1;
            float v2 = acc[mt][nt][2] + b0, v3 = acc[mt][nt][3] + b1;
            if (relu) { v0 = fmaxf(v0, 0.f); v1 = fmaxf(v1, 0.f);
                        v2 = fmaxf(v2, 0.f); v3 = fmaxf(v3, 0.f); }
            if (outh) {
                __half2* C2 = (__half2*)Cv;
                C2[((long)row * ldc + col) >> 1]       = __floats2half2_rn(v0, v1);
                C2[((long)(row + 8) * ldc + col) >> 1] = __floats2half2_rn(v2, v3);
            } else {
                float* C = (float*)Cv;
                long i0 = (long)row * ldc + col;
                long i1 = i0 + 8L * ldc;
                C[i0] = v0; C[i0 + 1] = v1; C[i1] = v2; C[i1 + 1] = v3;
            }
        }
    }
#undef HLOAD
}

// ========== hgemm64: 128x64 tile (SAGE layers, N=256) ========================
// Optional rowmap: epilogue scatters rows through map, writing fp32 (outf) and
// half (Cv) — used by SAGE layer 2 to write the packed transformer input.
#define A64BUF (128*HSTR)
#define B64BUF (64*HSTR)
#define HSMEM64 ((2*A64BUF + 2*B64BUF)*2)

__global__ void __launch_bounds__(256, 2)
hgemm64(const __half* __restrict__ A, const __half* __restrict__ Bt,
        const float* __restrict__ bias, void* __restrict__ Cv,
        int M, int N, int K, int lda, int ldc, int relu, int outh,
        const int* __restrict__ rowmap, float* __restrict__ outf) {
    extern __shared__ __half shh[];
    const int tid  = threadIdx.x;
    const int lane = tid & 31;
    const int wid  = tid >> 5;
    const int wr   = wid >> 1;
    const int wc   = wid & 1;
    const int bm   = blockIdx.y * 128;
    const int bn   = blockIdx.x * 64;

    uint32_t sbase = (uint32_t)__cvta_generic_to_shared(shh);

    float acc[2][4][4];
#pragma unroll
    for (int mt = 0; mt < 2; mt++)
#pragma unroll
        for (int nt = 0; nt < 4; nt++)
#pragma unroll
            for (int r = 0; r < 4; r++) acc[mt][nt][r] = 0.0f;

#define HLOAD64(buf, k0)                                                        \
    do {                                                                        \
        _Pragma("unroll")                                                       \
        for (int i = 0; i < 4; i++) {                                           \
            int idx = tid + i * 256;                                            \
            int r = idx >> 3, c = (idx & 7) << 3;                               \
            CPA16(sbase + (uint32_t)((buf) * A64BUF + r * HSTR + c) * 2u,       \
                  A + (long)(bm + r) * lda + (k0) + c);                         \
        }                                                                       \
        _Pragma("unroll")                                                       \
        for (int i = 0; i < 2; i++) {                                           \
            int idx = tid + i * 256;                                            \
            int r = idx >> 3, c = (idx & 7) << 3;                               \
            CPA16(sbase + (uint32_t)(2 * A64BUF + (buf) * B64BUF + r * HSTR + c) * 2u, \
                  Bt + (long)(bn + r) * K + (k0) + c);                          \
        }                                                                       \
        asm volatile("cp.async.commit_group;");                                 \
    } while (0)

    const int nk = K >> 6;
    HLOAD64(0, 0);

    const int arow = wr * 32 + (lane & 15);
    const int ach  = (lane >> 4) << 3;
    const int brow = wc * 32 + (lane & 7);
    const int bch  = ((lane >> 3) & 1) << 3;

    for (int it = 0; it < nk; it++) {
        int cur = it & 1;
        if (it + 1 < nk) {
            HLOAD64(cur ^ 1, (it + 1) << 6);
            asm volatile("cp.async.wait_group 1;");
        } else {
            asm volatile("cp.async.wait_group 0;");
        }
        __syncthreads();

        uint32_t aB = sbase + (uint32_t)(cur * A64BUF) * 2u;
        uint32_t bB = sbase + (uint32_t)(2 * A64BUF + cur * B64BUF) * 2u;

#pragma unroll
        for (int ks = 0; ks < 4; ks++) {
            uint32_t af[2][4], bf[4][2];
#pragma unroll
            for (int mt = 0; mt < 2; mt++)
                ldsm4(af[mt], aB + (uint32_t)((arow + mt * 16) * HSTR + ks * 16 + ach) * 2u);
#pragma unroll
            for (int nt = 0; nt < 4; nt++)
                ldsm2(bf[nt], bB + (uint32_t)((brow + nt * 8) * HSTR + ks * 16 + bch) * 2u);
#pragma unroll
            for (int mt = 0; mt < 2; mt++)
#pragma unroll
                for (int nt = 0; nt < 4; nt++)
                    HMMA(acc[mt][nt], af[mt], bf[nt][0], bf[nt][1]);
        }
        __syncthreads();
    }

#pragma unroll
    for (int mt = 0; mt < 2; mt++) {
        int row = bm + wr * 32 + mt * 16 + (lane >> 2);
        long orow0 = rowmap ? (long)rowmap[row]     : (long)row;
        long orow1 = rowmap ? (long)rowmap[row + 8] : (long)(row + 8);
#pragma unroll
        for (int nt = 0; nt < 4; nt++) {
            int col = bn + wc * 32 + nt * 8 + ((lane & 3) << 1);
            float b0 = bias[col], b1 = bias[col + 1];
            float v0 = acc[mt][nt][0] + b0, v1 = acc[mt][nt][1] + b1;
            float v2 = acc[mt][nt][2] + b0, v3 = acc[mt][nt][3] + b1;
            if (relu) { v0 = fmaxf(v0, 0.f); v1 = fmaxf(v1, 0.f);
                        v2 = fmaxf(v2, 0.f); v3 = fmaxf(v3, 0.f); }
            if (outf) {
                *(float2*)(outf + orow0 * ldc + col) = make_float2(v0, v1);
                *(float2*)(outf + orow1 * ldc + col) = make_float2(v2, v3);
            }
            if (outh) {
                __half2* C2 = (__half2*)Cv;
                C2[(orow0 * ldc + col) >> 1] = __floats2half2_rn(v0, v1);
                C2[(orow1 * ldc + col) >> 1] = __floats2half2_rn(v2, v3);
            }
        }
    }
#undef HLOAD64
}

// ===== hgemm_ln: 64x256 tile GEMM + bias + residual + LayerNorm epilogue ====
#define LNA (64*HSTR)
#define LNB (256*HSTR)
#define HSMEM_LN ((2*LNA + 2*LNB)*2)

__global__ void __launch_bounds__(256, 2)
hgemm_ln(const __half* __restrict__ A, const __half* __restrict__ Bt,
         const float* __restrict__ bias, const float* __restrict__ resid,
         const float* __restrict__ gamma, const float* __restrict__ beta,
         float* __restrict__ outf, __half* __restrict__ outh, int K) {
    extern __shared__ __half shh[];
    __shared__ float red[64][4];
    const int tid  = threadIdx.x;
    const int lane = tid & 31;
    const int wid  = tid >> 5;
    const int wr   = wid >> 2;
    const int wc   = wid & 3;
    const long bm  = (long)blockIdx.x * 64;

    uint32_t sbase = (uint32_t)__cvta_generic_to_shared(shh);

    float acc[2][8][4];
#pragma unroll
    for (int mt = 0; mt < 2; mt++)
#pragma unroll
        for (int nt = 0; nt < 8; nt++)
#pragma unroll
            for (int r = 0; r < 4; r++) acc[mt][nt][r] = 0.0f;

#define LNLOAD(buf, k0)                                                         \
    do {                                                                        \
        _Pragma("unroll")                                                       \
        for (int i = 0; i < 2; i++) {                                           \
            int idx = tid + i * 256;                                            \
            int r = idx >> 3, c = (idx & 7) << 3;                               \
            CPA16(sbase + (uint32_t)((buf) * LNA + r * HSTR + c) * 2u,          \
                  A + (bm + r) * K + (k0) + c);                                 \
        }                                                                       \
        _Pragma("unroll")                                                       \
        for (int i = 0; i < 8; i++) {                                           \
            int idx = tid + i * 256;                                            \
            int r = idx >> 3, c = (idx & 7) << 3;                               \
            CPA16(sbase + (uint32_t)(2 * LNA + (buf) * LNB + r * HSTR + c) * 2u,\
                  Bt + (long)r * K + (k0) + c);                                 \
        }                                                                       \
        asm volatile("cp.async.commit_group;");                                 \
    } while (0)

    const int nk = K >> 6;
    LNLOAD(0, 0);

    const int arowb = wr * 32 + (lane & 15);
    const int ach   = (lane >> 4) << 3;
    const int browb = wc * 64 + (lane & 7) + ((lane >> 4) << 3);
    const int bch   = lane & 8;

    for (int it = 0; it < nk; it++) {
        int cur = it & 1;
        if (it + 1 < nk) {
            LNLOAD(cur ^ 1, (it + 1) << 6);
            asm volatile("cp.async.wait_group 1;");
        } else {
            asm volatile("cp.async.wait_group 0;");
        }
        __syncthreads();

        uint32_t aB = sbase + (uint32_t)(cur * LNA) * 2u;
        uint32_t bB = sbase + (uint32_t)(2 * LNA + cur * LNB) * 2u;

#pragma unroll
        for (int ks = 0; ks < 4; ks++) {
            uint32_t af[2][4];
#pragma unroll
            for (int mt = 0; mt < 2; mt++)
                ldsm4(af[mt], aB + (uint32_t)((arowb + mt * 16) * HSTR + ks * 16 + ach) * 2u);
#pragma unroll
            for (int np = 0; np < 4; np++) {
                uint32_t kf[4];
                ldsm4(kf, bB + (uint32_t)((browb + np * 16) * HSTR + ks * 16 + bch) * 2u);
#pragma unroll
                for (int mt = 0; mt < 2; mt++) {
                    HMMA(acc[mt][2 * np],     af[mt], kf[0], kf[1]);
                    HMMA(acc[mt][2 * np + 1], af[mt], kf[2], kf[3]);
                }
            }
        }
        __syncthreads();
    }

    const int q = lane >> 2, t2 = (lane & 3) << 1;
#pragma unroll
    for (int mt = 0; mt < 2; mt++) {
        long r0 = bm + wr * 32 + mt * 16 + q;
        long r1 = r0 + 8;
        float s0 = 0.f, s1 = 0.f;
#pragma unroll
        for (int nt = 0; nt < 8; nt++) {
            int col = wc * 64 + nt * 8 + t2;
            float b0 = bias[col], b1 = bias[col + 1];
            float2 q0 = *(const float2*)(resid + r0 * 256 + col);
            float2 q1 = *(const float2*)(resid + r1 * 256 + col);
            acc[mt][nt][0] += b0 + q0.x; acc[mt][nt][1] += b1 + q0.y;
            acc[mt][nt][2] += b0 + q1.x; acc[mt][nt][3] += b1 + q1.y;
            s0 += acc[mt][nt][0] + acc[mt][nt][1];
            s1 += acc[mt][nt][2] + acc[mt][nt][3];
        }
        s0 += __shfl_xor_sync(0xffffffffu, s0, 1);
        s0 += __shfl_xor_sync(0xffffffffu, s0, 2);
        s1 += __shfl_xor_sync(0xffffffffu, s1, 1);
        s1 += __shfl_xor_sync(0xffffffffu, s1, 2);
        int lr = wr * 32 + mt * 16 + q;
        if ((lane & 3) == 0) { red[lr][wc] = s0; red[lr + 8][wc] = s1; }
    }
    __syncthreads();
    float mean[2][2];
#pragma unroll
    for (int mt = 0; mt < 2; mt++) {
        int lr = wr * 32 + mt * 16 + q;
        mean[mt][0] = (red[lr][0] + red[lr][1] + red[lr][2] + red[lr][3]) * (1.0f / EMBD);
        mean[mt][1] = (red[lr + 8][0] + red[lr + 8][1] + red[lr + 8][2] + red[lr + 8][3]) * (1.0f / EMBD);
    }
    __syncthreads();
#pragma unroll
    for (int mt = 0; mt < 2; mt++) {
        float s0 = 0.f, s1 = 0.f;
#pragma unroll
        for (int nt = 0; nt < 8; nt++) {
            float d0 = acc[mt][nt][0] - mean[mt][0];
            float d1 = acc[mt][nt][1] - mean[mt][0];
            float d2 = acc[mt][nt][2] - mean[mt][1];
            float d3 = acc[mt][nt][3] - mean[mt][1];
            s0 += d0 * d0 + d1 * d1;
            s1 += d2 * d2 + d3 * d3;
        }
        s0 += __shfl_xor_sync(0xffffffffu, s0, 1);
        s0 += __shfl_xor_sync(0xffffffffu, s0, 2);
        s1 += __shfl_xor_sync(0xffffffffu, s1, 1);
        s1 += __shfl_xor_sync(0xffffffffu, s1, 2);
        int lr = wr * 32 + mt * 16 + q;
        if ((lane & 3) == 0) { red[lr][wc] = s0; red[lr + 8][wc] = s1; }
    }
    __syncthreads();
#pragma unroll
    for (int mt = 0; mt < 2; mt++) {
        int lr = wr * 32 + mt * 16 + q;
        float rstd0 = rsqrtf((red[lr][0] + red[lr][1] + red[lr][2] + red[lr][3]) * (1.0f / EMBD) + 1e-5f);
        float rstd1 = rsqrtf((red[lr + 8][0] + red[lr + 8][1] + red[lr + 8][2] + red[lr + 8][3]) * (1.0f / EMBD) + 1e-5f);
        long r0 = bm + lr;
        long r1 = r0 + 8;
#pragma unroll
        for (int nt = 0; nt < 8; nt++) {
            int col = wc * 64 + nt * 8 + t2;
            float g0 = gamma[col], g1 = gamma[col + 1];
            float e0 = beta[col],  e1 = beta[col + 1];
            float o0 = (acc[mt][nt][0] - mean[mt][0]) * rstd0 * g0 + e0;
            float o1 = (acc[mt][nt][1] - mean[mt][0]) * rstd0 * g1 + e1;
            float o2 = (acc[mt][nt][2] - mean[mt][1]) * rstd1 * g0 + e0;
            float o3 = (acc[mt][nt][3] - mean[mt][1]) * rstd1 * g1 + e1;
            *(float2*)(outf + r0 * 256 + col) = make_float2(o0, o1);
            *(float2*)(outf + r1 * 256 + col) = make_float2(o2, o3);
            if (outh) {
                *(__half2*)(outh + r0 * 256 + col) = __floats2half2_rn(o0, o1);
                *(__half2*)(outh + r1 * 256 + col) = __floats2half2_rn(o2, o3);
            }
        }
    }
#undef LNLOAD
}

// ============ tensor-core flash attention: one block per (graph, head) ======
#define ATT_SMEM (2*320*40*2)

__global__ void __launch_bounds__(128, 4)
attn_mma(const __half* __restrict__ qkv, const int* __restrict__ batches,
         __half* __restrict__ oh) {
    int g = blockIdx.x, h = blockIdx.y;
    int len = batches[g + 1] - batches[g];
    extern __shared__ __half smh[];
    uint32_t sb = (uint32_t)__cvta_generic_to_shared(smh);
    const uint32_t voff = 320u * 40u * 2u;

    int tid = threadIdx.x;
    for (int idx = tid; idx < len * 4; idx += 128) {
        int l = idx >> 2, c = idx & 3;
        const __half* srcK = qkv + ((long)l * NG + g) * 768 + 256 + h * 32 + c * 8;
        uint32_t d = (uint32_t)(l * 40 + c * 8) * 2u;
        CPA16(sb + d, srcK);
        CPA16(sb + voff + d, srcK + 256);
    }
    asm volatile("cp.async.commit_group;");
    asm volatile("cp.async.wait_group 0;");
    __syncthreads();

    const int w = tid >> 5, lane = tid & 31;
    const int r = lane >> 2, t = lane & 3;
    const int nch = (len + 63) >> 6;
    const float scale = 0.17677669529663687f;

    for (int mt = 0; mt < 5; mt++) {
        int m0 = w * 80 + mt * 16;
        uint32_t qf[2][4];
        {
            const __half* q0 = qkv + ((long)(m0 + r) * NG + g) * 768 + h * 32;
            const __half* q1 = q0 + 8L * NG * 768;
#pragma unroll
            for (int ks = 0; ks < 2; ks++) {
                int c0 = ks * 16 + 2 * t;
                qf[ks][0] = *(const uint32_t*)(q0 + c0);
                qf[ks][1] = *(const uint32_t*)(q1 + c0);
                qf[ks][2] = *(const uint32_t*)(q0 + c0 + 8);
                qf[ks][3] = *(const uint32_t*)(q1 + c0 + 8);
            }
        }
        float o_[4][4];
#pragma unroll
        for (int nt = 0; nt < 4; nt++)
#pragma unroll
            for (int j = 0; j < 4; j++) o_[nt][j] = 0.f;
        float mx0 = -3e38f, mx1 = -3e38f, sm0 = 0.f, sm1 = 0.f;

        for (int ch = 0; ch < nch; ch++) {
            int base = ch << 6;
            float s[8][4];
#pragma unroll
            for (int nt = 0; nt < 8; nt++)
#pragma unroll
                for (int j = 0; j < 4; j++) s[nt][j] = 0.f;

#pragma unroll
            for (int ks = 0; ks < 2; ks++) {
#pragma unroll
                for (int np = 0; np < 4; np++) {
                    uint32_t kf[4];
                    int krow = base + np * 16 + (lane & 7) + ((lane >> 4) << 3);
                    int kcol = ks * 16 + (lane & 8);
                    ldsm4(kf, sb + (uint32_t)(krow * 40 + kcol) * 2u);
                    HMMA(s[2 * np],     qf[ks], kf[0], kf[1]);
                    HMMA(s[2 * np + 1], qf[ks], kf[2], kf[3]);
                }
            }

            if (base + 64 > len) {
#pragma unroll
                for (int nt = 0; nt < 8; nt++) {
                    int c0 = base + nt * 8 + 2 * t;
                    if (c0 >= len)     { s[nt][0] = -3e38f; s[nt][2] = -3e38f; }
                    if (c0 + 1 >= len) { s[nt][1] = -3e38f; s[nt][3] = -3e38f; }
                }
            }

            float cm0 = -3e38f, cm1 = -3e38f;
#pragma unroll
            for (int nt = 0; nt < 8; nt++) {
                cm0 = fmaxf(cm0, fmaxf(s[nt][0], s[nt][1]));
                cm1 = fmaxf(cm1, fmaxf(s[nt][2], s[nt][3]));
            }
            cm0 = fmaxf(cm0, __shfl_xor_sync(0xffffffffu, cm0, 1));
            cm0 = fmaxf(cm0, __shfl_xor_sync(0xffffffffu, cm0, 2));
            cm1 = fmaxf(cm1, __shfl_xor_sync(0xffffffffu, cm1, 1));
            cm1 = fmaxf(cm1, __shfl_xor_sync(0xffffffffu, cm1, 2));
            float nm0 = fmaxf(mx0, cm0), nm1 = fmaxf(mx1, cm1);
            float corr0 = __expf((mx0 - nm0) * scale);
            float corr1 = __expf((mx1 - nm1) * scale);
            mx0 = nm0; mx1 = nm1;

            uint32_t pf[4][4];
            float ps0 = 0.f, ps1 = 0.f;
#pragma unroll
            for (int kf = 0; kf < 4; kf++) {
                float p00 = __expf((s[2 * kf][0] - nm0) * scale);
                float p01 = __expf((s[2 * kf][1] - nm0) * scale);
                float p02 = __expf((s[2 * kf][2] - nm1) * scale);
                float p03 = __expf((s[2 * kf][3] - nm1) * scale);
                float p10 = __expf((s[2 * kf + 1][0] - nm0) * scale);
                float p11 = __expf((s[2 * kf + 1][1] - nm0) * scale);
                float p12 = __expf((s[2 * kf + 1][2] - nm1) * scale);
                float p13 = __expf((s[2 * kf + 1][3] - nm1) * scale);
                ps0 += (p00 + p01) + (p10 + p11);
                ps1 += (p02 + p03) + (p12 + p13);
                pf[kf][0] = packh2(p00, p01);
                pf[kf][1] = packh2(p02, p03);
                pf[kf][2] = packh2(p10, p11);
                pf[kf][3] = packh2(p12, p13);
            }
            sm0 = sm0 * corr0 + ps0;
            sm1 = sm1 * corr1 + ps1;
#pragma unroll
            for (int nt = 0; nt < 4; nt++) {
                o_[nt][0] *= corr0; o_[nt][1] *= corr0;
                o_[nt][2] *= corr1; o_[nt][3] *= corr1;
            }

#pragma unroll
            for (int kf = 0; kf < 4; kf++) {
                int k0 = base + kf * 16;
                uint32_t vrow = (uint32_t)((k0 + (lane & 15)) * 40 + ((lane >> 4) << 3));
                uint32_t vf[4];
                ldsm4t(vf, sb + voff + vrow * 2u);
                HMMA(o_[0], pf[kf], vf[0], vf[1]);
                HMMA(o_[1], pf[kf], vf[2], vf[3]);
                ldsm4t(vf, sb + voff + (vrow + 16u) * 2u);
                HMMA(o_[2], pf[kf], vf[0], vf[1]);
                HMMA(o_[3], pf[kf], vf[2], vf[3]);
            }
        }

        float rs0 = sm0 + __shfl_xor_sync(0xffffffffu, sm0, 1);
        rs0 += __shfl_xor_sync(0xffffffffu, rs0, 2);
        float rs1 = sm1 + __shfl_xor_sync(0xffffffffu, sm1, 1);
        rs1 += __shfl_xor_sync(0xffffffffu, rs1, 2);
        float inv0 = 1.f / rs0, inv1 = 1.f / rs1;
        long r0base = ((long)(m0 + r) * NG + g) * 256 + h * 32 + 2 * t;
        long r1base = ((long)(m0 + r + 8) * NG + g) * 256 + h * 32 + 2 * t;
#pragma unroll
        for (int nt = 0; nt < 4; nt++) {
            *(__half2*)(oh + r0base + nt * 8) = __floats2half2_rn(o_[nt][0] * inv0, o_[nt][1] * inv0);
            *(__half2*)(oh + r1base + nt * 8) = __floats2half2_rn(o_[nt][2] * inv1, o_[nt][3] * inv1);
        }
    }
}

// ---------------- host orchestration ----------------------------------------
static void run_hgemm(const __half* A, const __half* Bt, const float* bias, void* C,
                      int M, int N, int K, int lda, int ldc, int relu, int outh) {
    dim3 grid(N / 128, M / 128);
    hgemm<<<grid, 256, HSMEM>>>(A, Bt, bias, C, M, N, K, lda, ldc, relu, outh);
}

static void run_hgemm64(const __half* A, const __half* Bt, const float* bias, void* C,
                        int M, int N, int K, int lda, int ldc, int relu, int outh,
                        const int* rowmap, float* outf) {
    dim3 grid(N / 64, M / 128);
    hgemm64<<<grid, 256, HSMEM64>>>(A, Bt, bias, C, M, N, K, lda, ldc, relu, outh,
                                    rowmap, outf);
}

extern "C" void kernel_launch(void* const* d_in, const int* in_sizes, int n_in,
                              void* d_out, int out_size) {
    const float* x       = (const float*)d_in[0];
    const int*   ei      = (const int*)d_in[1];
    const int*   batches = (const int*)d_in[2];

    int wi = 3;
    if (n_in >= 29 && in_sizes[3] == 1) wi = 4;

    const float* sW0  = (const float*)d_in[wi++];
    const float* sWn0 = (const float*)d_in[wi++];
    const float* sb0  = (const float*)d_in[wi++];
    const float* sW1  = (const float*)d_in[wi++];
    const float* sWn1 = (const float*)d_in[wi++];
    const float* sb1  = (const float*)d_in[wi++];
    const float* sW2  = (const float*)d_in[wi++];
    const float* sWn2 = (const float*)d_in[wi++];
    const float* sb2  = (const float*)d_in[wi++];
    const float* Wq   = (const float*)d_in[wi++];
    const float* Wk   = (const float*)d_in[wi++];
    const float* Wv   = (const float*)d_in[wi++];
    const float* bq   = (const float*)d_in[wi++];
    const float* bk   = (const float*)d_in[wi++];
    const float* bv   = (const float*)d_in[wi++];
    const float* Wo   = (const float*)d_in[wi++];
    const float* bo   = (const float*)d_in[wi++];
    const float* ln1g = (const float*)d_in[wi++];
    const float* ln1b = (const float*)d_in[wi++];
    const float* ln2g = (const float*)d_in[wi++];
    const float* ln2b = (const float*)d_in[wi++];
    const float* W1   = (const float*)d_in[wi++];
    const float* b1   = (const float*)d_in[wi++];
    const float* W2   = (const float*)d_in[wi++];
    const float* b2   = (const float*)d_in[wi++];

    int *rowptr, *cnt, *csrc, *tokmap;
    float *comb0, *wsg0, *hp, *bqkv;
    __half *comb1h, *comb2h, *hph, *qkvh, *oh, *midh;
    __half *wsg1t, *wsg2t, *wqkvt, *wot, *w1t, *w2t;
    cudaGetSymbolAddress((void**)&rowptr, g_rowptr);
    cudaGetSymbolAddress((void**)&cnt,    g_cnt);
    cudaGetSymbolAddress((void**)&csrc,   g_csrc);
    cudaGetSymbolAddress((void**)&tokmap, g_tokmap);
    cudaGetSymbolAddress((void**)&comb0,  g_comb0);
    cudaGetSymbolAddress((void**)&wsg0,   g_wsg0);
    cudaGetSymbolAddress((void**)&comb1h, g_comb1h);
    cudaGetSymbolAddress((void**)&comb2h, g_comb2h);
    cudaGetSymbolAddress((void**)&hp,     g_hp);
    cudaGetSymbolAddress((void**)&hph,    g_hph);
    cudaGetSymbolAddress((void**)&qkvh,   g_qkvh);
    cudaGetSymbolAddress((void**)&oh,     g_oh);
    cudaGetSymbolAddress((void**)&midh,   g_midh);
    cudaGetSymbolAddress((void**)&wsg1t,  g_wsg1t);
    cudaGetSymbolAddress((void**)&wsg2t,  g_wsg2t);
    cudaGetSymbolAddress((void**)&wqkvt,  g_wqkvt);
    cudaGetSymbolAddress((void**)&wot,    g_wot);
    cudaGetSymbolAddress((void**)&w1t,    g_w1t);
    cudaGetSymbolAddress((void**)&w2t,    g_w2t);
    cudaGetSymbolAddress((void**)&bqkv,   g_bqkv);

    cudaFuncSetAttribute(attn_mma, cudaFuncAttributeMaxDynamicSharedMemorySize, ATT_SMEM);
    cudaFuncSetAttribute(hgemm, cudaFuncAttributeMaxDynamicSharedMemorySize, HSMEM);
    cudaFuncSetAttribute(hgemm64, cudaFuncAttributeMaxDynamicSharedMemorySize, HSMEM64);
    cudaFuncSetAttribute(hgemm_ln, cudaFuncAttributeMaxDynamicSharedMemorySize, HSMEM_LN);

    // ---- all weight transposes in one launch ----
    TJobs J;
    const float* srcs[10] = {sW1, sWn1, sW2, sWn2, Wq, Wk, Wv, Wo, W1, W2};
    __half* dsts[10] = {wsg1t, wsg1t + 256, wsg2t, wsg2t + 256,
                        wqkvt, wqkvt + 65536, wqkvt + 131072, wot, w1t, w2t};
    int gxs[10]  = {8, 8, 8, 8, 8, 8, 8, 8, 32, 8};
    int gys[10]  = {8, 8, 8, 8, 8, 8, 8, 8, 8, 32};
    int nzs[10]  = {1, 1, 1, 1, 4, 4, 4, 4, 4, 4};
    int Ns[10]   = {256, 256, 256, 256, 256, 256, 256, 256, 1024, 256};
    int ldds[10] = {512, 512, 512, 512, 256, 256, 256, 256, 256, 1024};
    long slss[10] = {0, 0, 0, 0, 65536, 65536, 65536, 65536, 262144, 262144};
    long dlss[10] = {0, 0, 0, 0, 196608, 196608, 196608, 65536, 262144, 262144};
    int acc = 0;
    for (int i = 0; i < 10; i++) {
        J.src[i] = srcs[i]; J.dst[i] = dsts[i];
        J.gx[i] = gxs[i]; J.gy[i] = gys[i]; J.N[i] = Ns[i]; J.ldd[i] = ldds[i];
        J.sls[i] = slss[i]; J.dls[i] = dlss[i];
        J.base[i] = acc;
        acc += gxs[i] * gys[i] * nzs[i];
    }
    J.base[10] = acc;
    transpose_all<<<acc, dim3(32, 8)>>>(J);
    pack0_kernel<<<32, 256>>>(sW0, sWn0, wsg0);
    pack_bqkv<<<dim3(3, 4), 256>>>(bq, bk, bv, bqkv);

    // ---- CSR build + token map + pad zeroing ----
    cudaMemsetAsync(cnt, 0, NN * sizeof(int), 0);
    degi_kernel<<<(NE + 255) / 256, 256>>>(ei, cnt);
    scan_kernel<<<1, 1024>>>(cnt, rowptr);
    fill_kernel<<<(NE + 255) / 256, 256>>>(ei, cnt, csrc);
    tokmap_kernel<<<NN / 256, 256>>>(batches, tokmap);
    zero_pad<<<dim3(LMAXC, NG), EMBD>>>(batches, hp, hph);

    // ---- SAGE layer 0 ----
    agg0_kernel<<<NN / 8, 256>>>(x, comb0);
    gemm32h_kernel<<<dim3(256 / BN, NN / BM), 256>>>(comb0, wsg0, sb0, comb1h, 512);

    // ---- SAGE layer 1 ----
    agg_csr_h<<<NN, 128>>>(comb1h);
    run_hgemm64(comb1h, wsg1t, sb1, comb2h, NN, 256, 512, 512, 512, 1, 1, nullptr, nullptr);

    // ---- SAGE layer 2: write packed hp (fp32) + hph (half) via token map ----
    agg_csr_h<<<NN, 128>>>(comb2h);
    run_hgemm64(comb2h, wsg2t, sb2, hph, NN, 256, 512, 512, 256, 0, 1, tokmap, hp);

    // ---- 4 transformer layers ----
    for (int l = 0; l < 4; l++) {
        run_hgemm(hph, wqkvt + (long)l * 196608, bqkv + l * 768, qkvh,
                  NTOK, 768, 256, 256, 768, 0, 1);

        attn_mma<<<dim3(NG, NHD), 128, ATT_SMEM>>>(qkvh, batches, oh);

        hgemm_ln<<<NTOK / 64, 256, HSMEM_LN>>>(
            oh, wot + (long)l * 65536, bo + l * 256, hp,
            ln1g + l * EMBD, ln1b + l * EMBD, hp, hph, 256);

        run_hgemm(hph, w1t + (long)l * 262144, b1 + l * FFND, midh,
                  NTOK, 1024, 256, 256, 1024, 1, 1);

        if (l < 3) {
            hgemm_ln<<<NTOK / 64, 256, HSMEM_LN>>>(
                midh, w2t + (long)l * 262144, b2 + l * 256, hp,
                ln2g + l * EMBD, ln2b + l * EMBD, hp, hph, 1024);
        } else {
            hgemm_ln<<<NTOK / 64, 256, HSMEM_LN>>>(
                midh, w2t + (long)l * 262144, b2 + l * 256, hp,
                ln2g + l * EMBD, ln2b + l * EMBD, (float*)d_out, nullptr, 1024);
        }
    }
}